// round 1
// baseline (speedup 1.0000x reference)
#include <cuda_runtime.h>
#include <math.h>

// ---------------- problem constants ----------------
#define BATCH 8
#define C 256
#define H 64
#define W 64
#define NH 4
#define HD 64
#define P 1024           // 32*32 coarse tokens
#define KF 256           // top-k patches
#define HW (H*W)         // 4096
#define PLANE32 1024     // 32*32

// ---------------- device scratch ----------------
__device__ float g_xd[BATCH*C*PLANE32];          // down conv out [b,c,32,32]
__device__ float g_qkv[BATCH*NH*P*192];          // qkv (coarse then fine)
__device__ float g_attn[(size_t)BATCH*NH*P*P];   // attention matrix scratch (134MB)
__device__ float g_outc[BATCH*C*PLANE32];        // coarse attn out, channel-major
__device__ float g_coarse[BATCH*C*HW];           // conv-transpose out [b,c,64,64]
__device__ float g_score[BATCH*NH*P];
__device__ int   g_topk[BATCH*NH*KF];
__device__ float g_outf[BATCH*NH*P*HD];          // fine attn out, token-major
__device__ float g_y[BATCH*C*HW];                // coarse + region
__device__ float g_yd[BATCH*C*HW];               // after dwconv

// ---------------- down conv: C->C, k4 s2 p1, 64x64 -> 32x32 ----------------
// grid (8, 32) block 256; block = (b, 8 output channels), full 32x32 spatial
__global__ __launch_bounds__(256) void k_down(const float* __restrict__ x,
                                              const float* __restrict__ w,
                                              const float* __restrict__ bias) {
    int b = blockIdx.x, cg = blockIdx.y;
    int co0 = cg * 8;
    __shared__ float sin_[66*68];   // padded input plane (-1..64), row stride 68
    __shared__ float sw_[128];      // 8 co x 16 taps
    int t = threadIdx.x;
    float acc[4][8];
#pragma unroll
    for (int i = 0; i < 4; i++)
#pragma unroll
        for (int j = 0; j < 8; j++) acc[i][j] = 0.f;
    const float* xb = x + (size_t)b * C * HW;
    for (int ci = 0; ci < C; ci++) {
        const float* plane = xb + ci * HW;
        for (int idx = t; idx < 66*66; idx += 256) {
            int r = idx / 66, c = idx - r * 66;
            int iy = r - 1, ix = c - 1;
            sin_[r*68 + c] = (iy >= 0 && iy < 64 && ix >= 0 && ix < 64)
                                 ? plane[(iy << 6) + ix] : 0.f;
        }
        if (t < 128) sw_[t] = w[((co0 + (t >> 4)) * 256 + ci) * 16 + (t & 15)];
        __syncthreads();
        float v[4][16];
#pragma unroll
        for (int i = 0; i < 4; i++) {
            int p = t + (i << 8);
            int oy = p >> 5, ox = p & 31;
            int base = (oy << 1) * 68 + (ox << 1);
#pragma unroll
            for (int ky = 0; ky < 4; ky++)
#pragma unroll
                for (int kx = 0; kx < 4; kx++)
                    v[i][ky*4+kx] = sin_[base + ky*68 + kx];
        }
#pragma unroll
        for (int co = 0; co < 8; co++) {
#pragma unroll
            for (int j = 0; j < 16; j++) {
                float wv = sw_[co*16 + j];
#pragma unroll
                for (int i = 0; i < 4; i++)
                    acc[i][co] = fmaf(wv, v[i][j], acc[i][co]);
            }
        }
        __syncthreads();
    }
#pragma unroll
    for (int co = 0; co < 8; co++) {
        float bb = bias[co0 + co];
#pragma unroll
        for (int i = 0; i < 4; i++) {
            int p = t + (i << 8);
            g_xd[((size_t)(b*C + co0 + co) << 10) + p] = acc[i][co] + bb;
        }
    }
}

// ---------------- qkv projection (coarse: read g_xd, fine: gather from g_coarse) ----
// grid (32 bh, 16 ptile) block 256
__global__ __launch_bounds__(256) void k_qkv(const float* __restrict__ Wm,
                                             const float* __restrict__ bias,
                                             int fine) {
    int bh = blockIdx.x, pt = blockIdx.y;
    int b = bh >> 2, h = bh & 3;
    __shared__ float sA[64][65];    // [p][d]
    __shared__ float sW[64][97];    // [d][n-half]
    int t = threadIdx.x;
    if (!fine) {
        const float* src = g_xd + ((size_t)(b*C + h*HD)) * PLANE32 + pt*64;
        for (int idx = t; idx < 4096; idx += 256) {
            int d = idx >> 6, p = idx & 63;
            sA[p][d] = src[d * PLANE32 + p];
        }
    } else {
        for (int idx = t; idx < 4096; idx += 256) {
            int d = idx >> 6, p = idx & 63;
            int tok = pt*64 + p;
            int ki = tok >> 2, s = tok & 3;
            int pi = g_topk[bh*KF + ki];
            int yy = ((pi >> 5) << 1) + (s >> 1);
            int xx = ((pi & 31) << 1) + (s & 1);
            sA[p][d] = g_coarse[(((size_t)(b*C + h*HD + d)) << 12) + (yy << 6) + xx];
        }
    }
    float* dst = g_qkv + ((size_t)bh * P + pt*64) * 192;
    int p0 = (t >> 4) << 2, n0 = (t & 15) * 6;
    for (int half = 0; half < 2; half++) {
        __syncthreads();
        for (int idx = t; idx < 64*96; idx += 256) {
            int d = idx / 96, n = idx - d*96;
            sW[d][n] = Wm[d*192 + half*96 + n];
        }
        __syncthreads();
        float acc[4][6];
#pragma unroll
        for (int i = 0; i < 4; i++)
#pragma unroll
            for (int j = 0; j < 6; j++) acc[i][j] = 0.f;
#pragma unroll 8
        for (int d = 0; d < 64; d++) {
            float a0 = sA[p0][d], a1 = sA[p0+1][d], a2 = sA[p0+2][d], a3 = sA[p0+3][d];
#pragma unroll
            for (int j = 0; j < 6; j++) {
                float wv = sW[d][n0+j];
                acc[0][j] = fmaf(a0, wv, acc[0][j]);
                acc[1][j] = fmaf(a1, wv, acc[1][j]);
                acc[2][j] = fmaf(a2, wv, acc[2][j]);
                acc[3][j] = fmaf(a3, wv, acc[3][j]);
            }
        }
#pragma unroll
        for (int i = 0; i < 4; i++)
#pragma unroll
            for (int j = 0; j < 6; j++)
                dst[(p0+i)*192 + half*96 + n0 + j] = acc[i][j] + bias[half*96 + n0 + j];
    }
}

// ---------------- attention logits: attn = (Q K^T) * 0.125 ----------------
// grid (32, 16, 16) block 256, 64x64 output tile
__global__ __launch_bounds__(256) void k_logits() {
    int bh = blockIdx.x, qt = blockIdx.y, kt = blockIdx.z;
    __shared__ float sQ[64][65], sK[64][65];
    const float* qkv = g_qkv + (size_t)bh * P * 192;
    int t = threadIdx.x;
    for (int idx = t; idx < 4096; idx += 256) {
        int r = idx >> 6, d = idx & 63;
        sQ[r][d] = qkv[(qt*64 + r)*192 + d];
        sK[r][d] = qkv[(kt*64 + r)*192 + 64 + d];
    }
    __syncthreads();
    int q0 = (t >> 4) << 2, k0 = (t & 15) << 2;
    float acc[4][4];
#pragma unroll
    for (int i = 0; i < 4; i++)
#pragma unroll
        for (int j = 0; j < 4; j++) acc[i][j] = 0.f;
#pragma unroll 8
    for (int d = 0; d < 64; d++) {
        float a0 = sQ[q0][d], a1 = sQ[q0+1][d], a2 = sQ[q0+2][d], a3 = sQ[q0+3][d];
        float b0 = sK[k0][d], b1 = sK[k0+1][d], b2 = sK[k0+2][d], b3 = sK[k0+3][d];
        acc[0][0]=fmaf(a0,b0,acc[0][0]); acc[0][1]=fmaf(a0,b1,acc[0][1]);
        acc[0][2]=fmaf(a0,b2,acc[0][2]); acc[0][3]=fmaf(a0,b3,acc[0][3]);
        acc[1][0]=fmaf(a1,b0,acc[1][0]); acc[1][1]=fmaf(a1,b1,acc[1][1]);
        acc[1][2]=fmaf(a1,b2,acc[1][2]); acc[1][3]=fmaf(a1,b3,acc[1][3]);
        acc[2][0]=fmaf(a2,b0,acc[2][0]); acc[2][1]=fmaf(a2,b1,acc[2][1]);
        acc[2][2]=fmaf(a2,b2,acc[2][2]); acc[2][3]=fmaf(a2,b3,acc[2][3]);
        acc[3][0]=fmaf(a3,b0,acc[3][0]); acc[3][1]=fmaf(a3,b1,acc[3][1]);
        acc[3][2]=fmaf(a3,b2,acc[3][2]); acc[3][3]=fmaf(a3,b3,acc[3][3]);
    }
    float* dst = g_attn + ((size_t)bh << 20);
#pragma unroll
    for (int i = 0; i < 4; i++)
#pragma unroll
        for (int j = 0; j < 4; j++)
            dst[(size_t)(qt*64 + q0 + i)*1024 + kt*64 + k0 + j] = acc[i][j] * 0.125f;
}

// ---------------- row softmax over 1024 ----------------
__global__ __launch_bounds__(256) void k_softmax() {
    float* row = g_attn + ((size_t)blockIdx.x * 1024 + blockIdx.y) * 1024;
    int t = threadIdx.x;
    float v0 = row[t], v1 = row[t+256], v2 = row[t+512], v3 = row[t+768];
    float m = fmaxf(fmaxf(v0, v1), fmaxf(v2, v3));
    __shared__ float red[8];
    __shared__ float red2[8];
#pragma unroll
    for (int o = 16; o; o >>= 1) m = fmaxf(m, __shfl_xor_sync(0xffffffffu, m, o));
    if ((t & 31) == 0) red[t >> 5] = m;
    __syncthreads();
    if (t == 0) {
        float mm = red[0];
#pragma unroll
        for (int i = 1; i < 8; i++) mm = fmaxf(mm, red[i]);
        red[0] = mm;
    }
    __syncthreads();
    m = red[0];
    float e0 = __expf(v0 - m), e1 = __expf(v1 - m), e2 = __expf(v2 - m), e3 = __expf(v3 - m);
    float s = e0 + e1 + e2 + e3;
#pragma unroll
    for (int o = 16; o; o >>= 1) s += __shfl_xor_sync(0xffffffffu, s, o);
    if ((t & 31) == 0) red2[t >> 5] = s;
    __syncthreads();
    if (t == 0) {
        float ss = 0.f;
#pragma unroll
        for (int i = 0; i < 8; i++) ss += red2[i];
        red2[0] = ss;
    }
    __syncthreads();
    float inv = 1.0f / red2[0];
    row[t] = e0*inv; row[t+256] = e1*inv; row[t+512] = e2*inv; row[t+768] = e3*inv;
}

// ---------------- column sums (coarse_score) ----------------
__global__ __launch_bounds__(256) void k_colsum() {
    int bh = blockIdx.x;
    int k = blockIdx.y * 256 + threadIdx.x;
    const float* a = g_attn + ((size_t)bh << 20) + k;
    float s = 0.f;
#pragma unroll 8
    for (int q = 0; q < 1024; q++) s += a[(size_t)q << 10];
    g_score[bh*1024 + k] = s;
}

// ---------------- top-k via bitonic sort (desc value, asc index ties) ----------
__global__ __launch_bounds__(512) void k_topk() {
    int bh = blockIdx.x;
    __shared__ float sv[1024];
    __shared__ int si[1024];
    int t = threadIdx.x;
    sv[t]       = g_score[bh*1024 + t];       si[t]       = t;
    sv[t + 512] = g_score[bh*1024 + t + 512]; si[t + 512] = t + 512;
    __syncthreads();
    for (int k = 2; k <= 1024; k <<= 1) {
        for (int j = k >> 1; j > 0; j >>= 1) {
#pragma unroll
            for (int mm = 0; mm < 2; mm++) {
                int i = t + mm*512;
                int l = i ^ j;
                if (l > i) {
                    float vi = sv[i], vl = sv[l];
                    int ii = si[i], il = si[l];
                    bool before = (vi > vl) || (vi == vl && ii < il);
                    bool keep = ((i & k) == 0) ? before : !before;
                    if (!keep) { sv[i] = vl; sv[l] = vi; si[i] = il; si[l] = ii; }
                }
            }
            __syncthreads();
        }
    }
    if (t < 256) g_topk[bh*KF + t] = si[t];
}

// ---------------- attn output GEMM: out = attn @ V ----------------
// grid (32, 16 qtiles) block 256
__global__ __launch_bounds__(256) void k_attn_out(int fine) {
    int bh = blockIdx.x, qt = blockIdx.y;
    int b = bh >> 2, h = bh & 3;
    __shared__ float sA[64][65], sV[64][65];
    int t = threadIdx.x;
    int q0 = (t >> 4) << 2, n0 = (t & 15) << 2;
    float acc[4][4];
#pragma unroll
    for (int i = 0; i < 4; i++)
#pragma unroll
        for (int j = 0; j < 4; j++) acc[i][j] = 0.f;
    const float* attn = g_attn + ((size_t)bh << 20) + (size_t)qt * 64 * 1024;
    const float* vptr = g_qkv + (size_t)bh * P * 192 + 128;
    for (int kc = 0; kc < 16; kc++) {
        for (int idx = t; idx < 4096; idx += 256) {
            int r = idx >> 6, c = idx & 63;
            sA[r][c] = attn[(size_t)r*1024 + kc*64 + c];
            sV[r][c] = vptr[(kc*64 + r)*192 + c];
        }
        __syncthreads();
#pragma unroll 8
        for (int kk = 0; kk < 64; kk++) {
            float a0 = sA[q0][kk], a1 = sA[q0+1][kk], a2 = sA[q0+2][kk], a3 = sA[q0+3][kk];
            float b0 = sV[kk][n0], b1 = sV[kk][n0+1], b2 = sV[kk][n0+2], b3 = sV[kk][n0+3];
            acc[0][0]=fmaf(a0,b0,acc[0][0]); acc[0][1]=fmaf(a0,b1,acc[0][1]);
            acc[0][2]=fmaf(a0,b2,acc[0][2]); acc[0][3]=fmaf(a0,b3,acc[0][3]);
            acc[1][0]=fmaf(a1,b0,acc[1][0]); acc[1][1]=fmaf(a1,b1,acc[1][1]);
            acc[1][2]=fmaf(a1,b2,acc[1][2]); acc[1][3]=fmaf(a1,b3,acc[1][3]);
            acc[2][0]=fmaf(a2,b0,acc[2][0]); acc[2][1]=fmaf(a2,b1,acc[2][1]);
            acc[2][2]=fmaf(a2,b2,acc[2][2]); acc[2][3]=fmaf(a2,b3,acc[2][3]);
            acc[3][0]=fmaf(a3,b0,acc[3][0]); acc[3][1]=fmaf(a3,b1,acc[3][1]);
            acc[3][2]=fmaf(a3,b2,acc[3][2]); acc[3][3]=fmaf(a3,b3,acc[3][3]);
        }
        __syncthreads();
    }
    if (!fine) {
#pragma unroll
        for (int i = 0; i < 4; i++)
#pragma unroll
            for (int j = 0; j < 4; j++)
                g_outc[((size_t)(b*C + h*HD + n0 + j)) * PLANE32 + qt*64 + q0 + i] = acc[i][j];
    } else {
#pragma unroll
        for (int i = 0; i < 4; i++)
#pragma unroll
            for (int j = 0; j < 4; j++)
                g_outf[(((size_t)bh * P) + qt*64 + q0 + i) * HD + n0 + j] = acc[i][j];
    }
}

// ---------------- conv transpose: k4 s2 p1, 32x32 -> 64x64 ----------------
// out[co,o] = sum_ci sum_{ky in {p,p+2}, kx} Wup[ci,co,ky,kx] * in[ci, (o+1-ky)/2]
// grid (8, 32 co-groups of 8, 4 quadrants of 32x32) block 256 (16x16)
__global__ __launch_bounds__(256) void k_up(const float* __restrict__ wup,
                                            const float* __restrict__ bup) {
    int b = blockIdx.x, cg = blockIdx.y, quad = blockIdx.z;
    int co0 = cg * 8;
    int oy0 = (quad >> 1) * 32, ox0 = (quad & 1) * 32;
    __shared__ float win[18][19];
    __shared__ float sw_[128];
    int t = threadIdx.x;
    int tr = t >> 4, tc = t & 15;
    int iy_base = oy0/2 - 1, ix_base = ox0/2 - 1;
    float acc[4][8];
#pragma unroll
    for (int i = 0; i < 4; i++)
#pragma unroll
        for (int j = 0; j < 8; j++) acc[i][j] = 0.f;
    int py  = ((oy0 + tr) + 1) & 1;
    int pxp = ((ox0 + tc) + 1) & 1;
    for (int ci = 0; ci < C; ci++) {
        const float* plane = g_outc + ((size_t)(b*C + ci)) * PLANE32;
        for (int idx = t; idx < 18*18; idx += 256) {
            int r = idx / 18, c = idx - r*18;
            int iy = iy_base + r, ix = ix_base + c;
            win[r][c] = (iy >= 0 && iy < 32 && ix >= 0 && ix < 32) ? plane[iy*32 + ix] : 0.f;
        }
        if (t < 128) sw_[t] = wup[((size_t)ci*256 + co0 + (t >> 4)) * 16 + (t & 15)];
        __syncthreads();
        float v[4][4];
#pragma unroll
        for (int pxi = 0; pxi < 4; pxi++) {
            int oy = oy0 + tr + (pxi >> 1) * 16;
            int ox = ox0 + tc + (pxi & 1) * 16;
            int r0 = ((oy + 1 - py) >> 1) - iy_base;
            int c0 = ((ox + 1 - pxp) >> 1) - ix_base;
            v[pxi][0] = win[r0][c0];      // ky=py,   kx=pxp
            v[pxi][1] = win[r0][c0-1];    // ky=py,   kx=pxp+2
            v[pxi][2] = win[r0-1][c0];    // ky=py+2, kx=pxp
            v[pxi][3] = win[r0-1][c0-1];  // ky=py+2, kx=pxp+2
        }
#pragma unroll
        for (int co = 0; co < 8; co++) {
            float w00 = sw_[co*16 + py*4 + pxp];
            float w01 = sw_[co*16 + py*4 + pxp + 2];
            float w10 = sw_[co*16 + (py+2)*4 + pxp];
            float w11 = sw_[co*16 + (py+2)*4 + pxp + 2];
#pragma unroll
            for (int pxi = 0; pxi < 4; pxi++) {
                float a = acc[pxi][co];
                a = fmaf(w00, v[pxi][0], a);
                a = fmaf(w01, v[pxi][1], a);
                a = fmaf(w10, v[pxi][2], a);
                a = fmaf(w11, v[pxi][3], a);
                acc[pxi][co] = a;
            }
        }
        __syncthreads();
    }
#pragma unroll
    for (int co = 0; co < 8; co++) {
        float bb = bup[co0 + co];
#pragma unroll
        for (int pxi = 0; pxi < 4; pxi++) {
            int oy = oy0 + tr + (pxi >> 1) * 16;
            int ox = ox0 + tc + (pxi & 1) * 16;
            g_coarse[(((size_t)(b*C + co0 + co)) << 12) + (oy << 6) + ox] = acc[pxi][co] + bb;
        }
    }
}

// ---------------- y = coarse ----------------
__global__ __launch_bounds__(1024) void k_copy() {
    size_t i = (size_t)blockIdx.x * 1024 + threadIdx.x;
    g_y[i] = g_coarse[i];
}

// ---------------- scatter fine attention output into y ----------------
// grid (32 bh, 256 ki) block 256 (= 4 subpix * 64 dims)
__global__ __launch_bounds__(256) void k_scatter() {
    int bh = blockIdx.x, ki = blockIdx.y;
    int t = threadIdx.x;
    int s = t >> 6, d = t & 63;
    int b = bh >> 2, h = bh & 3;
    int p = g_topk[bh*KF + ki];
    int yy = ((p >> 5) << 1) + (s >> 1);
    int xx = ((p & 31) << 1) + (s & 1);
    float val = g_outf[((size_t)bh * P + ki*4 + s) * HD + d];
    g_y[(((size_t)(b*C + h*HD + d)) << 12) + (yy << 6) + xx] += val;
}

// ---------------- depthwise 3x3 + BN + relu6 ----------------
__global__ __launch_bounds__(256) void k_dw(const float* __restrict__ wdw,
                                            const float* __restrict__ g,
                                            const float* __restrict__ bb,
                                            const float* __restrict__ m,
                                            const float* __restrict__ vv) {
    size_t i = (size_t)blockIdx.x * 256 + threadIdx.x;
    int x = i & 63, y = (i >> 6) & 63;
    int c = (int)((i >> 12) & 255);
    const float* plane = g_y + ((i >> 12) << 12);
    const float* wc = wdw + c*9;
    float s = 0.f;
#pragma unroll
    for (int ky = 0; ky < 3; ky++) {
        int yy = y + ky - 1;
        if (yy < 0 || yy >= 64) continue;
#pragma unroll
        for (int kx = 0; kx < 3; kx++) {
            int xx = x + kx - 1;
            if (xx < 0 || xx >= 64) continue;
            s = fmaf(wc[ky*3 + kx], plane[(yy << 6) + xx], s);
        }
    }
    float sc = g[c] * rsqrtf(vv[c] + 1e-5f);
    float r = s * sc + (bb[c] - m[c] * sc);
    g_yd[i] = fminf(fmaxf(r, 0.f), 6.f);
}

// ---------------- pointwise 1x1 (256x256) + BN + relu6 -> output ----------------
// grid (8 b, 32 px-tiles of 128, 4 co-tiles of 64) block 256
__global__ __launch_bounds__(256) void k_pw(const float* __restrict__ wpw,
                                            const float* __restrict__ g,
                                            const float* __restrict__ bb,
                                            const float* __restrict__ m,
                                            const float* __restrict__ vv,
                                            float* __restrict__ out) {
    int b = blockIdx.x, sp = blockIdx.y, cg = blockIdx.z;
    __shared__ float sX[32][128];
    __shared__ float sW[64][33];
    int t = threadIdx.x;
    int pxg = (t & 31) << 2;   // 0..124
    int cog = (t >> 5) << 3;   // 0..56
    float acc[8][4];
#pragma unroll
    for (int i = 0; i < 8; i++)
#pragma unroll
        for (int j = 0; j < 4; j++) acc[i][j] = 0.f;
    const float* xin = g_yd + (size_t)b * C * HW + sp * 128;
    for (int cc = 0; cc < 8; cc++) {
        for (int idx = t; idx < 32*128; idx += 256) {
            int r = idx >> 7, c = idx & 127;
            sX[r][c] = xin[(size_t)(cc*32 + r) * HW + c];
        }
        for (int idx = t; idx < 64*32; idx += 256) {
            int co = idx >> 5, kk = idx & 31;
            sW[co][kk] = wpw[(cg*64 + co) * 256 + cc*32 + kk];
        }
        __syncthreads();
#pragma unroll 4
        for (int kk = 0; kk < 32; kk++) {
            float4 xv = *reinterpret_cast<const float4*>(&sX[kk][pxg]);
            float wv[8];
#pragma unroll
            for (int i = 0; i < 8; i++) wv[i] = sW[cog + i][kk];
#pragma unroll
            for (int i = 0; i < 8; i++) {
                acc[i][0] = fmaf(wv[i], xv.x, acc[i][0]);
                acc[i][1] = fmaf(wv[i], xv.y, acc[i][1]);
                acc[i][2] = fmaf(wv[i], xv.z, acc[i][2]);
                acc[i][3] = fmaf(wv[i], xv.w, acc[i][3]);
            }
        }
        __syncthreads();
    }
#pragma unroll
    for (int i = 0; i < 8; i++) {
        int co = cg*64 + cog + i;
        float sc = g[co] * rsqrtf(vv[co] + 1e-5f);
        float off = bb[co] - m[co] * sc;
#pragma unroll
        for (int j = 0; j < 4; j++) {
            float r = acc[i][j] * sc + off;
            r = fminf(fmaxf(r, 0.f), 6.f);
            out[((size_t)(b*C + co)) * HW + sp*128 + pxg + j] = r;
        }
    }
}

// ---------------- launch ----------------
extern "C" void kernel_launch(void* const* d_in, const int* in_sizes, int n_in,
                              void* d_out, int out_size) {
    const float* x       = (const float*)d_in[0];
    const float* w_down  = (const float*)d_in[1];
    const float* b_down  = (const float*)d_in[2];
    const float* w_qkv_c = (const float*)d_in[3];
    const float* b_qkv_c = (const float*)d_in[4];
    const float* w_up    = (const float*)d_in[5];
    const float* b_up    = (const float*)d_in[6];
    const float* w_qkv_f = (const float*)d_in[7];
    const float* b_qkv_f = (const float*)d_in[8];
    const float* w_dw    = (const float*)d_in[9];
    const float* bn_dw_g = (const float*)d_in[10];
    const float* bn_dw_b = (const float*)d_in[11];
    const float* bn_dw_m = (const float*)d_in[12];
    const float* bn_dw_v = (const float*)d_in[13];
    const float* w_pw    = (const float*)d_in[14];
    const float* bn_pw_g = (const float*)d_in[15];
    const float* bn_pw_b = (const float*)d_in[16];
    const float* bn_pw_m = (const float*)d_in[17];
    const float* bn_pw_v = (const float*)d_in[18];
    float* out = (float*)d_out;

    // ---- coarse attention path ----
    k_down<<<dim3(8, 32), 256>>>(x, w_down, b_down);
    k_qkv<<<dim3(32, 16), 256>>>(w_qkv_c, b_qkv_c, 0);
    k_logits<<<dim3(32, 16, 16), 256>>>();
    k_softmax<<<dim3(32, 1024), 256>>>();
    k_colsum<<<dim3(32, 4), 256>>>();
    k_attn_out<<<dim3(32, 16), 256>>>(0);
    k_topk<<<32, 512>>>();
    k_up<<<dim3(8, 32, 4), 256>>>(w_up, b_up);

    // ---- fine (top-k) attention path ----
    k_qkv<<<dim3(32, 16), 256>>>(w_qkv_f, b_qkv_f, 1);
    k_logits<<<dim3(32, 16, 16), 256>>>();
    k_softmax<<<dim3(32, 1024), 256>>>();
    k_attn_out<<<dim3(32, 16), 256>>>(1);

    // ---- combine + feed-forward ----
    k_copy<<<8192, 1024>>>();
    k_scatter<<<dim3(32, 256), 256>>>();
    k_dw<<<32768, 256>>>(w_dw, bn_dw_g, bn_dw_b, bn_dw_m, bn_dw_v);
    k_pw<<<dim3(8, 32, 4), 256>>>(w_pw, bn_pw_g, bn_pw_b, bn_pw_m, bn_pw_v, out);
}

// round 2
// speedup vs baseline: 1.7819x; 1.7819x over previous
#include <cuda_runtime.h>
#include <math.h>

// ---------------- problem constants ----------------
#define BATCH 8
#define C 256
#define H 64
#define W 64
#define NH 4
#define HD 64
#define P 1024
#define KF 256
#define HW (H*W)
#define PLANE32 1024

// ---------------- device scratch ----------------
__device__ float g_xd[BATCH*C*PLANE32];
__device__ float g_qkv[BATCH*NH*P*192];
__device__ float g_attn[(size_t)BATCH*NH*P*P];
__device__ float g_outc[BATCH*C*PLANE32];
__device__ float g_coarse[BATCH*C*HW];
__device__ float g_score[BATCH*NH*P];
__device__ int   g_topk[BATCH*NH*KF];
__device__ float g_outf[BATCH*NH*P*HD];
__device__ float g_y[BATCH*C*HW];
__device__ float g_yd[BATCH*C*HW];
__device__ float g_wupt[4*256*1024];   // transposed convT weights [cls][co][ci*4+j]

// ---------------- tf32 mma helpers ----------------
__device__ __forceinline__ unsigned f2tf(float x){
    unsigned r; asm("cvt.rna.tf32.f32 %0, %1;" : "=r"(r) : "f"(x)); return r;
}
__device__ __forceinline__ void split_tf(float x, unsigned &hi, unsigned &lo){
    hi = f2tf(x);
    lo = f2tf(x - __uint_as_float(hi));
}
__device__ __forceinline__ void mma8(float* c, unsigned a0,unsigned a1,unsigned a2,unsigned a3,
                                     unsigned b0,unsigned b1){
    asm volatile("mma.sync.aligned.m16n8k8.row.col.f32.tf32.tf32.f32 "
        "{%0,%1,%2,%3}, {%4,%5,%6,%7}, {%8,%9}, {%0,%1,%2,%3};"
        : "+f"(c[0]),"+f"(c[1]),"+f"(c[2]),"+f"(c[3])
        : "r"(a0),"r"(a1),"r"(a2),"r"(a3),"r"(b0),"r"(b1));
}
__device__ __forceinline__ void mma3x(float* c, const unsigned* ah, const unsigned* al,
                                      const unsigned* bh, const unsigned* bl){
    mma8(c, ah[0],ah[1],ah[2],ah[3], bh[0],bh[1]);
    mma8(c, ah[0],ah[1],ah[2],ah[3], bl[0],bl[1]);
    mma8(c, al[0],al[1],al[2],al[3], bh[0],bh[1]);
}

// ---------------- weight pre-transpose for convT ----------------
__global__ __launch_bounds__(256) void k_wt(const float* __restrict__ wup){
    int idx = blockIdx.x*256 + threadIdx.x;      // [cls][co][ci][j]
    int cls = idx>>18, co = (idx>>10)&255, ci = (idx>>2)&255, j = idx&3;
    int py = cls>>1, pxp = cls&1;
    int ky = py + ((j>>1)<<1), kx = pxp + ((j&1)<<1);
    g_wupt[idx] = wup[((size_t)ci*256 + co)*16 + ky*4 + kx];
}

// ---------------- down conv (implicit GEMM, tf32 3x) ----------------
// grid (64, 4): bx -> b=bx>>3, oyq=bx&7 (4 output rows); by -> co tile of 64
__global__ __launch_bounds__(256) void k_down_t(const float* __restrict__ x,
                                                const float* __restrict__ wgt,
                                                const float* __restrict__ bias){
    int b = blockIdx.x>>3, oyq = blockIdx.x&7;
    int co0 = blockIdx.y*64;
    __shared__ float sW[64*68];
    __shared__ float sraw[4*10*72];
    int t=threadIdx.x, w=t>>5, lane=t&31, gp=lane>>2, tig=lane&3;
    int mrow=(w>>2)*32, ncol=(w&3)*32;
    float c[2][4][4];
#pragma unroll
    for (int i=0;i<2;i++)
#pragma unroll
    for (int jn=0;jn<4;jn++)
#pragma unroll
    for (int k=0;k<4;k++) c[i][jn][k]=0.f;

    for (int cc=0; cc<64; cc++){
        __syncthreads();
        for (int idx=t; idx<1024; idx+=256){
            int co=idx>>4, c4=(idx&15)<<2;
            *(float4*)(sW + co*68 + c4) =
                *(const float4*)(wgt + (size_t)(co0+co)*4096 + cc*64 + c4);
        }
        int ci0 = cc*4;
        for (int idx=t; idx<640; idx+=256){
            int rowid = idx>>4, c4=(idx&15)<<2;
            int ci4 = rowid/10, r = rowid - ci4*10;
            int iy = oyq*8 - 1 + r;
            float4 v = make_float4(0.f,0.f,0.f,0.f);
            if (iy>=0 && iy<64)
                v = *(const float4*)(x + (((size_t)(b*C + ci0+ci4))<<12) + (iy<<6) + c4);
            *(float4*)(sraw + rowid*72 + 4 + c4) = v;
        }
        if (t<40){ sraw[t*72+3]=0.f; sraw[t*72+68]=0.f; }
        __syncthreads();
#pragma unroll
        for (int kk=0;kk<8;kk++){
            int k0=kk*8;
            unsigned ah[2][4], al[2][4], bhi[4][2], blo[4][2];
#pragma unroll
            for (int mi=0;mi<2;mi++){
                const float* base = sW + (mrow+mi*16+gp)*68 + k0 + tig;
                split_tf(base[0],      ah[mi][0], al[mi][0]);
                split_tf(base[8*68],   ah[mi][1], al[mi][1]);
                split_tf(base[4],      ah[mi][2], al[mi][2]);
                split_tf(base[8*68+4], ah[mi][3], al[mi][3]);
            }
#pragma unroll
            for (int ni=0;ni<4;ni++){
                int n = ncol+ni*8+gp; int opy=n>>5, opx=n&31;
#pragma unroll
                for (int kj=0;kj<2;kj++){
                    int k = k0+tig+kj*4;
                    int ci4=k>>4, tap=k&15, ky=tap>>2, kx=tap&3;
                    float v = sraw[(ci4*10 + 2*opy+ky)*72 + 3 + 2*opx + kx];
                    split_tf(v, bhi[ni][kj], blo[ni][kj]);
                }
            }
#pragma unroll
            for (int mi=0;mi<2;mi++)
#pragma unroll
            for (int ni=0;ni<4;ni++)
                mma3x(c[mi][ni], ah[mi], al[mi], bhi[ni], blo[ni]);
        }
    }
#pragma unroll
    for (int mi=0;mi<2;mi++){
        int co = co0+mrow+mi*16+gp;
        float b0v = bias[co], b1v = bias[co+8];
#pragma unroll
        for (int ni=0;ni<4;ni++){
            int n = ncol+ni*8+2*tig; int opy=n>>5, opx=n&31;
            size_t o = ((size_t)(b*C+co)<<10) + (oyq*4+opy)*32 + opx;
            *(float2*)(g_xd + o) = make_float2(c[mi][ni][0]+b0v, c[mi][ni][1]+b0v);
            *(float2*)(g_xd + o + (8<<10)) = make_float2(c[mi][ni][2]+b1v, c[mi][ni][3]+b1v);
        }
    }
}

// ---------------- convT (implicit GEMM per parity class, tf32 3x) ----------------
// grid (64, 16): bx -> b=bx>>3, uq=bx&7 ; by -> cls=by>>2, co tile = (by&3)*64
__global__ __launch_bounds__(256) void k_up_t(const float* __restrict__ bup){
    int b = blockIdx.x>>3, uq = blockIdx.x&7;
    int cls = blockIdx.y>>2, co0 = (blockIdx.y&3)*64;
    int py = cls>>1, pxp = cls&1;
    __shared__ float sW[64*68];
    __shared__ float sraw[16*5*40];
    int t=threadIdx.x, w=t>>5, lane=t&31, gp=lane>>2, tig=lane&3;
    int mrow=(w>>2)*32, ncol=(w&3)*32;
    float c[2][4][4];
#pragma unroll
    for (int i=0;i<2;i++)
#pragma unroll
    for (int jn=0;jn<4;jn++)
#pragma unroll
    for (int k=0;k<4;k++) c[i][jn][k]=0.f;

    for (int cc=0; cc<16; cc++){
        __syncthreads();
        for (int idx=t; idx<1024; idx+=256){
            int co=idx>>4, c4=(idx&15)<<2;
            *(float4*)(sW + co*68 + c4) =
                *(const float4*)(g_wupt + (size_t)cls*262144 + (size_t)(co0+co)*1024 + cc*64 + c4);
        }
        int ci0 = cc*16;
        for (int idx=t; idx<640; idx+=256){
            int rowid=idx>>3, c4=(idx&7)<<2;
            int ci16=rowid/5, rr=rowid-ci16*5;
            int iy = uq*4 - py + rr;
            float4 v = make_float4(0.f,0.f,0.f,0.f);
            if (iy>=0 && iy<32)
                v = *(const float4*)(g_outc + (((size_t)(b*C+ci0+ci16))<<10) + (iy<<5) + c4);
            *(float4*)(sraw + rowid*40 + 4 + c4) = v;
        }
        if (t<80){ sraw[t*40+3]=0.f; sraw[t*40+36]=0.f; }
        __syncthreads();
#pragma unroll
        for (int kk=0;kk<8;kk++){
            int k0=kk*8;
            unsigned ah[2][4], al[2][4], bhi[4][2], blo[4][2];
#pragma unroll
            for (int mi=0;mi<2;mi++){
                const float* base = sW + (mrow+mi*16+gp)*68 + k0 + tig;
                split_tf(base[0],      ah[mi][0], al[mi][0]);
                split_tf(base[8*68],   ah[mi][1], al[mi][1]);
                split_tf(base[4],      ah[mi][2], al[mi][2]);
                split_tf(base[8*68+4], ah[mi][3], al[mi][3]);
            }
#pragma unroll
            for (int ni=0;ni<4;ni++){
                int n = ncol+ni*8+gp; int uu=n>>5, vv=n&31;
#pragma unroll
                for (int kj=0;kj<2;kj++){
                    int k = k0+tig+kj*4;
                    int ci16=k>>2, j=k&3;
                    float v = sraw[(ci16*5 + uu+1-(j>>1))*40 + vv + 5 - pxp - (j&1)];
                    split_tf(v, bhi[ni][kj], blo[ni][kj]);
                }
            }
#pragma unroll
            for (int mi=0;mi<2;mi++)
#pragma unroll
            for (int ni=0;ni<4;ni++)
                mma3x(c[mi][ni], ah[mi], al[mi], bhi[ni], blo[ni]);
        }
    }
#pragma unroll
    for (int mi=0;mi<2;mi++){
        int co = co0+mrow+mi*16+gp;
        float b0v = bup[co], b1v = bup[co+8];
#pragma unroll
        for (int ni=0;ni<4;ni++){
            int n = ncol+ni*8+2*tig; int uu=n>>5, vv=n&31;
            int oy = 2*(uq*4+uu) + 1 - py;
            int ox = 2*vv + 1 - pxp;
            size_t o0 = (((size_t)(b*C+co))<<12) + oy*64 + ox;
            g_coarse[o0]     = c[mi][ni][0]+b0v;
            g_coarse[o0+2]   = c[mi][ni][1]+b0v;
            size_t o1 = (((size_t)(b*C+co+8))<<12) + oy*64 + ox;
            g_coarse[o1]     = c[mi][ni][2]+b1v;
            g_coarse[o1+2]   = c[mi][ni][3]+b1v;
        }
    }
}

// ---------------- qkv projection (unchanged FFMA) ----------------
__global__ __launch_bounds__(256) void k_qkv(const float* __restrict__ Wm,
                                             const float* __restrict__ bias,
                                             int fine) {
    int bh = blockIdx.x, pt = blockIdx.y;
    int b = bh >> 2, h = bh & 3;
    __shared__ float sA[64][65];
    __shared__ float sW[64][97];
    int t = threadIdx.x;
    if (!fine) {
        const float* src = g_xd + ((size_t)(b*C + h*HD)) * PLANE32 + pt*64;
        for (int idx = t; idx < 4096; idx += 256) {
            int d = idx >> 6, p = idx & 63;
            sA[p][d] = src[d * PLANE32 + p];
        }
    } else {
        for (int idx = t; idx < 4096; idx += 256) {
            int d = idx >> 6, p = idx & 63;
            int tok = pt*64 + p;
            int ki = tok >> 2, s = tok & 3;
            int pi = g_topk[bh*KF + ki];
            int yy = ((pi >> 5) << 1) + (s >> 1);
            int xx = ((pi & 31) << 1) + (s & 1);
            sA[p][d] = g_coarse[(((size_t)(b*C + h*HD + d)) << 12) + (yy << 6) + xx];
        }
    }
    float* dst = g_qkv + ((size_t)bh * P + pt*64) * 192;
    int p0 = (t >> 4) << 2, n0 = (t & 15) * 6;
    for (int half = 0; half < 2; half++) {
        __syncthreads();
        for (int idx = t; idx < 64*96; idx += 256) {
            int d = idx / 96, n = idx - d*96;
            sW[d][n] = Wm[d*192 + half*96 + n];
        }
        __syncthreads();
        float acc[4][6];
#pragma unroll
        for (int i = 0; i < 4; i++)
#pragma unroll
            for (int j = 0; j < 6; j++) acc[i][j] = 0.f;
#pragma unroll 8
        for (int d = 0; d < 64; d++) {
            float a0 = sA[p0][d], a1 = sA[p0+1][d], a2 = sA[p0+2][d], a3 = sA[p0+3][d];
#pragma unroll
            for (int j = 0; j < 6; j++) {
                float wv = sW[d][n0+j];
                acc[0][j] = fmaf(a0, wv, acc[0][j]);
                acc[1][j] = fmaf(a1, wv, acc[1][j]);
                acc[2][j] = fmaf(a2, wv, acc[2][j]);
                acc[3][j] = fmaf(a3, wv, acc[3][j]);
            }
        }
#pragma unroll
        for (int i = 0; i < 4; i++)
#pragma unroll
            for (int j = 0; j < 6; j++)
                dst[(p0+i)*192 + half*96 + n0 + j] = acc[i][j] + bias[half*96 + n0 + j];
    }
}

// ---------------- attention logits (tf32 3x): attn = QK^T * 0.125 -----------
// grid (32 bh, 16 qt) block 256
__global__ __launch_bounds__(256) void k_logits_t() {
    int bh = blockIdx.x, qt = blockIdx.y;
    __shared__ float sQ[64*68];
    __shared__ float sK[64*68];
    int t=threadIdx.x, w=t>>5, lane=t&31, gp=lane>>2, tig=lane&3;
    int mrow=(w>>2)*32, ncol=(w&3)*16;
    const float* qkv = g_qkv + (size_t)bh*P*192;
    for (int idx=t; idx<1024; idx+=256){
        int r=idx>>4, c4=(idx&15)<<2;
        *(float4*)(sQ + r*68 + c4) = *(const float4*)(qkv + (qt*64+r)*192 + c4);
    }
    float* dst = g_attn + ((size_t)bh<<20) + (size_t)qt*64*1024;
    for (int kt=0; kt<16; kt++){
        __syncthreads();
        for (int idx=t; idx<1024; idx+=256){
            int r=idx>>4, c4=(idx&15)<<2;
            *(float4*)(sK + r*68 + c4) = *(const float4*)(qkv + (kt*64+r)*192 + 64 + c4);
        }
        __syncthreads();
        float c[2][2][4];
#pragma unroll
        for (int i=0;i<2;i++)
#pragma unroll
        for (int jn=0;jn<2;jn++)
#pragma unroll
        for (int k=0;k<4;k++) c[i][jn][k]=0.f;
#pragma unroll
        for (int kk=0;kk<8;kk++){
            int k0=kk*8;
            unsigned ah[2][4], al[2][4], bhi[2][2], blo[2][2];
#pragma unroll
            for (int mi=0;mi<2;mi++){
                const float* base = sQ + (mrow+mi*16+gp)*68 + k0 + tig;
                split_tf(base[0],      ah[mi][0], al[mi][0]);
                split_tf(base[8*68],   ah[mi][1], al[mi][1]);
                split_tf(base[4],      ah[mi][2], al[mi][2]);
                split_tf(base[8*68+4], ah[mi][3], al[mi][3]);
            }
#pragma unroll
            for (int ni=0;ni<2;ni++){
                const float* base = sK + (ncol+ni*8+gp)*68 + k0 + tig;
                split_tf(base[0], bhi[ni][0], blo[ni][0]);
                split_tf(base[4], bhi[ni][1], blo[ni][1]);
            }
#pragma unroll
            for (int mi=0;mi<2;mi++)
#pragma unroll
            for (int ni=0;ni<2;ni++)
                mma3x(c[mi][ni], ah[mi], al[mi], bhi[ni], blo[ni]);
        }
#pragma unroll
        for (int mi=0;mi<2;mi++)
#pragma unroll
        for (int ni=0;ni<2;ni++){
            int row = mrow+mi*16+gp, col = kt*64+ncol+ni*8+2*tig;
            *(float2*)(dst + (size_t)row*1024 + col) =
                make_float2(c[mi][ni][0]*0.125f, c[mi][ni][1]*0.125f);
            *(float2*)(dst + (size_t)(row+8)*1024 + col) =
                make_float2(c[mi][ni][2]*0.125f, c[mi][ni][3]*0.125f);
        }
    }
}

// ---------------- softmax ----------------
__global__ __launch_bounds__(256) void k_softmax() {
    float* row = g_attn + ((size_t)blockIdx.x * 1024 + blockIdx.y) * 1024;
    int t = threadIdx.x;
    float v0 = row[t], v1 = row[t+256], v2 = row[t+512], v3 = row[t+768];
    float m = fmaxf(fmaxf(v0, v1), fmaxf(v2, v3));
    __shared__ float red[8];
    __shared__ float red2[8];
#pragma unroll
    for (int o = 16; o; o >>= 1) m = fmaxf(m, __shfl_xor_sync(0xffffffffu, m, o));
    if ((t & 31) == 0) red[t >> 5] = m;
    __syncthreads();
    if (t == 0) {
        float mm = red[0];
#pragma unroll
        for (int i = 1; i < 8; i++) mm = fmaxf(mm, red[i]);
        red[0] = mm;
    }
    __syncthreads();
    m = red[0];
    float e0 = __expf(v0 - m), e1 = __expf(v1 - m), e2 = __expf(v2 - m), e3 = __expf(v3 - m);
    float s = e0 + e1 + e2 + e3;
#pragma unroll
    for (int o = 16; o; o >>= 1) s += __shfl_xor_sync(0xffffffffu, s, o);
    if ((t & 31) == 0) red2[t >> 5] = s;
    __syncthreads();
    if (t == 0) {
        float ss = 0.f;
#pragma unroll
        for (int i = 0; i < 8; i++) ss += red2[i];
        red2[0] = ss;
    }
    __syncthreads();
    float inv = 1.0f / red2[0];
    row[t] = e0*inv; row[t+256] = e1*inv; row[t+512] = e2*inv; row[t+768] = e3*inv;
}

// ---------------- column sums ----------------
__global__ __launch_bounds__(256) void k_colsum() {
    int bh = blockIdx.x;
    int k = blockIdx.y * 256 + threadIdx.x;
    const float* a = g_attn + ((size_t)bh << 20) + k;
    float s = 0.f;
#pragma unroll 8
    for (int q = 0; q < 1024; q++) s += a[(size_t)q << 10];
    g_score[bh*1024 + k] = s;
}

// ---------------- top-k bitonic ----------------
__global__ __launch_bounds__(512) void k_topk() {
    int bh = blockIdx.x;
    __shared__ float sv[1024];
    __shared__ int si[1024];
    int t = threadIdx.x;
    sv[t]       = g_score[bh*1024 + t];       si[t]       = t;
    sv[t + 512] = g_score[bh*1024 + t + 512]; si[t + 512] = t + 512;
    __syncthreads();
    for (int k = 2; k <= 1024; k <<= 1) {
        for (int j = k >> 1; j > 0; j >>= 1) {
#pragma unroll
            for (int mm = 0; mm < 2; mm++) {
                int i = t + mm*512;
                int l = i ^ j;
                if (l > i) {
                    float vi = sv[i], vl = sv[l];
                    int ii = si[i], il = si[l];
                    bool before = (vi > vl) || (vi == vl && ii < il);
                    bool keep = ((i & k) == 0) ? before : !before;
                    if (!keep) { sv[i] = vl; sv[l] = vi; si[i] = il; si[l] = ii; }
                }
            }
            __syncthreads();
        }
    }
    if (t < 256) g_topk[bh*KF + t] = si[t];
}

// ---------------- attn @ V (tf32 3x) ----------------
// grid (32 bh, 16 qt) block 256
__global__ __launch_bounds__(256) void k_av_t(int fine) {
    int bh = blockIdx.x, qt = blockIdx.y;
    int b = bh >> 2, h = bh & 3;
    __shared__ float sA[64*68];
    __shared__ float sV[64*72];
    int t=threadIdx.x, w=t>>5, lane=t&31, gp=lane>>2, tig=lane&3;
    int mrow=(w>>2)*32, ncol=(w&3)*16;
    const float* attn = g_attn + ((size_t)bh << 20) + (size_t)qt*64*1024;
    const float* vptr = g_qkv + (size_t)bh * P * 192 + 128;
    float c[2][2][4];
#pragma unroll
    for (int i=0;i<2;i++)
#pragma unroll
    for (int jn=0;jn<2;jn++)
#pragma unroll
    for (int k=0;k<4;k++) c[i][jn][k]=0.f;

    for (int kc = 0; kc < 16; kc++) {
        __syncthreads();
        for (int idx=t; idx<1024; idx+=256){
            int r=idx>>4, c4=(idx&15)<<2;
            *(float4*)(sA + r*68 + c4) = *(const float4*)(attn + (size_t)r*1024 + kc*64 + c4);
            *(float4*)(sV + r*72 + c4) = *(const float4*)(vptr + (size_t)(kc*64+r)*192 + c4);
        }
        __syncthreads();
#pragma unroll
        for (int kk=0;kk<8;kk++){
            int k0=kk*8;
            unsigned ah[2][4], al[2][4], bhi[2][2], blo[2][2];
#pragma unroll
            for (int mi=0;mi<2;mi++){
                const float* base = sA + (mrow+mi*16+gp)*68 + k0 + tig;
                split_tf(base[0],      ah[mi][0], al[mi][0]);
                split_tf(base[8*68],   ah[mi][1], al[mi][1]);
                split_tf(base[4],      ah[mi][2], al[mi][2]);
                split_tf(base[8*68+4], ah[mi][3], al[mi][3]);
            }
#pragma unroll
            for (int ni=0;ni<2;ni++){
                split_tf(sV[(k0+tig)*72   + ncol+ni*8+gp], bhi[ni][0], blo[ni][0]);
                split_tf(sV[(k0+tig+4)*72 + ncol+ni*8+gp], bhi[ni][1], blo[ni][1]);
            }
#pragma unroll
            for (int mi=0;mi<2;mi++)
#pragma unroll
            for (int ni=0;ni<2;ni++)
                mma3x(c[mi][ni], ah[mi], al[mi], bhi[ni], blo[ni]);
        }
    }
    if (!fine) {
#pragma unroll
        for (int mi=0;mi<2;mi++)
#pragma unroll
        for (int ni=0;ni<2;ni++){
            int row = qt*64 + mrow+mi*16+gp;
            int d0 = ncol+ni*8+2*tig;
            g_outc[((size_t)(b*C + h*HD + d0  ))*PLANE32 + row] = c[mi][ni][0];
            g_outc[((size_t)(b*C + h*HD + d0+1))*PLANE32 + row] = c[mi][ni][1];
            g_outc[((size_t)(b*C + h*HD + d0  ))*PLANE32 + row + 8] = c[mi][ni][2];
            g_outc[((size_t)(b*C + h*HD + d0+1))*PLANE32 + row + 8] = c[mi][ni][3];
        }
    } else {
#pragma unroll
        for (int mi=0;mi<2;mi++)
#pragma unroll
        for (int ni=0;ni<2;ni++){
            int row = qt*64 + mrow+mi*16+gp;
            int d0 = ncol+ni*8+2*tig;
            *(float2*)(g_outf + ((size_t)bh*P + row)*HD + d0) =
                make_float2(c[mi][ni][0], c[mi][ni][1]);
            *(float2*)(g_outf + ((size_t)bh*P + row + 8)*HD + d0) =
                make_float2(c[mi][ni][2], c[mi][ni][3]);
        }
    }
}

// ---------------- y = coarse ----------------
__global__ __launch_bounds__(1024) void k_copy() {
    size_t i = (size_t)blockIdx.x * 1024 + threadIdx.x;
    g_y[i] = g_coarse[i];
}

// ---------------- scatter fine output ----------------
__global__ __launch_bounds__(256) void k_scatter() {
    int bh = blockIdx.x, ki = blockIdx.y;
    int t = threadIdx.x;
    int s = t >> 6, d = t & 63;
    int b = bh >> 2, h = bh & 3;
    int p = g_topk[bh*KF + ki];
    int yy = ((p >> 5) << 1) + (s >> 1);
    int xx = ((p & 31) << 1) + (s & 1);
    float val = g_outf[((size_t)bh * P + ki*4 + s) * HD + d];
    g_y[(((size_t)(b*C + h*HD + d)) << 12) + (yy << 6) + xx] += val;
}

// ---------------- depthwise 3x3 + BN + relu6 ----------------
__global__ __launch_bounds__(256) void k_dw(const float* __restrict__ wdw,
                                            const float* __restrict__ g,
                                            const float* __restrict__ bb,
                                            const float* __restrict__ m,
                                            const float* __restrict__ vv) {
    size_t i = (size_t)blockIdx.x * 256 + threadIdx.x;
    int x = i & 63, y = (i >> 6) & 63;
    int c = (int)((i >> 12) & 255);
    const float* plane = g_y + ((i >> 12) << 12);
    const float* wc = wdw + c*9;
    float s = 0.f;
#pragma unroll
    for (int ky = 0; ky < 3; ky++) {
        int yy = y + ky - 1;
        if (yy < 0 || yy >= 64) continue;
#pragma unroll
        for (int kx = 0; kx < 3; kx++) {
            int xx = x + kx - 1;
            if (xx < 0 || xx >= 64) continue;
            s = fmaf(wc[ky*3 + kx], plane[(yy << 6) + xx], s);
        }
    }
    float sc = g[c] * rsqrtf(vv[c] + 1e-5f);
    float r = s * sc + (bb[c] - m[c] * sc);
    g_yd[i] = fminf(fmaxf(r, 0.f), 6.f);
}

// ---------------- pointwise 1x1 + BN + relu6 ----------------
__global__ __launch_bounds__(256) void k_pw(const float* __restrict__ wpw,
                                            const float* __restrict__ g,
                                            const float* __restrict__ bb,
                                            const float* __restrict__ m,
                                            const float* __restrict__ vv,
                                            float* __restrict__ out) {
    int b = blockIdx.x, sp = blockIdx.y, cg = blockIdx.z;
    __shared__ float sX[32][128];
    __shared__ float sW[64][33];
    int t = threadIdx.x;
    int pxg = (t & 31) << 2;
    int cog = (t >> 5) << 3;
    float acc[8][4];
#pragma unroll
    for (int i = 0; i < 8; i++)
#pragma unroll
        for (int j = 0; j < 4; j++) acc[i][j] = 0.f;
    const float* xin = g_yd + (size_t)b * C * HW + sp * 128;
    for (int cc = 0; cc < 8; cc++) {
        for (int idx = t; idx < 32*128; idx += 256) {
            int r = idx >> 7, c = idx & 127;
            sX[r][c] = xin[(size_t)(cc*32 + r) * HW + c];
        }
        for (int idx = t; idx < 64*32; idx += 256) {
            int co = idx >> 5, kk = idx & 31;
            sW[co][kk] = wpw[(cg*64 + co) * 256 + cc*32 + kk];
        }
        __syncthreads();
#pragma unroll 4
        for (int kk = 0; kk < 32; kk++) {
            float4 xv = *reinterpret_cast<const float4*>(&sX[kk][pxg]);
            float wv[8];
#pragma unroll
            for (int i = 0; i < 8; i++) wv[i] = sW[cog + i][kk];
#pragma unroll
            for (int i = 0; i < 8; i++) {
                acc[i][0] = fmaf(wv[i], xv.x, acc[i][0]);
                acc[i][1] = fmaf(wv[i], xv.y, acc[i][1]);
                acc[i][2] = fmaf(wv[i], xv.z, acc[i][2]);
                acc[i][3] = fmaf(wv[i], xv.w, acc[i][3]);
            }
        }
        __syncthreads();
    }
#pragma unroll
    for (int i = 0; i < 8; i++) {
        int co = cg*64 + cog + i;
        float sc = g[co] * rsqrtf(vv[co] + 1e-5f);
        float off = bb[co] - m[co] * sc;
#pragma unroll
        for (int j = 0; j < 4; j++) {
            float r = acc[i][j] * sc + off;
            r = fminf(fmaxf(r, 0.f), 6.f);
            out[((size_t)(b*C + co)) * HW + sp*128 + pxg + j] = r;
        }
    }
}

// ---------------- launch ----------------
extern "C" void kernel_launch(void* const* d_in, const int* in_sizes, int n_in,
                              void* d_out, int out_size) {
    const float* x       = (const float*)d_in[0];
    const float* w_down  = (const float*)d_in[1];
    const float* b_down  = (const float*)d_in[2];
    const float* w_qkv_c = (const float*)d_in[3];
    const float* b_qkv_c = (const float*)d_in[4];
    const float* w_up    = (const float*)d_in[5];
    const float* b_up    = (const float*)d_in[6];
    const float* w_qkv_f = (const float*)d_in[7];
    const float* b_qkv_f = (const float*)d_in[8];
    const float* w_dw    = (const float*)d_in[9];
    const float* bn_dw_g = (const float*)d_in[10];
    const float* bn_dw_b = (const float*)d_in[11];
    const float* bn_dw_m = (const float*)d_in[12];
    const float* bn_dw_v = (const float*)d_in[13];
    const float* w_pw    = (const float*)d_in[14];
    const float* bn_pw_g = (const float*)d_in[15];
    const float* bn_pw_b = (const float*)d_in[16];
    const float* bn_pw_m = (const float*)d_in[17];
    const float* bn_pw_v = (const float*)d_in[18];
    float* out = (float*)d_out;

    k_wt<<<4096, 256>>>(w_up);

    // ---- coarse attention path ----
    k_down_t<<<dim3(64, 4), 256>>>(x, w_down, b_down);
    k_qkv<<<dim3(32, 16), 256>>>(w_qkv_c, b_qkv_c, 0);
    k_logits_t<<<dim3(32, 16), 256>>>();
    k_softmax<<<dim3(32, 1024), 256>>>();
    k_colsum<<<dim3(32, 4), 256>>>();
    k_av_t<<<dim3(32, 16), 256>>>(0);
    k_topk<<<32, 512>>>();
    k_up_t<<<dim3(64, 16), 256>>>(b_up);

    // ---- fine (top-k) attention path ----
    k_qkv<<<dim3(32, 16), 256>>>(w_qkv_f, b_qkv_f, 1);
    k_logits_t<<<dim3(32, 16), 256>>>();
    k_softmax<<<dim3(32, 1024), 256>>>();
    k_av_t<<<dim3(32, 16), 256>>>(1);

    // ---- combine + feed-forward ----
    k_copy<<<8192, 1024>>>();
    k_scatter<<<dim3(32, 256), 256>>>();
    k_dw<<<32768, 256>>>(w_dw, bn_dw_g, bn_dw_b, bn_dw_m, bn_dw_v);
    k_pw<<<dim3(8, 32, 4), 256>>>(w_pw, bn_pw_g, bn_pw_b, bn_pw_m, bn_pw_v, out);
}

// round 3
// speedup vs baseline: 2.0489x; 1.1498x over previous
#include <cuda_runtime.h>
#include <math.h>

// ---------------- problem constants ----------------
#define BATCH 8
#define C 256
#define H 64
#define W 64
#define NH 4
#define HD 64
#define P 1024
#define KF 256
#define HW (H*W)
#define PLANE32 1024

// ---------------- device scratch ----------------
__device__ float g_xd[BATCH*C*PLANE32];
__device__ float g_qkv[BATCH*NH*P*192];
__device__ float g_attn[(size_t)BATCH*NH*P*P];
__device__ float g_outc[BATCH*C*PLANE32];
__device__ float g_coarse[BATCH*C*HW];
__device__ float g_score[BATCH*NH*P];
__device__ int   g_topk[BATCH*NH*KF];
__device__ float g_outf[BATCH*NH*P*HD];
__device__ float g_y[BATCH*C*HW];
__device__ float g_yd[BATCH*C*HW];
__device__ float g_wupt[4*256*1024];   // transposed convT weights [cls][co][ci*4+j]

// ---------------- tf32 mma helpers ----------------
// mask-split: hi = top-10-mantissa truncation (valid tf32), lo = exact remainder.
__device__ __forceinline__ void msplit(float x, unsigned &hi, unsigned &lo){
    unsigned xb = __float_as_uint(x);
    hi = xb & 0xFFFFE000u;
    lo = __float_as_uint(x - __uint_as_float(hi));
}
__device__ __forceinline__ void mma8(float* c, unsigned a0,unsigned a1,unsigned a2,unsigned a3,
                                     unsigned b0,unsigned b1){
    asm volatile("mma.sync.aligned.m16n8k8.row.col.f32.tf32.tf32.f32 "
        "{%0,%1,%2,%3}, {%4,%5,%6,%7}, {%8,%9}, {%0,%1,%2,%3};"
        : "+f"(c[0]),"+f"(c[1]),"+f"(c[2]),"+f"(c[3])
        : "r"(a0),"r"(a1),"r"(a2),"r"(a3),"r"(b0),"r"(b1));
}
__device__ __forceinline__ void mma3x(float* c, const unsigned* ah, const unsigned* al,
                                      const unsigned* bh, const unsigned* bl){
    mma8(c, ah[0],ah[1],ah[2],ah[3], bh[0],bh[1]);
    mma8(c, ah[0],ah[1],ah[2],ah[3], bl[0],bl[1]);
    mma8(c, al[0],al[1],al[2],al[3], bh[0],bh[1]);
}

// ---------------- weight pre-transpose for convT ----------------
__global__ __launch_bounds__(256) void k_wt(const float* __restrict__ wup){
    int idx = blockIdx.x*256 + threadIdx.x;      // [cls][co][ci][j]
    int cls = idx>>18, co = (idx>>10)&255, ci = (idx>>2)&255, j = idx&3;
    int py = cls>>1, pxp = cls&1;
    int ky = py + ((j>>1)<<1), kx = pxp + ((j&1)<<1);
    g_wupt[idx] = wup[((size_t)ci*256 + co)*16 + ky*4 + kx];
}

// ---------------- down conv (implicit GEMM, tf32 3x) ----------------
// grid (128, 4): bx -> b=bx>>4, oyp=bx&15 (2 output rows); by -> co tile of 64
__global__ __launch_bounds__(256) void k_down_t(const float* __restrict__ x,
                                                const float* __restrict__ wgt,
                                                const float* __restrict__ bias){
    int b = blockIdx.x>>4, oyp = blockIdx.x&15;
    int co0 = blockIdx.y*64;
    __shared__ float sW[64*68];
    __shared__ float sraw[4*6*72];
    int t=threadIdx.x, w=t>>5, lane=t&31, gp=lane>>2, tig=lane&3;
    int mrow=(w>>2)*32, ncol=(w&3)*16;
    float c[2][2][4];
#pragma unroll
    for (int i=0;i<2;i++)
#pragma unroll
    for (int jn=0;jn<2;jn++)
#pragma unroll
    for (int k=0;k<4;k++) c[i][jn][k]=0.f;

    for (int cc=0; cc<64; cc++){
        __syncthreads();
        for (int idx=t; idx<1024; idx+=256){
            int co=idx>>4, c4=(idx&15)<<2;
            *(float4*)(sW + co*68 + c4) =
                *(const float4*)(wgt + (size_t)(co0+co)*4096 + cc*64 + c4);
        }
        int ci0 = cc*4;
        for (int idx=t; idx<384; idx+=256){
            int rowid = idx>>4, c4=(idx&15)<<2;
            int ci4 = rowid/6, r = rowid - ci4*6;
            int iy = oyp*4 - 1 + r;
            float4 v = make_float4(0.f,0.f,0.f,0.f);
            if (iy>=0 && iy<64)
                v = *(const float4*)(x + (((size_t)(b*C + ci0+ci4))<<12) + (iy<<6) + c4);
            *(float4*)(sraw + rowid*72 + 4 + c4) = v;
        }
        if (t<24){ sraw[t*72+3]=0.f; sraw[t*72+68]=0.f; }
        __syncthreads();
#pragma unroll
        for (int kk=0;kk<8;kk++){
            int k0=kk*8;
            unsigned ah[2][4], al[2][4], bhi[2][2], blo[2][2];
#pragma unroll
            for (int mi=0;mi<2;mi++){
                const float* base = sW + (mrow+mi*16+gp)*68 + k0 + tig;
                msplit(base[0],      ah[mi][0], al[mi][0]);
                msplit(base[8*68],   ah[mi][1], al[mi][1]);
                msplit(base[4],      ah[mi][2], al[mi][2]);
                msplit(base[8*68+4], ah[mi][3], al[mi][3]);
            }
#pragma unroll
            for (int ni=0;ni<2;ni++){
                int n = ncol+ni*8+gp; int opy=n>>5, opx=n&31;
#pragma unroll
                for (int kj=0;kj<2;kj++){
                    int k = k0+tig+kj*4;
                    int ci4=k>>4, tap=k&15, ky=tap>>2, kx=tap&3;
                    float v = sraw[(ci4*6 + 2*opy+ky)*72 + 3 + 2*opx + kx];
                    msplit(v, bhi[ni][kj], blo[ni][kj]);
                }
            }
#pragma unroll
            for (int mi=0;mi<2;mi++)
#pragma unroll
            for (int ni=0;ni<2;ni++)
                mma3x(c[mi][ni], ah[mi], al[mi], bhi[ni], blo[ni]);
        }
    }
#pragma unroll
    for (int mi=0;mi<2;mi++){
        int co = co0+mrow+mi*16+gp;
        float b0v = bias[co], b1v = bias[co+8];
#pragma unroll
        for (int ni=0;ni<2;ni++){
            int n = ncol+ni*8+2*tig;
            size_t o = ((size_t)(b*C+co)<<10) + oyp*64 + n;
            *(float2*)(g_xd + o) = make_float2(c[mi][ni][0]+b0v, c[mi][ni][1]+b0v);
            *(float2*)(g_xd + o + (8<<10)) = make_float2(c[mi][ni][2]+b1v, c[mi][ni][3]+b1v);
        }
    }
}

// ---------------- convT (implicit GEMM per parity class, tf32 3x) ----------------
// grid (64, 16): bx -> b=bx>>3, uq=bx&7 ; by -> cls=by>>2, co tile = (by&3)*64
__global__ __launch_bounds__(256) void k_up_t(const float* __restrict__ bup){
    int b = blockIdx.x>>3, uq = blockIdx.x&7;
    int cls = blockIdx.y>>2, co0 = (blockIdx.y&3)*64;
    int py = cls>>1, pxp = cls&1;
    __shared__ float sW[64*68];
    __shared__ float sraw[16*5*40];
    int t=threadIdx.x, w=t>>5, lane=t&31, gp=lane>>2, tig=lane&3;
    int mrow=(w>>2)*32, ncol=(w&3)*32;
    float c[2][4][4];
#pragma unroll
    for (int i=0;i<2;i++)
#pragma unroll
    for (int jn=0;jn<4;jn++)
#pragma unroll
    for (int k=0;k<4;k++) c[i][jn][k]=0.f;

    for (int cc=0; cc<16; cc++){
        __syncthreads();
        for (int idx=t; idx<1024; idx+=256){
            int co=idx>>4, c4=(idx&15)<<2;
            *(float4*)(sW + co*68 + c4) =
                *(const float4*)(g_wupt + (size_t)cls*262144 + (size_t)(co0+co)*1024 + cc*64 + c4);
        }
        int ci0 = cc*16;
        for (int idx=t; idx<640; idx+=256){
            int rowid=idx>>3, c4=(idx&7)<<2;
            int ci16=rowid/5, rr=rowid-ci16*5;
            int iy = uq*4 - py + rr;
            float4 v = make_float4(0.f,0.f,0.f,0.f);
            if (iy>=0 && iy<32)
                v = *(const float4*)(g_outc + (((size_t)(b*C+ci0+ci16))<<10) + (iy<<5) + c4);
            *(float4*)(sraw + rowid*40 + 4 + c4) = v;
        }
        if (t<80){ sraw[t*40+3]=0.f; sraw[t*40+36]=0.f; }
        __syncthreads();
#pragma unroll
        for (int kk=0;kk<8;kk++){
            int k0=kk*8;
            unsigned ah[2][4], al[2][4], bhi[4][2], blo[4][2];
#pragma unroll
            for (int mi=0;mi<2;mi++){
                const float* base = sW + (mrow+mi*16+gp)*68 + k0 + tig;
                msplit(base[0],      ah[mi][0], al[mi][0]);
                msplit(base[8*68],   ah[mi][1], al[mi][1]);
                msplit(base[4],      ah[mi][2], al[mi][2]);
                msplit(base[8*68+4], ah[mi][3], al[mi][3]);
            }
#pragma unroll
            for (int ni=0;ni<4;ni++){
                int n = ncol+ni*8+gp; int uu=n>>5, vv=n&31;
#pragma unroll
                for (int kj=0;kj<2;kj++){
                    int k = k0+tig+kj*4;
                    int ci16=k>>2, j=k&3;
                    float v = sraw[(ci16*5 + uu+1-(j>>1))*40 + vv + 5 - pxp - (j&1)];
                    msplit(v, bhi[ni][kj], blo[ni][kj]);
                }
            }
#pragma unroll
            for (int mi=0;mi<2;mi++)
#pragma unroll
            for (int ni=0;ni<4;ni++)
                mma3x(c[mi][ni], ah[mi], al[mi], bhi[ni], blo[ni]);
        }
    }
#pragma unroll
    for (int mi=0;mi<2;mi++){
        int co = co0+mrow+mi*16+gp;
        float b0v = bup[co], b1v = bup[co+8];
#pragma unroll
        for (int ni=0;ni<4;ni++){
            int n = ncol+ni*8+2*tig; int uu=n>>5, vv=n&31;
            int oy = 2*(uq*4+uu) + 1 - py;
            int ox = 2*vv + 1 - pxp;
            size_t o0 = (((size_t)(b*C+co))<<12) + oy*64 + ox;
            g_coarse[o0]     = c[mi][ni][0]+b0v;
            g_coarse[o0+2]   = c[mi][ni][1]+b0v;
            size_t o1 = (((size_t)(b*C+co+8))<<12) + oy*64 + ox;
            g_coarse[o1]     = c[mi][ni][2]+b1v;
            g_coarse[o1+2]   = c[mi][ni][3]+b1v;
        }
    }
}

// ---------------- qkv projection (FFMA) ----------------
__global__ __launch_bounds__(256) void k_qkv(const float* __restrict__ Wm,
                                             const float* __restrict__ bias,
                                             int fine) {
    int bh = blockIdx.x, pt = blockIdx.y;
    int b = bh >> 2, h = bh & 3;
    __shared__ float sA[64][65];
    __shared__ float sW[64][97];
    int t = threadIdx.x;
    if (!fine) {
        const float* src = g_xd + ((size_t)(b*C + h*HD)) * PLANE32 + pt*64;
        for (int idx = t; idx < 4096; idx += 256) {
            int d = idx >> 6, p = idx & 63;
            sA[p][d] = src[d * PLANE32 + p];
        }
    } else {
        for (int idx = t; idx < 4096; idx += 256) {
            int d = idx >> 6, p = idx & 63;
            int tok = pt*64 + p;
            int ki = tok >> 2, s = tok & 3;
            int pi = g_topk[bh*KF + ki];
            int yy = ((pi >> 5) << 1) + (s >> 1);
            int xx = ((pi & 31) << 1) + (s & 1);
            sA[p][d] = g_coarse[(((size_t)(b*C + h*HD + d)) << 12) + (yy << 6) + xx];
        }
    }
    float* dst = g_qkv + ((size_t)bh * P + pt*64) * 192;
    int p0 = (t >> 4) << 2, n0 = (t & 15) * 6;
    for (int half = 0; half < 2; half++) {
        __syncthreads();
        for (int idx = t; idx < 64*96; idx += 256) {
            int d = idx / 96, n = idx - d*96;
            sW[d][n] = Wm[d*192 + half*96 + n];
        }
        __syncthreads();
        float acc[4][6];
#pragma unroll
        for (int i = 0; i < 4; i++)
#pragma unroll
            for (int j = 0; j < 6; j++) acc[i][j] = 0.f;
#pragma unroll 8
        for (int d = 0; d < 64; d++) {
            float a0 = sA[p0][d], a1 = sA[p0+1][d], a2 = sA[p0+2][d], a3 = sA[p0+3][d];
#pragma unroll
            for (int j = 0; j < 6; j++) {
                float wv = sW[d][n0+j];
                acc[0][j] = fmaf(a0, wv, acc[0][j]);
                acc[1][j] = fmaf(a1, wv, acc[1][j]);
                acc[2][j] = fmaf(a2, wv, acc[2][j]);
                acc[3][j] = fmaf(a3, wv, acc[3][j]);
            }
        }
#pragma unroll
        for (int i = 0; i < 4; i++)
#pragma unroll
            for (int j = 0; j < 6; j++)
                dst[(p0+i)*192 + half*96 + n0 + j] = acc[i][j] + bias[half*96 + n0 + j];
    }
}

// ---------------- attention logits (tf32 3x): attn = QK^T * 0.125 -----------
// grid (32 bh, 16 qt, 2 kz) block 256
__global__ __launch_bounds__(256) void k_logits_t() {
    int bh = blockIdx.x, qt = blockIdx.y, kz = blockIdx.z;
    __shared__ float sQ[64*68];
    __shared__ float sK[64*68];
    int t=threadIdx.x, w=t>>5, lane=t&31, gp=lane>>2, tig=lane&3;
    int mrow=(w>>2)*32, ncol=(w&3)*16;
    const float* qkv = g_qkv + (size_t)bh*P*192;
    for (int idx=t; idx<1024; idx+=256){
        int r=idx>>4, c4=(idx&15)<<2;
        *(float4*)(sQ + r*68 + c4) = *(const float4*)(qkv + (qt*64+r)*192 + c4);
    }
    float* dst = g_attn + ((size_t)bh<<20) + (size_t)qt*64*1024;
    for (int kt=kz*8; kt<kz*8+8; kt++){
        __syncthreads();
        for (int idx=t; idx<1024; idx+=256){
            int r=idx>>4, c4=(idx&15)<<2;
            *(float4*)(sK + r*68 + c4) = *(const float4*)(qkv + (kt*64+r)*192 + 64 + c4);
        }
        __syncthreads();
        float c[2][2][4];
#pragma unroll
        for (int i=0;i<2;i++)
#pragma unroll
        for (int jn=0;jn<2;jn++)
#pragma unroll
        for (int k=0;k<4;k++) c[i][jn][k]=0.f;
#pragma unroll
        for (int kk=0;kk<8;kk++){
            int k0=kk*8;
            unsigned ah[2][4], al[2][4], bhi[2][2], blo[2][2];
#pragma unroll
            for (int mi=0;mi<2;mi++){
                const float* base = sQ + (mrow+mi*16+gp)*68 + k0 + tig;
                msplit(base[0],      ah[mi][0], al[mi][0]);
                msplit(base[8*68],   ah[mi][1], al[mi][1]);
                msplit(base[4],      ah[mi][2], al[mi][2]);
                msplit(base[8*68+4], ah[mi][3], al[mi][3]);
            }
#pragma unroll
            for (int ni=0;ni<2;ni++){
                const float* base = sK + (ncol+ni*8+gp)*68 + k0 + tig;
                msplit(base[0], bhi[ni][0], blo[ni][0]);
                msplit(base[4], bhi[ni][1], blo[ni][1]);
            }
#pragma unroll
            for (int mi=0;mi<2;mi++)
#pragma unroll
            for (int ni=0;ni<2;ni++)
                mma3x(c[mi][ni], ah[mi], al[mi], bhi[ni], blo[ni]);
        }
#pragma unroll
        for (int mi=0;mi<2;mi++)
#pragma unroll
        for (int ni=0;ni<2;ni++){
            int row = mrow+mi*16+gp, col = kt*64+ncol+ni*8+2*tig;
            *(float2*)(dst + (size_t)row*1024 + col) =
                make_float2(c[mi][ni][0]*0.125f, c[mi][ni][1]*0.125f);
            *(float2*)(dst + (size_t)(row+8)*1024 + col) =
                make_float2(c[mi][ni][2]*0.125f, c[mi][ni][3]*0.125f);
        }
    }
}

// ---------------- softmax ----------------
__global__ __launch_bounds__(256) void k_softmax() {
    float* row = g_attn + ((size_t)blockIdx.x * 1024 + blockIdx.y) * 1024;
    int t = threadIdx.x;
    float v0 = row[t], v1 = row[t+256], v2 = row[t+512], v3 = row[t+768];
    float m = fmaxf(fmaxf(v0, v1), fmaxf(v2, v3));
    __shared__ float red[8];
    __shared__ float red2[8];
#pragma unroll
    for (int o = 16; o; o >>= 1) m = fmaxf(m, __shfl_xor_sync(0xffffffffu, m, o));
    if ((t & 31) == 0) red[t >> 5] = m;
    __syncthreads();
    if (t == 0) {
        float mm = red[0];
#pragma unroll
        for (int i = 1; i < 8; i++) mm = fmaxf(mm, red[i]);
        red[0] = mm;
    }
    __syncthreads();
    m = red[0];
    float e0 = __expf(v0 - m), e1 = __expf(v1 - m), e2 = __expf(v2 - m), e3 = __expf(v3 - m);
    float s = e0 + e1 + e2 + e3;
#pragma unroll
    for (int o = 16; o; o >>= 1) s += __shfl_xor_sync(0xffffffffu, s, o);
    if ((t & 31) == 0) red2[t >> 5] = s;
    __syncthreads();
    if (t == 0) {
        float ss = 0.f;
#pragma unroll
        for (int i = 0; i < 8; i++) ss += red2[i];
        red2[0] = ss;
    }
    __syncthreads();
    float inv = 1.0f / red2[0];
    row[t] = e0*inv; row[t+256] = e1*inv; row[t+512] = e2*inv; row[t+768] = e3*inv;
}

// ---------------- column sums ----------------
__global__ __launch_bounds__(256) void k_colsum() {
    int bh = blockIdx.x;
    int k = blockIdx.y * 256 + threadIdx.x;
    const float* a = g_attn + ((size_t)bh << 20) + k;
    float s = 0.f;
#pragma unroll 8
    for (int q = 0; q < 1024; q++) s += a[(size_t)q << 10];
    g_score[bh*1024 + k] = s;
}

// ---------------- top-k bitonic ----------------
__global__ __launch_bounds__(512) void k_topk() {
    int bh = blockIdx.x;
    __shared__ float sv[1024];
    __shared__ int si[1024];
    int t = threadIdx.x;
    sv[t]       = g_score[bh*1024 + t];       si[t]       = t;
    sv[t + 512] = g_score[bh*1024 + t + 512]; si[t + 512] = t + 512;
    __syncthreads();
    for (int k = 2; k <= 1024; k <<= 1) {
        for (int j = k >> 1; j > 0; j >>= 1) {
#pragma unroll
            for (int mm = 0; mm < 2; mm++) {
                int i = t + mm*512;
                int l = i ^ j;
                if (l > i) {
                    float vi = sv[i], vl = sv[l];
                    int ii = si[i], il = si[l];
                    bool before = (vi > vl) || (vi == vl && ii < il);
                    bool keep = ((i & k) == 0) ? before : !before;
                    if (!keep) { sv[i] = vl; sv[l] = vi; si[i] = il; si[l] = ii; }
                }
            }
            __syncthreads();
        }
    }
    if (t < 256) g_topk[bh*KF + t] = si[t];
}

// ---------------- attn @ V (tf32 3x) ----------------
// grid (32 bh, 16 qt) block 256
__global__ __launch_bounds__(256) void k_av_t(int fine) {
    int bh = blockIdx.x, qt = blockIdx.y;
    int b = bh >> 2, h = bh & 3;
    __shared__ float sA[64*68];
    __shared__ float sV[64*72];
    int t=threadIdx.x, w=t>>5, lane=t&31, gp=lane>>2, tig=lane&3;
    int mrow=(w>>2)*32, ncol=(w&3)*16;
    const float* attn = g_attn + ((size_t)bh << 20) + (size_t)qt*64*1024;
    const float* vptr = g_qkv + (size_t)bh * P * 192 + 128;
    float c[2][2][4];
#pragma unroll
    for (int i=0;i<2;i++)
#pragma unroll
    for (int jn=0;jn<2;jn++)
#pragma unroll
    for (int k=0;k<4;k++) c[i][jn][k]=0.f;

    for (int kc = 0; kc < 16; kc++) {
        __syncthreads();
        for (int idx=t; idx<1024; idx+=256){
            int r=idx>>4, c4=(idx&15)<<2;
            *(float4*)(sA + r*68 + c4) = *(const float4*)(attn + (size_t)r*1024 + kc*64 + c4);
            *(float4*)(sV + r*72 + c4) = *(const float4*)(vptr + (size_t)(kc*64+r)*192 + c4);
        }
        __syncthreads();
#pragma unroll
        for (int kk=0;kk<8;kk++){
            int k0=kk*8;
            unsigned ah[2][4], al[2][4], bhi[2][2], blo[2][2];
#pragma unroll
            for (int mi=0;mi<2;mi++){
                const float* base = sA + (mrow+mi*16+gp)*68 + k0 + tig;
                msplit(base[0],      ah[mi][0], al[mi][0]);
                msplit(base[8*68],   ah[mi][1], al[mi][1]);
                msplit(base[4],      ah[mi][2], al[mi][2]);
                msplit(base[8*68+4], ah[mi][3], al[mi][3]);
            }
#pragma unroll
            for (int ni=0;ni<2;ni++){
                msplit(sV[(k0+tig)*72   + ncol+ni*8+gp], bhi[ni][0], blo[ni][0]);
                msplit(sV[(k0+tig+4)*72 + ncol+ni*8+gp], bhi[ni][1], blo[ni][1]);
            }
#pragma unroll
            for (int mi=0;mi<2;mi++)
#pragma unroll
            for (int ni=0;ni<2;ni++)
                mma3x(c[mi][ni], ah[mi], al[mi], bhi[ni], blo[ni]);
        }
    }
    if (!fine) {
#pragma unroll
        for (int mi=0;mi<2;mi++)
#pragma unroll
        for (int ni=0;ni<2;ni++){
            int row = qt*64 + mrow+mi*16+gp;
            int d0 = ncol+ni*8+2*tig;
            g_outc[((size_t)(b*C + h*HD + d0  ))*PLANE32 + row] = c[mi][ni][0];
            g_outc[((size_t)(b*C + h*HD + d0+1))*PLANE32 + row] = c[mi][ni][1];
            g_outc[((size_t)(b*C + h*HD + d0  ))*PLANE32 + row + 8] = c[mi][ni][2];
            g_outc[((size_t)(b*C + h*HD + d0+1))*PLANE32 + row + 8] = c[mi][ni][3];
        }
    } else {
#pragma unroll
        for (int mi=0;mi<2;mi++)
#pragma unroll
        for (int ni=0;ni<2;ni++){
            int row = qt*64 + mrow+mi*16+gp;
            int d0 = ncol+ni*8+2*tig;
            *(float2*)(g_outf + ((size_t)bh*P + row)*HD + d0) =
                make_float2(c[mi][ni][0], c[mi][ni][1]);
            *(float2*)(g_outf + ((size_t)bh*P + row + 8)*HD + d0) =
                make_float2(c[mi][ni][2], c[mi][ni][3]);
        }
    }
}

// ---------------- y = coarse ----------------
__global__ __launch_bounds__(1024) void k_copy() {
    size_t i = (size_t)blockIdx.x * 1024 + threadIdx.x;
    g_y[i] = g_coarse[i];
}

// ---------------- scatter fine output ----------------
__global__ __launch_bounds__(256) void k_scatter() {
    int bh = blockIdx.x, ki = blockIdx.y;
    int t = threadIdx.x;
    int s = t >> 6, d = t & 63;
    int b = bh >> 2, h = bh & 3;
    int p = g_topk[bh*KF + ki];
    int yy = ((p >> 5) << 1) + (s >> 1);
    int xx = ((p & 31) << 1) + (s & 1);
    float val = g_outf[((size_t)bh * P + ki*4 + s) * HD + d];
    g_y[(((size_t)(b*C + h*HD + d)) << 12) + (yy << 6) + xx] += val;
}

// ---------------- depthwise 3x3 + BN + relu6 ----------------
__global__ __launch_bounds__(256) void k_dw(const float* __restrict__ wdw,
                                            const float* __restrict__ g,
                                            const float* __restrict__ bb,
                                            const float* __restrict__ m,
                                            const float* __restrict__ vv) {
    size_t i = (size_t)blockIdx.x * 256 + threadIdx.x;
    int x = i & 63, y = (i >> 6) & 63;
    int c = (int)((i >> 12) & 255);
    const float* plane = g_y + ((i >> 12) << 12);
    const float* wc = wdw + c*9;
    float s = 0.f;
#pragma unroll
    for (int ky = 0; ky < 3; ky++) {
        int yy = y + ky - 1;
        if (yy < 0 || yy >= 64) continue;
#pragma unroll
        for (int kx = 0; kx < 3; kx++) {
            int xx = x + kx - 1;
            if (xx < 0 || xx >= 64) continue;
            s = fmaf(wc[ky*3 + kx], plane[(yy << 6) + xx], s);
        }
    }
    float sc = g[c] * rsqrtf(vv[c] + 1e-5f);
    float r = s * sc + (bb[c] - m[c] * sc);
    g_yd[i] = fminf(fmaxf(r, 0.f), 6.f);
}

// ---------------- pointwise 1x1 + BN + relu6 ----------------
__global__ __launch_bounds__(256) void k_pw(const float* __restrict__ wpw,
                                            const float* __restrict__ g,
                                            const float* __restrict__ bb,
                                            const float* __restrict__ m,
                                            const float* __restrict__ vv,
                                            float* __restrict__ out) {
    int b = blockIdx.x, sp = blockIdx.y, cg = blockIdx.z;
    __shared__ float sX[32][128];
    __shared__ float sW[64][33];
    int t = threadIdx.x;
    int pxg = (t & 31) << 2;
    int cog = (t >> 5) << 3;
    float acc[8][4];
#pragma unroll
    for (int i = 0; i < 8; i++)
#pragma unroll
        for (int j = 0; j < 4; j++) acc[i][j] = 0.f;
    const float* xin = g_yd + (size_t)b * C * HW + sp * 128;
    for (int cc = 0; cc < 8; cc++) {
        for (int idx = t; idx < 32*128; idx += 256) {
            int r = idx >> 7, c = idx & 127;
            sX[r][c] = xin[(size_t)(cc*32 + r) * HW + c];
        }
        for (int idx = t; idx < 64*32; idx += 256) {
            int co = idx >> 5, kk = idx & 31;
            sW[co][kk] = wpw[(cg*64 + co) * 256 + cc*32 + kk];
        }
        __syncthreads();
#pragma unroll 4
        for (int kk = 0; kk < 32; kk++) {
            float4 xv = *reinterpret_cast<const float4*>(&sX[kk][pxg]);
            float wv[8];
#pragma unroll
            for (int i = 0; i < 8; i++) wv[i] = sW[cog + i][kk];
#pragma unroll
            for (int i = 0; i < 8; i++) {
                acc[i][0] = fmaf(wv[i], xv.x, acc[i][0]);
                acc[i][1] = fmaf(wv[i], xv.y, acc[i][1]);
                acc[i][2] = fmaf(wv[i], xv.z, acc[i][2]);
                acc[i][3] = fmaf(wv[i], xv.w, acc[i][3]);
            }
        }
        __syncthreads();
    }
#pragma unroll
    for (int i = 0; i < 8; i++) {
        int co = cg*64 + cog + i;
        float sc = g[co] * rsqrtf(vv[co] + 1e-5f);
        float off = bb[co] - m[co] * sc;
#pragma unroll
        for (int j = 0; j < 4; j++) {
            float r = acc[i][j] * sc + off;
            r = fminf(fmaxf(r, 0.f), 6.f);
            out[((size_t)(b*C + co)) * HW + sp*128 + pxg + j] = r;
        }
    }
}

// ---------------- launch ----------------
extern "C" void kernel_launch(void* const* d_in, const int* in_sizes, int n_in,
                              void* d_out, int out_size) {
    const float* x       = (const float*)d_in[0];
    const float* w_down  = (const float*)d_in[1];
    const float* b_down  = (const float*)d_in[2];
    const float* w_qkv_c = (const float*)d_in[3];
    const float* b_qkv_c = (const float*)d_in[4];
    const float* w_up    = (const float*)d_in[5];
    const float* b_up    = (const float*)d_in[6];
    const float* w_qkv_f = (const float*)d_in[7];
    const float* b_qkv_f = (const float*)d_in[8];
    const float* w_dw    = (const float*)d_in[9];
    const float* bn_dw_g = (const float*)d_in[10];
    const float* bn_dw_b = (const float*)d_in[11];
    const float* bn_dw_m = (const float*)d_in[12];
    const float* bn_dw_v = (const float*)d_in[13];
    const float* w_pw    = (const float*)d_in[14];
    const float* bn_pw_g = (const float*)d_in[15];
    const float* bn_pw_b = (const float*)d_in[16];
    const float* bn_pw_m = (const float*)d_in[17];
    const float* bn_pw_v = (const float*)d_in[18];
    float* out = (float*)d_out;

    k_wt<<<4096, 256>>>(w_up);

    // ---- coarse attention path ----
    k_down_t<<<dim3(128, 4), 256>>>(x, w_down, b_down);
    k_qkv<<<dim3(32, 16), 256>>>(w_qkv_c, b_qkv_c, 0);
    k_logits_t<<<dim3(32, 16, 2), 256>>>();
    k_softmax<<<dim3(32, 1024), 256>>>();
    k_colsum<<<dim3(32, 4), 256>>>();
    k_av_t<<<dim3(32, 16), 256>>>(0);
    k_topk<<<32, 512>>>();
    k_up_t<<<dim3(64, 16), 256>>>(b_up);

    // ---- fine (top-k) attention path ----
    k_qkv<<<dim3(32, 16), 256>>>(w_qkv_f, b_qkv_f, 1);
    k_logits_t<<<dim3(32, 16, 2), 256>>>();
    k_softmax<<<dim3(32, 1024), 256>>>();
    k_av_t<<<dim3(32, 16), 256>>>(1);

    // ---- combine + feed-forward ----
    k_copy<<<8192, 1024>>>();
    k_scatter<<<dim3(32, 256), 256>>>();
    k_dw<<<32768, 256>>>(w_dw, bn_dw_g, bn_dw_b, bn_dw_m, bn_dw_v);
    k_pw<<<dim3(8, 32, 4), 256>>>(w_pw, bn_pw_g, bn_pw_b, bn_pw_m, bn_pw_v, out);
}

// round 5
// speedup vs baseline: 2.2883x; 1.1169x over previous
#include <cuda_runtime.h>
#include <math.h>

// ---------------- problem constants ----------------
#define BATCH 8
#define C 256
#define H 64
#define W 64
#define NH 4
#define HD 64
#define P 1024
#define KF 256
#define HW (H*W)
#define PLANE32 1024

// ---------------- device scratch ----------------
__device__ float g_xd[BATCH*C*PLANE32];
__device__ float g_qkv[BATCH*NH*P*192];
__device__ float g_attn[(size_t)BATCH*NH*P*P];
__device__ float g_outc[BATCH*C*PLANE32];
__device__ float g_coarse[BATCH*C*HW];
__device__ float g_score[BATCH*NH*P];
__device__ int   g_topk[BATCH*NH*KF];
__device__ float g_outf[BATCH*NH*P*HD];
__device__ float g_y[BATCH*C*HW];
__device__ float g_yd[BATCH*C*HW];
__device__ float g_wupt[4*256*1024];   // transposed convT weights [cls][co][ci*4+j]

// ---------------- tf32 mma helpers ----------------
__device__ __forceinline__ void msplit(float x, unsigned &hi, unsigned &lo){
    unsigned xb = __float_as_uint(x);
    hi = xb & 0xFFFFE000u;
    lo = __float_as_uint(x - __uint_as_float(hi));
}
__device__ __forceinline__ void mma8(float* c, unsigned a0,unsigned a1,unsigned a2,unsigned a3,
                                     unsigned b0,unsigned b1){
    asm volatile("mma.sync.aligned.m16n8k8.row.col.f32.tf32.tf32.f32 "
        "{%0,%1,%2,%3}, {%4,%5,%6,%7}, {%8,%9}, {%0,%1,%2,%3};"
        : "+f"(c[0]),"+f"(c[1]),"+f"(c[2]),"+f"(c[3])
        : "r"(a0),"r"(a1),"r"(a2),"r"(a3),"r"(b0),"r"(b1));
}
__device__ __forceinline__ void mma3x(float* c, const unsigned* ah, const unsigned* al,
                                      const unsigned* bh, const unsigned* bl){
    mma8(c, ah[0],ah[1],ah[2],ah[3], bh[0],bh[1]);
    mma8(c, ah[0],ah[1],ah[2],ah[3], bl[0],bl[1]);
    mma8(c, al[0],al[1],al[2],al[3], bh[0],bh[1]);
}

// ---------------- weight pre-transpose for convT ----------------
__global__ __launch_bounds__(256) void k_wt(const float* __restrict__ wup){
    int idx = blockIdx.x*256 + threadIdx.x;      // [cls][co][ci][j]
    int cls = idx>>18, co = (idx>>10)&255, ci = (idx>>2)&255, j = idx&3;
    int py = cls>>1, pxp = cls&1;
    int ky = py + ((j>>1)<<1), kx = pxp + ((j&1)<<1);
    g_wupt[idx] = wup[((size_t)ci*256 + co)*16 + ky*4 + kx];
}

// ---------------- down conv (implicit GEMM, tf32 3x), warp m32 x n32 --------
// grid (64, 4): bx -> b=bx>>3, oyq=bx&7 (4 output rows); by -> co tile of 64
__global__ __launch_bounds__(256) void k_down_t(const float* __restrict__ x,
                                                const float* __restrict__ wgt,
                                                const float* __restrict__ bias){
    int b = blockIdx.x>>3, oyq = blockIdx.x&7;
    int co0 = blockIdx.y*64;
    __shared__ float sW[64*68];
    __shared__ float sraw[4*10*72];
    int t=threadIdx.x, w=t>>5, lane=t&31, gp=lane>>2, tig=lane&3;
    int mrow=(w>>2)*32, ncol=(w&3)*32;
    float c[2][4][4];
#pragma unroll
    for (int i=0;i<2;i++)
#pragma unroll
    for (int jn=0;jn<4;jn++)
#pragma unroll
    for (int k=0;k<4;k++) c[i][jn][k]=0.f;

    for (int cc=0; cc<64; cc++){
        __syncthreads();
        for (int idx=t; idx<1024; idx+=256){
            int co=idx>>4, c4=(idx&15)<<2;
            *(float4*)(sW + co*68 + c4) =
                *(const float4*)(wgt + (size_t)(co0+co)*4096 + cc*64 + c4);
        }
        int ci0 = cc*4;
        for (int idx=t; idx<640; idx+=256){
            int rowid = idx>>4, c4=(idx&15)<<2;
            int ci4 = rowid/10, r = rowid - ci4*10;
            int iy = oyq*8 - 1 + r;
            float4 v = make_float4(0.f,0.f,0.f,0.f);
            if (iy>=0 && iy<64)
                v = *(const float4*)(x + (((size_t)(b*C + ci0+ci4))<<12) + (iy<<6) + c4);
            *(float4*)(sraw + rowid*72 + 4 + c4) = v;
        }
        if (t<40){ sraw[t*72+3]=0.f; sraw[t*72+68]=0.f; }
        __syncthreads();
#pragma unroll
        for (int kk=0;kk<8;kk++){
            int k0=kk*8;
            unsigned ah[2][4], al[2][4], bhi[4][2], blo[4][2];
#pragma unroll
            for (int mi=0;mi<2;mi++){
                const float* base = sW + (mrow+mi*16+gp)*68 + k0 + tig;
                msplit(base[0],      ah[mi][0], al[mi][0]);
                msplit(base[8*68],   ah[mi][1], al[mi][1]);
                msplit(base[4],      ah[mi][2], al[mi][2]);
                msplit(base[8*68+4], ah[mi][3], al[mi][3]);
            }
#pragma unroll
            for (int ni=0;ni<4;ni++){
                int n = ncol+ni*8+gp; int opy=n>>5, opx=n&31;
#pragma unroll
                for (int kj=0;kj<2;kj++){
                    int k = k0+tig+kj*4;
                    int ci4=k>>4, tap=k&15, ky=tap>>2, kx=tap&3;
                    float v = sraw[(ci4*10 + 2*opy+ky)*72 + 3 + 2*opx + kx];
                    msplit(v, bhi[ni][kj], blo[ni][kj]);
                }
            }
#pragma unroll
            for (int mi=0;mi<2;mi++)
#pragma unroll
            for (int ni=0;ni<4;ni++)
                mma3x(c[mi][ni], ah[mi], al[mi], bhi[ni], blo[ni]);
        }
    }
#pragma unroll
    for (int mi=0;mi<2;mi++){
        int co = co0+mrow+mi*16+gp;
        float b0v = bias[co], b1v = bias[co+8];
#pragma unroll
        for (int ni=0;ni<4;ni++){
            int n = ncol+ni*8+2*tig; int opy=n>>5, opx=n&31;
            size_t o = ((size_t)(b*C+co)<<10) + (oyq*4+opy)*32 + opx;
            *(float2*)(g_xd + o) = make_float2(c[mi][ni][0]+b0v, c[mi][ni][1]+b0v);
            *(float2*)(g_xd + o + (8<<10)) = make_float2(c[mi][ni][2]+b1v, c[mi][ni][3]+b1v);
        }
    }
}

// ---------------- convT (implicit GEMM per parity class, tf32 3x) -----------
// grid (64, 16); also writes g_y (= coarse) to eliminate copy kernel
__global__ __launch_bounds__(256) void k_up_t(const float* __restrict__ bup){
    int b = blockIdx.x>>3, uq = blockIdx.x&7;
    int cls = blockIdx.y>>2, co0 = (blockIdx.y&3)*64;
    int py = cls>>1, pxp = cls&1;
    __shared__ float sW[64*68];
    __shared__ float sraw[16*5*40];
    int t=threadIdx.x, w=t>>5, lane=t&31, gp=lane>>2, tig=lane&3;
    int mrow=(w>>2)*32, ncol=(w&3)*32;
    float c[2][4][4];
#pragma unroll
    for (int i=0;i<2;i++)
#pragma unroll
    for (int jn=0;jn<4;jn++)
#pragma unroll
    for (int k=0;k<4;k++) c[i][jn][k]=0.f;

    for (int cc=0; cc<16; cc++){
        __syncthreads();
        for (int idx=t; idx<1024; idx+=256){
            int co=idx>>4, c4=(idx&15)<<2;
            *(float4*)(sW + co*68 + c4) =
                *(const float4*)(g_wupt + (size_t)cls*262144 + (size_t)(co0+co)*1024 + cc*64 + c4);
        }
        int ci0 = cc*16;
        for (int idx=t; idx<640; idx+=256){
            int rowid=idx>>3, c4=(idx&7)<<2;
            int ci16=rowid/5, rr=rowid-ci16*5;
            int iy = uq*4 - py + rr;
            float4 v = make_float4(0.f,0.f,0.f,0.f);
            if (iy>=0 && iy<32)
                v = *(const float4*)(g_outc + (((size_t)(b*C+ci0+ci16))<<10) + (iy<<5) + c4);
            *(float4*)(sraw + rowid*40 + 4 + c4) = v;
        }
        if (t<80){ sraw[t*40+3]=0.f; sraw[t*40+36]=0.f; }
        __syncthreads();
#pragma unroll
        for (int kk=0;kk<8;kk++){
            int k0=kk*8;
            unsigned ah[2][4], al[2][4], bhi[4][2], blo[4][2];
#pragma unroll
            for (int mi=0;mi<2;mi++){
                const float* base = sW + (mrow+mi*16+gp)*68 + k0 + tig;
                msplit(base[0],      ah[mi][0], al[mi][0]);
                msplit(base[8*68],   ah[mi][1], al[mi][1]);
                msplit(base[4],      ah[mi][2], al[mi][2]);
                msplit(base[8*68+4], ah[mi][3], al[mi][3]);
            }
#pragma unroll
            for (int ni=0;ni<4;ni++){
                int n = ncol+ni*8+gp; int uu=n>>5, vv=n&31;
#pragma unroll
                for (int kj=0;kj<2;kj++){
                    int k = k0+tig+kj*4;
                    int ci16=k>>2, j=k&3;
                    float v = sraw[(ci16*5 + uu+1-(j>>1))*40 + vv + 5 - pxp - (j&1)];
                    msplit(v, bhi[ni][kj], blo[ni][kj]);
                }
            }
#pragma unroll
            for (int mi=0;mi<2;mi++)
#pragma unroll
            for (int ni=0;ni<4;ni++)
                mma3x(c[mi][ni], ah[mi], al[mi], bhi[ni], blo[ni]);
        }
    }
#pragma unroll
    for (int mi=0;mi<2;mi++){
        int co = co0+mrow+mi*16+gp;
        float b0v = bup[co], b1v = bup[co+8];
#pragma unroll
        for (int ni=0;ni<4;ni++){
            int n = ncol+ni*8+2*tig; int uu=n>>5, vv=n&31;
            int oy = 2*(uq*4+uu) + 1 - py;
            int ox = 2*vv + 1 - pxp;
            size_t o0 = (((size_t)(b*C+co))<<12) + oy*64 + ox;
            float v00 = c[mi][ni][0]+b0v, v01 = c[mi][ni][1]+b0v;
            g_coarse[o0]   = v00;  g_coarse[o0+2] = v01;
            g_y[o0]        = v00;  g_y[o0+2]      = v01;
            size_t o1 = (((size_t)(b*C+co+8))<<12) + oy*64 + ox;
            float v10 = c[mi][ni][2]+b1v, v11 = c[mi][ni][3]+b1v;
            g_coarse[o1]   = v10;  g_coarse[o1+2] = v11;
            g_y[o1]        = v10;  g_y[o1+2]      = v11;
        }
    }
}

// ---------------- qkv projection (tf32 3x) ----------------
// grid (32 bh, 16 pt) block 256; warp m32 x n24, two N-halves of 96
__global__ __launch_bounds__(256) void k_qkv_t(const float* __restrict__ Wm,
                                               const float* __restrict__ bias,
                                               int fine) {
    int bh = blockIdx.x, pt = blockIdx.y;
    int b = bh >> 2, h = bh & 3;
    __shared__ float sA[64*68];    // [p][d]
    __shared__ float sW[64*104];   // [d][n-half]
    int t=threadIdx.x, w=t>>5, lane=t&31, gp=lane>>2, tig=lane&3;
    int mrow=(w>>2)*32, ncol=(w&3)*24;
    if (!fine) {
        const float* src = g_xd + ((size_t)(b*C + h*HD)) * PLANE32 + pt*64;
        for (int idx = t; idx < 4096; idx += 256) {
            int d = idx >> 6, p = idx & 63;
            sA[p*68 + d] = src[d * PLANE32 + p];
        }
    } else {
        for (int idx = t; idx < 4096; idx += 256) {
            int d = idx >> 6, p = idx & 63;
            int tok = pt*64 + p;
            int ki = tok >> 2, s = tok & 3;
            int pi = g_topk[bh*KF + ki];
            int yy = ((pi >> 5) << 1) + (s >> 1);
            int xx = ((pi & 31) << 1) + (s & 1);
            sA[p*68 + d] = g_coarse[(((size_t)(b*C + h*HD + d)) << 12) + (yy << 6) + xx];
        }
    }
    float* dst = g_qkv + ((size_t)bh * P + pt*64) * 192;
    for (int half = 0; half < 2; half++) {
        __syncthreads();
        for (int idx = t; idx < 1536; idx += 256) {
            int d = idx / 24, n4 = (idx - d*24) << 2;   // 64 rows x 24 float4
            *(float4*)(sW + d*104 + n4) = *(const float4*)(Wm + d*192 + half*96 + n4);
        }
        __syncthreads();
        float c[2][3][4];
#pragma unroll
        for (int i=0;i<2;i++)
#pragma unroll
        for (int jn=0;jn<3;jn++)
#pragma unroll
        for (int k=0;k<4;k++) c[i][jn][k]=0.f;
#pragma unroll
        for (int kk=0;kk<8;kk++){
            int k0=kk*8;
            unsigned ah[2][4], al[2][4], bhi[3][2], blo[3][2];
#pragma unroll
            for (int mi=0;mi<2;mi++){
                const float* base = sA + (mrow+mi*16+gp)*68 + k0 + tig;
                msplit(base[0],      ah[mi][0], al[mi][0]);
                msplit(base[8*68],   ah[mi][1], al[mi][1]);
                msplit(base[4],      ah[mi][2], al[mi][2]);
                msplit(base[8*68+4], ah[mi][3], al[mi][3]);
            }
#pragma unroll
            for (int ni=0;ni<3;ni++){
                int n = ncol+ni*8+gp;
                msplit(sW[(k0+tig)*104 + n],   bhi[ni][0], blo[ni][0]);
                msplit(sW[(k0+tig+4)*104 + n], bhi[ni][1], blo[ni][1]);
            }
#pragma unroll
            for (int mi=0;mi<2;mi++)
#pragma unroll
            for (int ni=0;ni<3;ni++)
                mma3x(c[mi][ni], ah[mi], al[mi], bhi[ni], blo[ni]);
        }
#pragma unroll
        for (int mi=0;mi<2;mi++){
            int p = mrow+mi*16+gp;
#pragma unroll
            for (int ni=0;ni<3;ni++){
                int n = half*96 + ncol+ni*8+2*tig;
                float bb0 = bias[n], bb1 = bias[n+1];
                *(float2*)(dst + p*192 + n) =
                    make_float2(c[mi][ni][0]+bb0, c[mi][ni][1]+bb1);
                *(float2*)(dst + (p+8)*192 + n) =
                    make_float2(c[mi][ni][2]+bb0, c[mi][ni][3]+bb1);
            }
        }
    }
}

// ---------------- attention logits (tf32 3x): q64 x k128 stages -------------
// grid (32 bh, 16 qt, 2 kz) block 256; warp m32 x n32
__global__ __launch_bounds__(256) void k_logits_t() {
    int bh = blockIdx.x, qt = blockIdx.y, kz = blockIdx.z;
    __shared__ float sQ[64*68];
    __shared__ float sK[128*68];
    int t=threadIdx.x, w=t>>5, lane=t&31, gp=lane>>2, tig=lane&3;
    int mrow=(w>>2)*32, ncol=(w&3)*32;
    const float* qkv = g_qkv + (size_t)bh*P*192;
    for (int idx=t; idx<1024; idx+=256){
        int r=idx>>4, c4=(idx&15)<<2;
        *(float4*)(sQ + r*68 + c4) = *(const float4*)(qkv + (qt*64+r)*192 + c4);
    }
    float* dst = g_attn + ((size_t)bh<<20) + (size_t)qt*64*1024;
    for (int s=0; s<4; s++){
        int colbase = kz*512 + s*128;
        __syncthreads();
        for (int idx=t; idx<2048; idx+=256){
            int r=idx>>4, c4=(idx&15)<<2;
            *(float4*)(sK + r*68 + c4) = *(const float4*)(qkv + (colbase+r)*192 + 64 + c4);
        }
        __syncthreads();
        float c[2][4][4];
#pragma unroll
        for (int i=0;i<2;i++)
#pragma unroll
        for (int jn=0;jn<4;jn++)
#pragma unroll
        for (int k=0;k<4;k++) c[i][jn][k]=0.f;
#pragma unroll
        for (int kk=0;kk<8;kk++){
            int k0=kk*8;
            unsigned ah[2][4], al[2][4], bhi[4][2], blo[4][2];
#pragma unroll
            for (int mi=0;mi<2;mi++){
                const float* base = sQ + (mrow+mi*16+gp)*68 + k0 + tig;
                msplit(base[0],      ah[mi][0], al[mi][0]);
                msplit(base[8*68],   ah[mi][1], al[mi][1]);
                msplit(base[4],      ah[mi][2], al[mi][2]);
                msplit(base[8*68+4], ah[mi][3], al[mi][3]);
            }
#pragma unroll
            for (int ni=0;ni<4;ni++){
                const float* base = sK + (ncol+ni*8+gp)*68 + k0 + tig;
                msplit(base[0], bhi[ni][0], blo[ni][0]);
                msplit(base[4], bhi[ni][1], blo[ni][1]);
            }
#pragma unroll
            for (int mi=0;mi<2;mi++)
#pragma unroll
            for (int ni=0;ni<4;ni++)
                mma3x(c[mi][ni], ah[mi], al[mi], bhi[ni], blo[ni]);
        }
#pragma unroll
        for (int mi=0;mi<2;mi++)
#pragma unroll
        for (int ni=0;ni<4;ni++){
            int row = mrow+mi*16+gp, col = colbase+ncol+ni*8+2*tig;
            *(float2*)(dst + (size_t)row*1024 + col) =
                make_float2(c[mi][ni][0]*0.125f, c[mi][ni][1]*0.125f);
            *(float2*)(dst + (size_t)(row+8)*1024 + col) =
                make_float2(c[mi][ni][2]*0.125f, c[mi][ni][3]*0.125f);
        }
    }
}

// ---------------- softmax ----------------
__global__ __launch_bounds__(256) void k_softmax() {
    float* row = g_attn + ((size_t)blockIdx.x * 1024 + blockIdx.y) * 1024;
    int t = threadIdx.x;
    float v0 = row[t], v1 = row[t+256], v2 = row[t+512], v3 = row[t+768];
    float m = fmaxf(fmaxf(v0, v1), fmaxf(v2, v3));
    __shared__ float red[8];
    __shared__ float red2[8];
#pragma unroll
    for (int o = 16; o; o >>= 1) m = fmaxf(m, __shfl_xor_sync(0xffffffffu, m, o));
    if ((t & 31) == 0) red[t >> 5] = m;
    __syncthreads();
    if (t == 0) {
        float mm = red[0];
#pragma unroll
        for (int i = 1; i < 8; i++) mm = fmaxf(mm, red[i]);
        red[0] = mm;
    }
    __syncthreads();
    m = red[0];
    float e0 = __expf(v0 - m), e1 = __expf(v1 - m), e2 = __expf(v2 - m), e3 = __expf(v3 - m);
    float s = e0 + e1 + e2 + e3;
#pragma unroll
    for (int o = 16; o; o >>= 1) s += __shfl_xor_sync(0xffffffffu, s, o);
    if ((t & 31) == 0) red2[t >> 5] = s;
    __syncthreads();
    if (t == 0) {
        float ss = 0.f;
#pragma unroll
        for (int i = 0; i < 8; i++) ss += red2[i];
        red2[0] = ss;
    }
    __syncthreads();
    float inv = 1.0f / red2[0];
    row[t] = e0*inv; row[t+256] = e1*inv; row[t+512] = e2*inv; row[t+768] = e3*inv;
}

// ---------------- column sums ----------------
__global__ __launch_bounds__(256) void k_colsum() {
    int bh = blockIdx.x;
    int k = blockIdx.y * 256 + threadIdx.x;
    const float* a = g_attn + ((size_t)bh << 20) + k;
    float s = 0.f;
#pragma unroll 8
    for (int q = 0; q < 1024; q++) s += a[(size_t)q << 10];
    g_score[bh*1024 + k] = s;
}

// ---------------- top-k bitonic ----------------
__global__ __launch_bounds__(512) void k_topk() {
    int bh = blockIdx.x;
    __shared__ float sv[1024];
    __shared__ int si[1024];
    int t = threadIdx.x;
    sv[t]       = g_score[bh*1024 + t];       si[t]       = t;
    sv[t + 512] = g_score[bh*1024 + t + 512]; si[t + 512] = t + 512;
    __syncthreads();
    for (int k = 2; k <= 1024; k <<= 1) {
        for (int j = k >> 1; j > 0; j >>= 1) {
#pragma unroll
            for (int mm = 0; mm < 2; mm++) {
                int i = t + mm*512;
                int l = i ^ j;
                if (l > i) {
                    float vi = sv[i], vl = sv[l];
                    int ii = si[i], il = si[l];
                    bool before = (vi > vl) || (vi == vl && ii < il);
                    bool keep = ((i & k) == 0) ? before : !before;
                    if (!keep) { sv[i] = vl; sv[l] = vi; si[i] = il; si[l] = ii; }
                }
            }
            __syncthreads();
        }
    }
    if (t < 256) g_topk[bh*KF + t] = si[t];
}

// ---------------- attn @ V (tf32 3x): block m128 x n64, warp m32 x n32 ------
// grid (32 bh, 8 qb) block 256
__global__ __launch_bounds__(256) void k_av_t(int fine) {
    int bh = blockIdx.x, qb = blockIdx.y;
    int b = bh >> 2, h = bh & 3;
    __shared__ float sA[128*68];
    __shared__ float sV[64*72];
    int t=threadIdx.x, w=t>>5, lane=t&31, gp=lane>>2, tig=lane&3;
    int mrow=(w>>1)*32, ncol=(w&1)*32;
    const float* attn = g_attn + ((size_t)bh << 20) + (size_t)qb*128*1024;
    const float* vptr = g_qkv + (size_t)bh * P * 192 + 128;
    float c[2][4][4];
#pragma unroll
    for (int i=0;i<2;i++)
#pragma unroll
    for (int jn=0;jn<4;jn++)
#pragma unroll
    for (int k=0;k<4;k++) c[i][jn][k]=0.f;

    for (int kc = 0; kc < 16; kc++) {
        __syncthreads();
        for (int idx=t; idx<2048; idx+=256){
            int r=idx>>4, c4=(idx&15)<<2;
            *(float4*)(sA + r*68 + c4) = *(const float4*)(attn + (size_t)r*1024 + kc*64 + c4);
        }
        for (int idx=t; idx<1024; idx+=256){
            int r=idx>>4, c4=(idx&15)<<2;
            *(float4*)(sV + r*72 + c4) = *(const float4*)(vptr + (size_t)(kc*64+r)*192 + c4);
        }
        __syncthreads();
#pragma unroll
        for (int kk=0;kk<8;kk++){
            int k0=kk*8;
            unsigned ah[2][4], al[2][4], bhi[4][2], blo[4][2];
#pragma unroll
            for (int mi=0;mi<2;mi++){
                const float* base = sA + (mrow+mi*16+gp)*68 + k0 + tig;
                msplit(base[0],      ah[mi][0], al[mi][0]);
                msplit(base[8*68],   ah[mi][1], al[mi][1]);
                msplit(base[4],      ah[mi][2], al[mi][2]);
                msplit(base[8*68+4], ah[mi][3], al[mi][3]);
            }
#pragma unroll
            for (int ni=0;ni<4;ni++){
                int n = ncol+ni*8+gp;
                msplit(sV[(k0+tig)*72   + n], bhi[ni][0], blo[ni][0]);
                msplit(sV[(k0+tig+4)*72 + n], bhi[ni][1], blo[ni][1]);
            }
#pragma unroll
            for (int mi=0;mi<2;mi++)
#pragma unroll
            for (int ni=0;ni<4;ni++)
                mma3x(c[mi][ni], ah[mi], al[mi], bhi[ni], blo[ni]);
        }
    }
    if (!fine) {
#pragma unroll
        for (int mi=0;mi<2;mi++)
#pragma unroll
        for (int ni=0;ni<4;ni++){
            int row = qb*128 + mrow+mi*16+gp;
            int d0 = ncol+ni*8+2*tig;
            g_outc[((size_t)(b*C + h*HD + d0  ))*PLANE32 + row] = c[mi][ni][0];
            g_outc[((size_t)(b*C + h*HD + d0+1))*PLANE32 + row] = c[mi][ni][1];
            g_outc[((size_t)(b*C + h*HD + d0  ))*PLANE32 + row + 8] = c[mi][ni][2];
            g_outc[((size_t)(b*C + h*HD + d0+1))*PLANE32 + row + 8] = c[mi][ni][3];
        }
    } else {
#pragma unroll
        for (int mi=0;mi<2;mi++)
#pragma unroll
        for (int ni=0;ni<4;ni++){
            int row = qb*128 + mrow+mi*16+gp;
            int d0 = ncol+ni*8+2*tig;
            *(float2*)(g_outf + ((size_t)bh*P + row)*HD + d0) =
                make_float2(c[mi][ni][0], c[mi][ni][1]);
            *(float2*)(g_outf + ((size_t)bh*P + row + 8)*HD + d0) =
                make_float2(c[mi][ni][2], c[mi][ni][3]);
        }
    }
}

// ---------------- scatter fine output ----------------
__global__ __launch_bounds__(256) void k_scatter() {
    int bh = blockIdx.x, ki = blockIdx.y;
    int t = threadIdx.x;
    int s = t >> 6, d = t & 63;
    int b = bh >> 2, h = bh & 3;
    int p = g_topk[bh*KF + ki];
    int yy = ((p >> 5) << 1) + (s >> 1);
    int xx = ((p & 31) << 1) + (s & 1);
    float val = g_outf[((size_t)bh * P + ki*4 + s) * HD + d];
    g_y[(((size_t)(b*C + h*HD + d)) << 12) + (yy << 6) + xx] += val;
}

// ---------------- depthwise 3x3 + BN + relu6 ----------------
__global__ __launch_bounds__(256) void k_dw(const float* __restrict__ wdw,
                                            const float* __restrict__ g,
                                            const float* __restrict__ bb,
                                            const float* __restrict__ m,
                                            const float* __restrict__ vv) {
    size_t i = (size_t)blockIdx.x * 256 + threadIdx.x;
    int x = i & 63, y = (i >> 6) & 63;
    int c = (int)((i >> 12) & 255);
    const float* plane = g_y + ((i >> 12) << 12);
    const float* wc = wdw + c*9;
    float s = 0.f;
#pragma unroll
    for (int ky = 0; ky < 3; ky++) {
        int yy = y + ky - 1;
        if (yy < 0 || yy >= 64) continue;
#pragma unroll
        for (int kx = 0; kx < 3; kx++) {
            int xx = x + kx - 1;
            if (xx < 0 || xx >= 64) continue;
            s = fmaf(wc[ky*3 + kx], plane[(yy << 6) + xx], s);
        }
    }
    float sc = g[c] * rsqrtf(vv[c] + 1e-5f);
    float r = s * sc + (bb[c] - m[c] * sc);
    g_yd[i] = fminf(fmaxf(r, 0.f), 6.f);
}

// ---------------- pointwise 1x1 (tf32 3x) + BN + relu6 -> output ------------
// grid (8 b, 32 sp of 128px, 4 cg of 64co) block 256; warp m32 x n32
__global__ __launch_bounds__(256) void k_pw_t(const float* __restrict__ wpw,
                                              const float* __restrict__ g,
                                              const float* __restrict__ bb,
                                              const float* __restrict__ m,
                                              const float* __restrict__ vv,
                                              float* __restrict__ out) {
    int b = blockIdx.x, sp = blockIdx.y, cg = blockIdx.z;
    __shared__ float sW2[64*36];
    __shared__ float sX[32*136];
    int t=threadIdx.x, w=t>>5, lane=t&31, gp=lane>>2, tig=lane&3;
    int mrow=(w>>2)*32, ncol=(w&3)*32;
    float c[2][4][4];
#pragma unroll
    for (int i=0;i<2;i++)
#pragma unroll
    for (int jn=0;jn<4;jn++)
#pragma unroll
    for (int k=0;k<4;k++) c[i][jn][k]=0.f;
    const float* xin = g_yd + (size_t)b * C * HW + sp * 128;
    for (int cc = 0; cc < 8; cc++) {
        __syncthreads();
        for (int idx=t; idx<512; idx+=256){
            int mm2=idx>>3, k4=(idx&7)<<2;
            *(float4*)(sW2 + mm2*36 + k4) =
                *(const float4*)(wpw + (size_t)(cg*64+mm2)*256 + cc*32 + k4);
        }
        for (int idx=t; idx<1024; idx+=256){
            int k=idx>>5, n4=(idx&31)<<2;
            *(float4*)(sX + k*136 + n4) =
                *(const float4*)(xin + (size_t)(cc*32+k)*HW + n4);
        }
        __syncthreads();
#pragma unroll
        for (int kk=0;kk<4;kk++){
            int k0=kk*8;
            unsigned ah[2][4], al[2][4], bhi[4][2], blo[4][2];
#pragma unroll
            for (int mi=0;mi<2;mi++){
                const float* base = sW2 + (mrow+mi*16+gp)*36 + k0 + tig;
                msplit(base[0],      ah[mi][0], al[mi][0]);
                msplit(base[8*36],   ah[mi][1], al[mi][1]);
                msplit(base[4],      ah[mi][2], al[mi][2]);
                msplit(base[8*36+4], ah[mi][3], al[mi][3]);
            }
#pragma unroll
            for (int ni=0;ni<4;ni++){
                int n = ncol+ni*8+gp;
                msplit(sX[(k0+tig)*136   + n], bhi[ni][0], blo[ni][0]);
                msplit(sX[(k0+tig+4)*136 + n], bhi[ni][1], blo[ni][1]);
            }
#pragma unroll
            for (int mi=0;mi<2;mi++)
#pragma unroll
            for (int ni=0;ni<4;ni++)
                mma3x(c[mi][ni], ah[mi], al[mi], bhi[ni], blo[ni]);
        }
    }
#pragma unroll
    for (int mi=0;mi<2;mi++){
        int co = cg*64 + mrow+mi*16+gp;
        float sc0 = g[co] * rsqrtf(vv[co] + 1e-5f);
        float of0 = bb[co] - m[co] * sc0;
        float sc1 = g[co+8] * rsqrtf(vv[co+8] + 1e-5f);
        float of1 = bb[co+8] - m[co+8] * sc1;
#pragma unroll
        for (int ni=0;ni<4;ni++){
            int px = sp*128 + ncol+ni*8+2*tig;
            float r0 = fminf(fmaxf(c[mi][ni][0]*sc0 + of0, 0.f), 6.f);
            float r1 = fminf(fmaxf(c[mi][ni][1]*sc0 + of0, 0.f), 6.f);
            float r2 = fminf(fmaxf(c[mi][ni][2]*sc1 + of1, 0.f), 6.f);
            float r3 = fminf(fmaxf(c[mi][ni][3]*sc1 + of1, 0.f), 6.f);
            *(float2*)(out + ((size_t)(b*C+co))*HW + px)   = make_float2(r0, r1);
            *(float2*)(out + ((size_t)(b*C+co+8))*HW + px) = make_float2(r2, r3);
        }
    }
}

// ---------------- launch ----------------
extern "C" void kernel_launch(void* const* d_in, const int* in_sizes, int n_in,
                              void* d_out, int out_size) {
    const float* x       = (const float*)d_in[0];
    const float* w_down  = (const float*)d_in[1];
    const float* b_down  = (const float*)d_in[2];
    const float* w_qkv_c = (const float*)d_in[3];
    const float* b_qkv_c = (const float*)d_in[4];
    const float* w_up    = (const float*)d_in[5];
    const float* b_up    = (const float*)d_in[6];
    const float* w_qkv_f = (const float*)d_in[7];
    const float* b_qkv_f = (const float*)d_in[8];
    const float* w_dw    = (const float*)d_in[9];
    const float* bn_dw_g = (const float*)d_in[10];
    const float* bn_dw_b = (const float*)d_in[11];
    const float* bn_dw_m = (const float*)d_in[12];
    const float* bn_dw_v = (const float*)d_in[13];
    const float* w_pw    = (const float*)d_in[14];
    const float* bn_pw_g = (const float*)d_in[15];
    const float* bn_pw_b = (const float*)d_in[16];
    const float* bn_pw_m = (const float*)d_in[17];
    const float* bn_pw_v = (const float*)d_in[18];
    float* out = (float*)d_out;

    k_wt<<<4096, 256>>>(w_up);

    // ---- coarse attention path ----
    k_down_t<<<dim3(64, 4), 256>>>(x, w_down, b_down);
    k_qkv_t<<<dim3(32, 16), 256>>>(w_qkv_c, b_qkv_c, 0);
    k_logits_t<<<dim3(32, 16, 2), 256>>>();
    k_softmax<<<dim3(32, 1024), 256>>>();
    k_colsum<<<dim3(32, 4), 256>>>();
    k_av_t<<<dim3(32, 8), 256>>>(0);
    k_topk<<<32, 512>>>();
    k_up_t<<<dim3(64, 16), 256>>>(b_up);

    // ---- fine (top-k) attention path ----
    k_qkv_t<<<dim3(32, 16), 256>>>(w_qkv_f, b_qkv_f, 1);
    k_logits_t<<<dim3(32, 16, 2), 256>>>();
    k_softmax<<<dim3(32, 1024), 256>>>();
    k_av_t<<<dim3(32, 8), 256>>>(1);

    // ---- combine + feed-forward ----
    k_scatter<<<dim3(32, 256), 256>>>();
    k_dw<<<32768, 256>>>(w_dw, bn_dw_g, bn_dw_b, bn_dw_m, bn_dw_v);
    k_pw_t<<<dim3(8, 32, 4), 256>>>(w_pw, bn_pw_g, bn_pw_b, bn_pw_m, bn_pw_v, out);
}

// round 6
// speedup vs baseline: 2.2954x; 1.0031x over previous
#include <cuda_runtime.h>
#include <math.h>

// ---------------- problem constants ----------------
#define BATCH 8
#define C 256
#define H 64
#define W 64
#define NH 4
#define HD 64
#define P 1024
#define KF 256
#define HW (H*W)
#define PLANE32 1024

// ---------------- device scratch ----------------
__device__ float g_xd[BATCH*C*PLANE32];
__device__ float g_qkv[BATCH*NH*P*192];
__device__ float g_attn[(size_t)BATCH*NH*P*P];
__device__ float g_outc[BATCH*C*PLANE32];
__device__ float g_coarse[BATCH*C*HW];
__device__ float g_score[BATCH*NH*P];
__device__ int   g_topk[BATCH*NH*KF];
__device__ float g_outf[BATCH*NH*P*HD];
__device__ float g_y[BATCH*C*HW];
__device__ float g_yd[BATCH*C*HW];
__device__ float g_wupt[4*256*1024];   // transposed convT weights [cls][co][ci*4+j]

// ---------------- tf32 mma helpers ----------------
__device__ __forceinline__ void msplit(float x, unsigned &hi, unsigned &lo){
    unsigned xb = __float_as_uint(x);
    hi = xb & 0xFFFFE000u;
    lo = __float_as_uint(x - __uint_as_float(hi));
}
__device__ __forceinline__ void mma8(float* c, unsigned a0,unsigned a1,unsigned a2,unsigned a3,
                                     unsigned b0,unsigned b1){
    asm volatile("mma.sync.aligned.m16n8k8.row.col.f32.tf32.tf32.f32 "
        "{%0,%1,%2,%3}, {%4,%5,%6,%7}, {%8,%9}, {%0,%1,%2,%3};"
        : "+f"(c[0]),"+f"(c[1]),"+f"(c[2]),"+f"(c[3])
        : "r"(a0),"r"(a1),"r"(a2),"r"(a3),"r"(b0),"r"(b1));
}
__device__ __forceinline__ void mma3x(float* c, const unsigned* ah, const unsigned* al,
                                      const unsigned* bh, const unsigned* bl){
    mma8(c, ah[0],ah[1],ah[2],ah[3], bh[0],bh[1]);
    mma8(c, ah[0],ah[1],ah[2],ah[3], bl[0],bl[1]);
    mma8(c, al[0],al[1],al[2],al[3], bh[0],bh[1]);
}

// ---------------- weight pre-transpose for convT ----------------
__global__ __launch_bounds__(256) void k_wt(const float* __restrict__ wup){
    int idx = blockIdx.x*256 + threadIdx.x;      // [cls][co][ci][j]
    int cls = idx>>18, co = (idx>>10)&255, ci = (idx>>2)&255, j = idx&3;
    int py = cls>>1, pxp = cls&1;
    int ky = py + ((j>>1)<<1), kx = pxp + ((j&1)<<1);
    g_wupt[idx] = wup[((size_t)ci*256 + co)*16 + ky*4 + kx];
}

// ---------------- down conv (implicit GEMM, tf32 3x), warp m32 x n32 --------
// grid (64, 4): bx -> b=bx>>3, oyq=bx&7 (4 output rows); by -> co tile of 64
__global__ __launch_bounds__(256) void k_down_t(const float* __restrict__ x,
                                                const float* __restrict__ wgt,
                                                const float* __restrict__ bias){
    int b = blockIdx.x>>3, oyq = blockIdx.x&7;
    int co0 = blockIdx.y*64;
    __shared__ float sW[64*68];
    __shared__ float sraw[4*10*72];
    int t=threadIdx.x, w=t>>5, lane=t&31, gp=lane>>2, tig=lane&3;
    int mrow=(w>>2)*32, ncol=(w&3)*32;
    float c[2][4][4];
#pragma unroll
    for (int i=0;i<2;i++)
#pragma unroll
    for (int jn=0;jn<4;jn++)
#pragma unroll
    for (int k=0;k<4;k++) c[i][jn][k]=0.f;

    for (int cc=0; cc<64; cc++){
        __syncthreads();
        for (int idx=t; idx<1024; idx+=256){
            int co=idx>>4, c4=(idx&15)<<2;
            *(float4*)(sW + co*68 + c4) =
                *(const float4*)(wgt + (size_t)(co0+co)*4096 + cc*64 + c4);
        }
        int ci0 = cc*4;
        for (int idx=t; idx<640; idx+=256){
            int rowid = idx>>4, c4=(idx&15)<<2;
            int ci4 = rowid/10, r = rowid - ci4*10;
            int iy = oyq*8 - 1 + r;
            float4 v = make_float4(0.f,0.f,0.f,0.f);
            if (iy>=0 && iy<64)
                v = *(const float4*)(x + (((size_t)(b*C + ci0+ci4))<<12) + (iy<<6) + c4);
            *(float4*)(sraw + rowid*72 + 4 + c4) = v;
        }
        if (t<40){ sraw[t*72+3]=0.f; sraw[t*72+68]=0.f; }
        __syncthreads();
#pragma unroll
        for (int kk=0;kk<8;kk++){
            int k0=kk*8;
            unsigned ah[2][4], al[2][4], bhi[4][2], blo[4][2];
#pragma unroll
            for (int mi=0;mi<2;mi++){
                const float* base = sW + (mrow+mi*16+gp)*68 + k0 + tig;
                msplit(base[0],      ah[mi][0], al[mi][0]);
                msplit(base[8*68],   ah[mi][1], al[mi][1]);
                msplit(base[4],      ah[mi][2], al[mi][2]);
                msplit(base[8*68+4], ah[mi][3], al[mi][3]);
            }
#pragma unroll
            for (int ni=0;ni<4;ni++){
                int n = ncol+ni*8+gp; int opy=n>>5, opx=n&31;
#pragma unroll
                for (int kj=0;kj<2;kj++){
                    int k = k0+tig+kj*4;
                    int ci4=k>>4, tap=k&15, ky=tap>>2, kx=tap&3;
                    float v = sraw[(ci4*10 + 2*opy+ky)*72 + 3 + 2*opx + kx];
                    msplit(v, bhi[ni][kj], blo[ni][kj]);
                }
            }
#pragma unroll
            for (int mi=0;mi<2;mi++)
#pragma unroll
            for (int ni=0;ni<4;ni++)
                mma3x(c[mi][ni], ah[mi], al[mi], bhi[ni], blo[ni]);
        }
    }
#pragma unroll
    for (int mi=0;mi<2;mi++){
        int co = co0+mrow+mi*16+gp;
        float b0v = bias[co], b1v = bias[co+8];
#pragma unroll
        for (int ni=0;ni<4;ni++){
            int n = ncol+ni*8+2*tig; int opy=n>>5, opx=n&31;
            size_t o = ((size_t)(b*C+co)<<10) + (oyq*4+opy)*32 + opx;
            *(float2*)(g_xd + o) = make_float2(c[mi][ni][0]+b0v, c[mi][ni][1]+b0v);
            *(float2*)(g_xd + o + (8<<10)) = make_float2(c[mi][ni][2]+b1v, c[mi][ni][3]+b1v);
        }
    }
}

// ---------------- convT (implicit GEMM per parity class, tf32 3x) -----------
// grid (64, 16); also writes g_y (= coarse) to eliminate copy kernel
__global__ __launch_bounds__(256) void k_up_t(const float* __restrict__ bup){
    int b = blockIdx.x>>3, uq = blockIdx.x&7;
    int cls = blockIdx.y>>2, co0 = (blockIdx.y&3)*64;
    int py = cls>>1, pxp = cls&1;
    __shared__ float sW[64*68];
    __shared__ float sraw[16*5*40];
    int t=threadIdx.x, w=t>>5, lane=t&31, gp=lane>>2, tig=lane&3;
    int mrow=(w>>2)*32, ncol=(w&3)*32;
    float c[2][4][4];
#pragma unroll
    for (int i=0;i<2;i++)
#pragma unroll
    for (int jn=0;jn<4;jn++)
#pragma unroll
    for (int k=0;k<4;k++) c[i][jn][k]=0.f;

    for (int cc=0; cc<16; cc++){
        __syncthreads();
        for (int idx=t; idx<1024; idx+=256){
            int co=idx>>4, c4=(idx&15)<<2;
            *(float4*)(sW + co*68 + c4) =
                *(const float4*)(g_wupt + (size_t)cls*262144 + (size_t)(co0+co)*1024 + cc*64 + c4);
        }
        int ci0 = cc*16;
        for (int idx=t; idx<640; idx+=256){
            int rowid=idx>>3, c4=(idx&7)<<2;
            int ci16=rowid/5, rr=rowid-ci16*5;
            int iy = uq*4 - py + rr;
            float4 v = make_float4(0.f,0.f,0.f,0.f);
            if (iy>=0 && iy<32)
                v = *(const float4*)(g_outc + (((size_t)(b*C+ci0+ci16))<<10) + (iy<<5) + c4);
            *(float4*)(sraw + rowid*40 + 4 + c4) = v;
        }
        if (t<80){ sraw[t*40+3]=0.f; sraw[t*40+36]=0.f; }
        __syncthreads();
#pragma unroll
        for (int kk=0;kk<8;kk++){
            int k0=kk*8;
            unsigned ah[2][4], al[2][4], bhi[4][2], blo[4][2];
#pragma unroll
            for (int mi=0;mi<2;mi++){
                const float* base = sW + (mrow+mi*16+gp)*68 + k0 + tig;
                msplit(base[0],      ah[mi][0], al[mi][0]);
                msplit(base[8*68],   ah[mi][1], al[mi][1]);
                msplit(base[4],      ah[mi][2], al[mi][2]);
                msplit(base[8*68+4], ah[mi][3], al[mi][3]);
            }
#pragma unroll
            for (int ni=0;ni<4;ni++){
                int n = ncol+ni*8+gp; int uu=n>>5, vv=n&31;
#pragma unroll
                for (int kj=0;kj<2;kj++){
                    int k = k0+tig+kj*4;
                    int ci16=k>>2, j=k&3;
                    float v = sraw[(ci16*5 + uu+1-(j>>1))*40 + vv + 5 - pxp - (j&1)];
                    msplit(v, bhi[ni][kj], blo[ni][kj]);
                }
            }
#pragma unroll
            for (int mi=0;mi<2;mi++)
#pragma unroll
            for (int ni=0;ni<4;ni++)
                mma3x(c[mi][ni], ah[mi], al[mi], bhi[ni], blo[ni]);
        }
    }
#pragma unroll
    for (int mi=0;mi<2;mi++){
        int co = co0+mrow+mi*16+gp;
        float b0v = bup[co], b1v = bup[co+8];
#pragma unroll
        for (int ni=0;ni<4;ni++){
            int n = ncol+ni*8+2*tig; int uu=n>>5, vv=n&31;
            int oy = 2*(uq*4+uu) + 1 - py;
            int ox = 2*vv + 1 - pxp;
            size_t o0 = (((size_t)(b*C+co))<<12) + oy*64 + ox;
            float v00 = c[mi][ni][0]+b0v, v01 = c[mi][ni][1]+b0v;
            g_coarse[o0]   = v00;  g_coarse[o0+2] = v01;
            g_y[o0]        = v00;  g_y[o0+2]      = v01;
            size_t o1 = (((size_t)(b*C+co+8))<<12) + oy*64 + ox;
            float v10 = c[mi][ni][2]+b1v, v11 = c[mi][ni][3]+b1v;
            g_coarse[o1]   = v10;  g_coarse[o1+2] = v11;
            g_y[o1]        = v10;  g_y[o1+2]      = v11;
        }
    }
}

// ---------------- qkv projection (tf32 3x) ----------------
// grid (32 bh, 16 pt) block 256; warp m32 x n24, two N-halves of 96
__global__ __launch_bounds__(256) void k_qkv_t(const float* __restrict__ Wm,
                                               const float* __restrict__ bias,
                                               int fine) {
    int bh = blockIdx.x, pt = blockIdx.y;
    int b = bh >> 2, h = bh & 3;
    __shared__ float sA[64*68];    // [p][d]
    __shared__ float sW[64*104];   // [d][n-half]
    int t=threadIdx.x, w=t>>5, lane=t&31, gp=lane>>2, tig=lane&3;
    int mrow=(w>>2)*32, ncol=(w&3)*24;
    if (!fine) {
        const float* src = g_xd + ((size_t)(b*C + h*HD)) * PLANE32 + pt*64;
        for (int idx = t; idx < 4096; idx += 256) {
            int d = idx >> 6, p = idx & 63;
            sA[p*68 + d] = src[d * PLANE32 + p];
        }
    } else {
        for (int idx = t; idx < 4096; idx += 256) {
            int d = idx >> 6, p = idx & 63;
            int tok = pt*64 + p;
            int ki = tok >> 2, s = tok & 3;
            int pi = g_topk[bh*KF + ki];
            int yy = ((pi >> 5) << 1) + (s >> 1);
            int xx = ((pi & 31) << 1) + (s & 1);
            sA[p*68 + d] = g_coarse[(((size_t)(b*C + h*HD + d)) << 12) + (yy << 6) + xx];
        }
    }
    float* dst = g_qkv + ((size_t)bh * P + pt*64) * 192;
    for (int half = 0; half < 2; half++) {
        __syncthreads();
        for (int idx = t; idx < 1536; idx += 256) {
            int d = idx / 24, n4 = (idx - d*24) << 2;   // 64 rows x 24 float4
            *(float4*)(sW + d*104 + n4) = *(const float4*)(Wm + d*192 + half*96 + n4);
        }
        __syncthreads();
        float c[2][3][4];
#pragma unroll
        for (int i=0;i<2;i++)
#pragma unroll
        for (int jn=0;jn<3;jn++)
#pragma unroll
        for (int k=0;k<4;k++) c[i][jn][k]=0.f;
#pragma unroll
        for (int kk=0;kk<8;kk++){
            int k0=kk*8;
            unsigned ah[2][4], al[2][4], bhi[3][2], blo[3][2];
#pragma unroll
            for (int mi=0;mi<2;mi++){
                const float* base = sA + (mrow+mi*16+gp)*68 + k0 + tig;
                msplit(base[0],      ah[mi][0], al[mi][0]);
                msplit(base[8*68],   ah[mi][1], al[mi][1]);
                msplit(base[4],      ah[mi][2], al[mi][2]);
                msplit(base[8*68+4], ah[mi][3], al[mi][3]);
            }
#pragma unroll
            for (int ni=0;ni<3;ni++){
                int n = ncol+ni*8+gp;
                msplit(sW[(k0+tig)*104 + n],   bhi[ni][0], blo[ni][0]);
                msplit(sW[(k0+tig+4)*104 + n], bhi[ni][1], blo[ni][1]);
            }
#pragma unroll
            for (int mi=0;mi<2;mi++)
#pragma unroll
            for (int ni=0;ni<3;ni++)
                mma3x(c[mi][ni], ah[mi], al[mi], bhi[ni], blo[ni]);
        }
#pragma unroll
        for (int mi=0;mi<2;mi++){
            int p = mrow+mi*16+gp;
#pragma unroll
            for (int ni=0;ni<3;ni++){
                int n = half*96 + ncol+ni*8+2*tig;
                float bb0 = bias[n], bb1 = bias[n+1];
                *(float2*)(dst + p*192 + n) =
                    make_float2(c[mi][ni][0]+bb0, c[mi][ni][1]+bb1);
                *(float2*)(dst + (p+8)*192 + n) =
                    make_float2(c[mi][ni][2]+bb0, c[mi][ni][3]+bb1);
            }
        }
    }
}

// ---------------- attention logits (tf32 3x): q64 x k128 stages -------------
// grid (32 bh, 16 qt, 2 kz) block 256; warp m32 x n32
__global__ __launch_bounds__(256) void k_logits_t() {
    int bh = blockIdx.x, qt = blockIdx.y, kz = blockIdx.z;
    __shared__ float sQ[64*68];
    __shared__ float sK[128*68];
    int t=threadIdx.x, w=t>>5, lane=t&31, gp=lane>>2, tig=lane&3;
    int mrow=(w>>2)*32, ncol=(w&3)*32;
    const float* qkv = g_qkv + (size_t)bh*P*192;
    for (int idx=t; idx<1024; idx+=256){
        int r=idx>>4, c4=(idx&15)<<2;
        *(float4*)(sQ + r*68 + c4) = *(const float4*)(qkv + (qt*64+r)*192 + c4);
    }
    float* dst = g_attn + ((size_t)bh<<20) + (size_t)qt*64*1024;
    for (int s=0; s<4; s++){
        int colbase = kz*512 + s*128;
        __syncthreads();
        for (int idx=t; idx<2048; idx+=256){
            int r=idx>>4, c4=(idx&15)<<2;
            *(float4*)(sK + r*68 + c4) = *(const float4*)(qkv + (colbase+r)*192 + 64 + c4);
        }
        __syncthreads();
        float c[2][4][4];
#pragma unroll
        for (int i=0;i<2;i++)
#pragma unroll
        for (int jn=0;jn<4;jn++)
#pragma unroll
        for (int k=0;k<4;k++) c[i][jn][k]=0.f;
#pragma unroll
        for (int kk=0;kk<8;kk++){
            int k0=kk*8;
            unsigned ah[2][4], al[2][4], bhi[4][2], blo[4][2];
#pragma unroll
            for (int mi=0;mi<2;mi++){
                const float* base = sQ + (mrow+mi*16+gp)*68 + k0 + tig;
                msplit(base[0],      ah[mi][0], al[mi][0]);
                msplit(base[8*68],   ah[mi][1], al[mi][1]);
                msplit(base[4],      ah[mi][2], al[mi][2]);
                msplit(base[8*68+4], ah[mi][3], al[mi][3]);
            }
#pragma unroll
            for (int ni=0;ni<4;ni++){
                const float* base = sK + (ncol+ni*8+gp)*68 + k0 + tig;
                msplit(base[0], bhi[ni][0], blo[ni][0]);
                msplit(base[4], bhi[ni][1], blo[ni][1]);
            }
#pragma unroll
            for (int mi=0;mi<2;mi++)
#pragma unroll
            for (int ni=0;ni<4;ni++)
                mma3x(c[mi][ni], ah[mi], al[mi], bhi[ni], blo[ni]);
        }
#pragma unroll
        for (int mi=0;mi<2;mi++)
#pragma unroll
        for (int ni=0;ni<4;ni++){
            int row = mrow+mi*16+gp, col = colbase+ncol+ni*8+2*tig;
            *(float2*)(dst + (size_t)row*1024 + col) =
                make_float2(c[mi][ni][0]*0.125f, c[mi][ni][1]*0.125f);
            *(float2*)(dst + (size_t)(row+8)*1024 + col) =
                make_float2(c[mi][ni][2]*0.125f, c[mi][ni][3]*0.125f);
        }
    }
}

// ---------------- softmax ----------------
__global__ __launch_bounds__(256) void k_softmax() {
    float* row = g_attn + ((size_t)blockIdx.x * 1024 + blockIdx.y) * 1024;
    int t = threadIdx.x;
    float v0 = row[t], v1 = row[t+256], v2 = row[t+512], v3 = row[t+768];
    float m = fmaxf(fmaxf(v0, v1), fmaxf(v2, v3));
    __shared__ float red[8];
    __shared__ float red2[8];
#pragma unroll
    for (int o = 16; o; o >>= 1) m = fmaxf(m, __shfl_xor_sync(0xffffffffu, m, o));
    if ((t & 31) == 0) red[t >> 5] = m;
    __syncthreads();
    if (t == 0) {
        float mm = red[0];
#pragma unroll
        for (int i = 1; i < 8; i++) mm = fmaxf(mm, red[i]);
        red[0] = mm;
    }
    __syncthreads();
    m = red[0];
    float e0 = __expf(v0 - m), e1 = __expf(v1 - m), e2 = __expf(v2 - m), e3 = __expf(v3 - m);
    float s = e0 + e1 + e2 + e3;
#pragma unroll
    for (int o = 16; o; o >>= 1) s += __shfl_xor_sync(0xffffffffu, s, o);
    if ((t & 31) == 0) red2[t >> 5] = s;
    __syncthreads();
    if (t == 0) {
        float ss = 0.f;
#pragma unroll
        for (int i = 0; i < 8; i++) ss += red2[i];
        red2[0] = ss;
    }
    __syncthreads();
    float inv = 1.0f / red2[0];
    row[t] = e0*inv; row[t+256] = e1*inv; row[t+512] = e2*inv; row[t+768] = e3*inv;
}

// ---------------- column sums ----------------
__global__ __launch_bounds__(256) void k_colsum() {
    int bh = blockIdx.x;
    int k = blockIdx.y * 256 + threadIdx.x;
    const float* a = g_attn + ((size_t)bh << 20) + k;
    float s = 0.f;
#pragma unroll 8
    for (int q = 0; q < 1024; q++) s += a[(size_t)q << 10];
    g_score[bh*1024 + k] = s;
}

// ---------------- top-k bitonic ----------------
__global__ __launch_bounds__(512) void k_topk() {
    int bh = blockIdx.x;
    __shared__ float sv[1024];
    __shared__ int si[1024];
    int t = threadIdx.x;
    sv[t]       = g_score[bh*1024 + t];       si[t]       = t;
    sv[t + 512] = g_score[bh*1024 + t + 512]; si[t + 512] = t + 512;
    __syncthreads();
    for (int k = 2; k <= 1024; k <<= 1) {
        for (int j = k >> 1; j > 0; j >>= 1) {
#pragma unroll
            for (int mm = 0; mm < 2; mm++) {
                int i = t + mm*512;
                int l = i ^ j;
                if (l > i) {
                    float vi = sv[i], vl = sv[l];
                    int ii = si[i], il = si[l];
                    bool before = (vi > vl) || (vi == vl && ii < il);
                    bool keep = ((i & k) == 0) ? before : !before;
                    if (!keep) { sv[i] = vl; sv[l] = vi; si[i] = il; si[l] = ii; }
                }
            }
            __syncthreads();
        }
    }
    if (t < 256) g_topk[bh*KF + t] = si[t];
}

// ---------------- attn @ V (tf32 3x): block m128 x n64, warp m32 x n32 ------
// grid (32 bh, 8 qb) block 256
__global__ __launch_bounds__(256) void k_av_t(int fine) {
    int bh = blockIdx.x, qb = blockIdx.y;
    int b = bh >> 2, h = bh & 3;
    __shared__ float sA[128*68];
    __shared__ float sV[64*72];
    int t=threadIdx.x, w=t>>5, lane=t&31, gp=lane>>2, tig=lane&3;
    int mrow=(w>>1)*32, ncol=(w&1)*32;
    const float* attn = g_attn + ((size_t)bh << 20) + (size_t)qb*128*1024;
    const float* vptr = g_qkv + (size_t)bh * P * 192 + 128;
    float c[2][4][4];
#pragma unroll
    for (int i=0;i<2;i++)
#pragma unroll
    for (int jn=0;jn<4;jn++)
#pragma unroll
    for (int k=0;k<4;k++) c[i][jn][k]=0.f;

    for (int kc = 0; kc < 16; kc++) {
        __syncthreads();
        for (int idx=t; idx<2048; idx+=256){
            int r=idx>>4, c4=(idx&15)<<2;
            *(float4*)(sA + r*68 + c4) = *(const float4*)(attn + (size_t)r*1024 + kc*64 + c4);
        }
        for (int idx=t; idx<1024; idx+=256){
            int r=idx>>4, c4=(idx&15)<<2;
            *(float4*)(sV + r*72 + c4) = *(const float4*)(vptr + (size_t)(kc*64+r)*192 + c4);
        }
        __syncthreads();
#pragma unroll
        for (int kk=0;kk<8;kk++){
            int k0=kk*8;
            unsigned ah[2][4], al[2][4], bhi[4][2], blo[4][2];
#pragma unroll
            for (int mi=0;mi<2;mi++){
                const float* base = sA + (mrow+mi*16+gp)*68 + k0 + tig;
                msplit(base[0],      ah[mi][0], al[mi][0]);
                msplit(base[8*68],   ah[mi][1], al[mi][1]);
                msplit(base[4],      ah[mi][2], al[mi][2]);
                msplit(base[8*68+4], ah[mi][3], al[mi][3]);
            }
#pragma unroll
            for (int ni=0;ni<4;ni++){
                int n = ncol+ni*8+gp;
                msplit(sV[(k0+tig)*72   + n], bhi[ni][0], blo[ni][0]);
                msplit(sV[(k0+tig+4)*72 + n], bhi[ni][1], blo[ni][1]);
            }
#pragma unroll
            for (int mi=0;mi<2;mi++)
#pragma unroll
            for (int ni=0;ni<4;ni++)
                mma3x(c[mi][ni], ah[mi], al[mi], bhi[ni], blo[ni]);
        }
    }
    if (!fine) {
#pragma unroll
        for (int mi=0;mi<2;mi++)
#pragma unroll
        for (int ni=0;ni<4;ni++){
            int row = qb*128 + mrow+mi*16+gp;
            int d0 = ncol+ni*8+2*tig;
            g_outc[((size_t)(b*C + h*HD + d0  ))*PLANE32 + row] = c[mi][ni][0];
            g_outc[((size_t)(b*C + h*HD + d0+1))*PLANE32 + row] = c[mi][ni][1];
            g_outc[((size_t)(b*C + h*HD + d0  ))*PLANE32 + row + 8] = c[mi][ni][2];
            g_outc[((size_t)(b*C + h*HD + d0+1))*PLANE32 + row + 8] = c[mi][ni][3];
        }
    } else {
#pragma unroll
        for (int mi=0;mi<2;mi++)
#pragma unroll
        for (int ni=0;ni<4;ni++){
            int row = qb*128 + mrow+mi*16+gp;
            int d0 = ncol+ni*8+2*tig;
            *(float2*)(g_outf + ((size_t)bh*P + row)*HD + d0) =
                make_float2(c[mi][ni][0], c[mi][ni][1]);
            *(float2*)(g_outf + ((size_t)bh*P + row + 8)*HD + d0) =
                make_float2(c[mi][ni][2], c[mi][ni][3]);
        }
    }
}

// ---------------- scatter fine output ----------------
__global__ __launch_bounds__(256) void k_scatter() {
    int bh = blockIdx.x, ki = blockIdx.y;
    int t = threadIdx.x;
    int s = t >> 6, d = t & 63;
    int b = bh >> 2, h = bh & 3;
    int p = g_topk[bh*KF + ki];
    int yy = ((p >> 5) << 1) + (s >> 1);
    int xx = ((p & 31) << 1) + (s & 1);
    float val = g_outf[((size_t)bh * P + ki*4 + s) * HD + d];
    g_y[(((size_t)(b*C + h*HD + d)) << 12) + (yy << 6) + xx] += val;
}

// ---------------- depthwise 3x3 + BN + relu6 ----------------
__global__ __launch_bounds__(256) void k_dw(const float* __restrict__ wdw,
                                            const float* __restrict__ g,
                                            const float* __restrict__ bb,
                                            const float* __restrict__ m,
                                            const float* __restrict__ vv) {
    size_t i = (size_t)blockIdx.x * 256 + threadIdx.x;
    int x = i & 63, y = (i >> 6) & 63;
    int c = (int)((i >> 12) & 255);
    const float* plane = g_y + ((i >> 12) << 12);
    const float* wc = wdw + c*9;
    float s = 0.f;
#pragma unroll
    for (int ky = 0; ky < 3; ky++) {
        int yy = y + ky - 1;
        if (yy < 0 || yy >= 64) continue;
#pragma unroll
        for (int kx = 0; kx < 3; kx++) {
            int xx = x + kx - 1;
            if (xx < 0 || xx >= 64) continue;
            s = fmaf(wc[ky*3 + kx], plane[(yy << 6) + xx], s);
        }
    }
    float sc = g[c] * rsqrtf(vv[c] + 1e-5f);
    float r = s * sc + (bb[c] - m[c] * sc);
    g_yd[i] = fminf(fmaxf(r, 0.f), 6.f);
}

// ---------------- pointwise 1x1 (tf32 3x) + BN + relu6 -> output ------------
// grid (8 b, 32 sp of 128px, 4 cg of 64co) block 256; warp m32 x n32
__global__ __launch_bounds__(256) void k_pw_t(const float* __restrict__ wpw,
                                              const float* __restrict__ g,
                                              const float* __restrict__ bb,
                                              const float* __restrict__ m,
                                              const float* __restrict__ vv,
                                              float* __restrict__ out) {
    int b = blockIdx.x, sp = blockIdx.y, cg = blockIdx.z;
    __shared__ float sW2[64*36];
    __shared__ float sX[32*136];
    int t=threadIdx.x, w=t>>5, lane=t&31, gp=lane>>2, tig=lane&3;
    int mrow=(w>>2)*32, ncol=(w&3)*32;
    float c[2][4][4];
#pragma unroll
    for (int i=0;i<2;i++)
#pragma unroll
    for (int jn=0;jn<4;jn++)
#pragma unroll
    for (int k=0;k<4;k++) c[i][jn][k]=0.f;
    const float* xin = g_yd + (size_t)b * C * HW + sp * 128;
    for (int cc = 0; cc < 8; cc++) {
        __syncthreads();
        for (int idx=t; idx<512; idx+=256){
            int mm2=idx>>3, k4=(idx&7)<<2;
            *(float4*)(sW2 + mm2*36 + k4) =
                *(const float4*)(wpw + (size_t)(cg*64+mm2)*256 + cc*32 + k4);
        }
        for (int idx=t; idx<1024; idx+=256){
            int k=idx>>5, n4=(idx&31)<<2;
            *(float4*)(sX + k*136 + n4) =
                *(const float4*)(xin + (size_t)(cc*32+k)*HW + n4);
        }
        __syncthreads();
#pragma unroll
        for (int kk=0;kk<4;kk++){
            int k0=kk*8;
            unsigned ah[2][4], al[2][4], bhi[4][2], blo[4][2];
#pragma unroll
            for (int mi=0;mi<2;mi++){
                const float* base = sW2 + (mrow+mi*16+gp)*36 + k0 + tig;
                msplit(base[0],      ah[mi][0], al[mi][0]);
                msplit(base[8*36],   ah[mi][1], al[mi][1]);
                msplit(base[4],      ah[mi][2], al[mi][2]);
                msplit(base[8*36+4], ah[mi][3], al[mi][3]);
            }
#pragma unroll
            for (int ni=0;ni<4;ni++){
                int n = ncol+ni*8+gp;
                msplit(sX[(k0+tig)*136   + n], bhi[ni][0], blo[ni][0]);
                msplit(sX[(k0+tig+4)*136 + n], bhi[ni][1], blo[ni][1]);
            }
#pragma unroll
            for (int mi=0;mi<2;mi++)
#pragma unroll
            for (int ni=0;ni<4;ni++)
                mma3x(c[mi][ni], ah[mi], al[mi], bhi[ni], blo[ni]);
        }
    }
#pragma unroll
    for (int mi=0;mi<2;mi++){
        int co = cg*64 + mrow+mi*16+gp;
        float sc0 = g[co] * rsqrtf(vv[co] + 1e-5f);
        float of0 = bb[co] - m[co] * sc0;
        float sc1 = g[co+8] * rsqrtf(vv[co+8] + 1e-5f);
        float of1 = bb[co+8] - m[co+8] * sc1;
#pragma unroll
        for (int ni=0;ni<4;ni++){
            int px = sp*128 + ncol+ni*8+2*tig;
            float r0 = fminf(fmaxf(c[mi][ni][0]*sc0 + of0, 0.f), 6.f);
            float r1 = fminf(fmaxf(c[mi][ni][1]*sc0 + of0, 0.f), 6.f);
            float r2 = fminf(fmaxf(c[mi][ni][2]*sc1 + of1, 0.f), 6.f);
            float r3 = fminf(fmaxf(c[mi][ni][3]*sc1 + of1, 0.f), 6.f);
            *(float2*)(out + ((size_t)(b*C+co))*HW + px)   = make_float2(r0, r1);
            *(float2*)(out + ((size_t)(b*C+co+8))*HW + px) = make_float2(r2, r3);
        }
    }
}

// ---------------- launch ----------------
extern "C" void kernel_launch(void* const* d_in, const int* in_sizes, int n_in,
                              void* d_out, int out_size) {
    const float* x       = (const float*)d_in[0];
    const float* w_down  = (const float*)d_in[1];
    const float* b_down  = (const float*)d_in[2];
    const float* w_qkv_c = (const float*)d_in[3];
    const float* b_qkv_c = (const float*)d_in[4];
    const float* w_up    = (const float*)d_in[5];
    const float* b_up    = (const float*)d_in[6];
    const float* w_qkv_f = (const float*)d_in[7];
    const float* b_qkv_f = (const float*)d_in[8];
    const float* w_dw    = (const float*)d_in[9];
    const float* bn_dw_g = (const float*)d_in[10];
    const float* bn_dw_b = (const float*)d_in[11];
    const float* bn_dw_m = (const float*)d_in[12];
    const float* bn_dw_v = (const float*)d_in[13];
    const float* w_pw    = (const float*)d_in[14];
    const float* bn_pw_g = (const float*)d_in[15];
    const float* bn_pw_b = (const float*)d_in[16];
    const float* bn_pw_m = (const float*)d_in[17];
    const float* bn_pw_v = (const float*)d_in[18];
    float* out = (float*)d_out;

    k_wt<<<4096, 256>>>(w_up);

    // ---- coarse attention path ----
    k_down_t<<<dim3(64, 4), 256>>>(x, w_down, b_down);
    k_qkv_t<<<dim3(32, 16), 256>>>(w_qkv_c, b_qkv_c, 0);
    k_logits_t<<<dim3(32, 16, 2), 256>>>();
    k_softmax<<<dim3(32, 1024), 256>>>();
    k_colsum<<<dim3(32, 4), 256>>>();
    k_av_t<<<dim3(32, 8), 256>>>(0);
    k_topk<<<32, 512>>>();
    k_up_t<<<dim3(64, 16), 256>>>(b_up);

    // ---- fine (top-k) attention path ----
    k_qkv_t<<<dim3(32, 16), 256>>>(w_qkv_f, b_qkv_f, 1);
    k_logits_t<<<dim3(32, 16, 2), 256>>>();
    k_softmax<<<dim3(32, 1024), 256>>>();
    k_av_t<<<dim3(32, 8), 256>>>(1);

    // ---- combine + feed-forward ----
    k_scatter<<<dim3(32, 256), 256>>>();
    k_dw<<<32768, 256>>>(w_dw, bn_dw_g, bn_dw_b, bn_dw_m, bn_dw_v);
    k_pw_t<<<dim3(8, 32, 4), 256>>>(w_pw, bn_pw_g, bn_pw_b, bn_pw_m, bn_pw_v, out);
}

// round 7
// speedup vs baseline: 2.7174x; 1.1838x over previous
#include <cuda_runtime.h>
#include <math.h>

#define BATCH 8
#define C 256
#define NH 4
#define HD 64
#define P 1024
#define KF 256
#define HW 4096
#define PLANE32 1024

__device__ float g_xd[BATCH*C*PLANE32];
__device__ float g_qkv[BATCH*NH*P*192];
__device__ float g_attn[(size_t)BATCH*NH*P*P];
__device__ float g_outc[BATCH*C*PLANE32];
__device__ float g_coarse[BATCH*C*HW];
__device__ float g_score[BATCH*NH*P];
__device__ int   g_topk[BATCH*NH*KF];
__device__ float g_outf[BATCH*NH*P*HD];
__device__ float g_y[BATCH*C*HW];
__device__ float g_yd[BATCH*C*HW];
__device__ unsigned g_wdh[256*2048], g_wdl[256*2048];   // down W packed [co][kpair]
__device__ unsigned g_wuh[4*256*512], g_wul[4*256*512]; // convT W packed [cls][co][kpair]
__device__ unsigned g_pwh[256*128],  g_pwl[256*128];    // pw W packed [co][cipair]

// ---- tf32 helpers (qkv only) ----
__device__ __forceinline__ void msplit(float x, unsigned &hi, unsigned &lo){
    unsigned xb = __float_as_uint(x);
    hi = xb & 0xFFFFE000u;
    lo = __float_as_uint(x - __uint_as_float(hi));
}
__device__ __forceinline__ void mma8(float* c, unsigned a0,unsigned a1,unsigned a2,unsigned a3,
                                     unsigned b0,unsigned b1){
    asm volatile("mma.sync.aligned.m16n8k8.row.col.f32.tf32.tf32.f32 "
        "{%0,%1,%2,%3}, {%4,%5,%6,%7}, {%8,%9}, {%0,%1,%2,%3};"
        : "+f"(c[0]),"+f"(c[1]),"+f"(c[2]),"+f"(c[3])
        : "r"(a0),"r"(a1),"r"(a2),"r"(a3),"r"(b0),"r"(b1));
}
__device__ __forceinline__ void mma3x(float* c, const unsigned* ah, const unsigned* al,
                                      const unsigned* bh, const unsigned* bl){
    mma8(c, ah[0],ah[1],ah[2],ah[3], bh[0],bh[1]);
    mma8(c, ah[0],ah[1],ah[2],ah[3], bl[0],bl[1]);
    mma8(c, al[0],al[1],al[2],al[3], bh[0],bh[1]);
}

// ---- bf16 helpers ----
__device__ __forceinline__ unsigned bpack(float x0, float x1){   // x0->low, x1->high
    unsigned r; asm("cvt.rn.bf16x2.f32 %0, %1, %2;" : "=r"(r) : "f"(x1), "f"(x0)); return r;
}
__device__ __forceinline__ void bsplit2(float x0, float x1, unsigned &h, unsigned &l){
    h = bpack(x0, x1);
    l = bpack(x0 - __uint_as_float(h << 16), x1 - __uint_as_float(h & 0xFFFF0000u));
}
__device__ __forceinline__ void bmma(float* c, unsigned a0,unsigned a1,unsigned a2,unsigned a3,
                                     unsigned b0,unsigned b1){
    asm volatile("mma.sync.aligned.m16n8k16.row.col.f32.bf16.bf16.f32 "
        "{%0,%1,%2,%3}, {%4,%5,%6,%7}, {%8,%9}, {%0,%1,%2,%3};"
        : "+f"(c[0]),"+f"(c[1]),"+f"(c[2]),"+f"(c[3])
        : "r"(a0),"r"(a1),"r"(a2),"r"(a3),"r"(b0),"r"(b1));
}
__device__ __forceinline__ void bmma3(float* c, const unsigned* Ah, const unsigned* Al,
                                      const unsigned* Bh, const unsigned* Bl){
    bmma(c, Ah[0],Ah[1],Ah[2],Ah[3], Bh[0],Bh[1]);
    bmma(c, Ah[0],Ah[1],Ah[2],Ah[3], Bl[0],Bl[1]);
    bmma(c, Al[0],Al[1],Al[2],Al[3], Bh[0],Bh[1]);
}

// ---- weight prep ----
__global__ __launch_bounds__(256) void k_prep_wd(const float* __restrict__ w){
    int i = blockIdx.x*256 + threadIdx.x;
    float2 v = *(const float2*)(w + 2*(size_t)i);
    bsplit2(v.x, v.y, g_wdh[i], g_wdl[i]);
}
__global__ __launch_bounds__(256) void k_wt(const float* __restrict__ wup){
    int idx = blockIdx.x*256 + threadIdx.x;   // [cls][co][kp], 4*256*512
    int cls = idx>>17, co = (idx>>9)&255, kp = idx&511;
    int py = cls>>1, pxp = cls&1;
    int ci = kp>>1, j0 = (kp&1)*2;
    int ky0 = py + ((j0>>1)<<1);
    float v0 = wup[((size_t)ci*256+co)*16 + ky0*4 + pxp];
    float v1 = wup[((size_t)ci*256+co)*16 + ky0*4 + pxp + 2];
    bsplit2(v0, v1, g_wuh[idx], g_wul[idx]);
}
__global__ __launch_bounds__(256) void k_prep_pw(const float* __restrict__ w){
    int i = blockIdx.x*256 + threadIdx.x;
    float2 v = *(const float2*)(w + 2*(size_t)i);
    bsplit2(v.x, v.y, g_pwh[i], g_pwl[i]);
}

// ---- down conv, bf16: grid(64,4) ----
__global__ __launch_bounds__(256) void k_down_t(const float* __restrict__ x,
                                                const float* __restrict__ bias){
    int b = blockIdx.x>>3, oyq = blockIdx.x&7;
    int co0 = blockIdx.y*64;
    __shared__ unsigned sWh[64*36], sWl[64*36];
    __shared__ float sraw[4*10*72];
    int t=threadIdx.x, w=t>>5, lane=t&31, gp=lane>>2, tig=lane&3;
    int mrow=(w>>2)*32, ncol=(w&3)*32;
    float c[2][4][4];
#pragma unroll
    for (int i=0;i<2;i++)
#pragma unroll
    for (int jn=0;jn<4;jn++)
#pragma unroll
    for (int k=0;k<4;k++) c[i][jn][k]=0.f;
    for (int cc=0; cc<64; cc++){
        __syncthreads();
        for (int idx=t; idx<512; idx+=256){
            int co=idx>>3, c4=(idx&7)<<2;
            *(uint4*)(sWh + co*36 + c4) = *(const uint4*)(g_wdh + (size_t)(co0+co)*2048 + cc*32 + c4);
            *(uint4*)(sWl + co*36 + c4) = *(const uint4*)(g_wdl + (size_t)(co0+co)*2048 + cc*32 + c4);
        }
        int ci0 = cc*4;
        for (int idx=t; idx<640; idx+=256){
            int rowid = idx>>4, c4=(idx&15)<<2;
            int ci4 = rowid/10, r = rowid - ci4*10;
            int iy = oyq*8 - 1 + r;
            float4 v = make_float4(0.f,0.f,0.f,0.f);
            if (iy>=0 && iy<64)
                v = *(const float4*)(x + (((size_t)(b*C + ci0+ci4))<<12) + (iy<<6) + c4);
            *(float4*)(sraw + rowid*72 + 4 + c4) = v;
        }
        if (t<40){ sraw[t*72+3]=0.f; sraw[t*72+68]=0.f; }
        __syncthreads();
#pragma unroll
        for (int kk=0;kk<4;kk++){
            unsigned Ah[2][4], Al[2][4], Bh[4][2], Bl[4][2];
#pragma unroll
            for (int mi=0;mi<2;mi++){
                const unsigned* bh_ = sWh + (mrow+mi*16+gp)*36 + kk*8 + tig;
                const unsigned* bl_ = sWl + (mrow+mi*16+gp)*36 + kk*8 + tig;
                Ah[mi][0]=bh_[0]; Ah[mi][1]=bh_[8*36]; Ah[mi][2]=bh_[4]; Ah[mi][3]=bh_[8*36+4];
                Al[mi][0]=bl_[0]; Al[mi][1]=bl_[8*36]; Al[mi][2]=bl_[4]; Al[mi][3]=bl_[8*36+4];
            }
#pragma unroll
            for (int ni=0;ni<4;ni++){
                int n = ncol+ni*8+gp; int opy=n>>5, opx=n&31;
#pragma unroll
                for (int kj=0;kj<2;kj++){
                    int k0 = kk*16 + kj*8 + 2*tig;
                    int ci4=k0>>4, tap=k0&15, ky=tap>>2, kx=tap&3;
                    const float* pr = sraw + (ci4*10 + 2*opy+ky)*72 + 3 + 2*opx + kx;
                    bsplit2(pr[0], pr[1], Bh[ni][kj], Bl[ni][kj]);
                }
            }
#pragma unroll
            for (int mi=0;mi<2;mi++)
#pragma unroll
            for (int ni=0;ni<4;ni++)
                bmma3(c[mi][ni], Ah[mi], Al[mi], Bh[ni], Bl[ni]);
        }
    }
#pragma unroll
    for (int mi=0;mi<2;mi++){
        int co = co0+mrow+mi*16+gp;
        float b0v = bias[co], b1v = bias[co+8];
#pragma unroll
        for (int ni=0;ni<4;ni++){
            int n = ncol+ni*8+2*tig; int opy=n>>5, opx=n&31;
            size_t o = ((size_t)(b*C+co)<<10) + (oyq*4+opy)*32 + opx;
            *(float2*)(g_xd + o) = make_float2(c[mi][ni][0]+b0v, c[mi][ni][1]+b0v);
            *(float2*)(g_xd + o + (8<<10)) = make_float2(c[mi][ni][2]+b1v, c[mi][ni][3]+b1v);
        }
    }
}

// ---- convT, bf16: grid(64,16); also writes g_y ----
__global__ __launch_bounds__(256) void k_up_t(const float* __restrict__ bup){
    int b = blockIdx.x>>3, uq = blockIdx.x&7;
    int cls = blockIdx.y>>2, co0 = (blockIdx.y&3)*64;
    int py = cls>>1, pxp = cls&1;
    __shared__ unsigned sWh[64*36], sWl[64*36];
    __shared__ float sraw[16*5*40];
    int t=threadIdx.x, w=t>>5, lane=t&31, gp=lane>>2, tig=lane&3;
    int mrow=(w>>2)*32, ncol=(w&3)*32;
    float c[2][4][4];
#pragma unroll
    for (int i=0;i<2;i++)
#pragma unroll
    for (int jn=0;jn<4;jn++)
#pragma unroll
    for (int k=0;k<4;k++) c[i][jn][k]=0.f;
    for (int cc=0; cc<16; cc++){
        __syncthreads();
        for (int idx=t; idx<512; idx+=256){
            int co=idx>>3, c4=(idx&7)<<2;
            size_t s = (size_t)cls*131072 + (size_t)(co0+co)*512 + cc*32 + c4;
            *(uint4*)(sWh + co*36 + c4) = *(const uint4*)(g_wuh + s);
            *(uint4*)(sWl + co*36 + c4) = *(const uint4*)(g_wul + s);
        }
        int ci0 = cc*16;
        for (int idx=t; idx<640; idx+=256){
            int rowid=idx>>3, c4=(idx&7)<<2;
            int ci16=rowid/5, rr=rowid-ci16*5;
            int iy = uq*4 - py + rr;
            float4 v = make_float4(0.f,0.f,0.f,0.f);
            if (iy>=0 && iy<32)
                v = *(const float4*)(g_outc + (((size_t)(b*C+ci0+ci16))<<10) + (iy<<5) + c4);
            *(float4*)(sraw + rowid*40 + 4 + c4) = v;
        }
        if (t<80){ sraw[t*40+3]=0.f; sraw[t*40+36]=0.f; }
        __syncthreads();
#pragma unroll
        for (int kk=0;kk<4;kk++){
            unsigned Ah[2][4], Al[2][4], Bh[4][2], Bl[4][2];
#pragma unroll
            for (int mi=0;mi<2;mi++){
                const unsigned* bh_ = sWh + (mrow+mi*16+gp)*36 + kk*8 + tig;
                const unsigned* bl_ = sWl + (mrow+mi*16+gp)*36 + kk*8 + tig;
                Ah[mi][0]=bh_[0]; Ah[mi][1]=bh_[8*36]; Ah[mi][2]=bh_[4]; Ah[mi][3]=bh_[8*36+4];
                Al[mi][0]=bl_[0]; Al[mi][1]=bl_[8*36]; Al[mi][2]=bl_[4]; Al[mi][3]=bl_[8*36+4];
            }
#pragma unroll
            for (int ni=0;ni<4;ni++){
                int n = ncol+ni*8+gp; int uu=n>>5, vv=n&31;
#pragma unroll
                for (int kj=0;kj<2;kj++){
                    int k0 = kk*16 + kj*8 + 2*tig;
                    int ci16=k0>>2, j=k0&3;
                    const float* pr = sraw + (ci16*5 + uu+1-(j>>1))*40 + vv + 5 - pxp;
                    bsplit2(pr[0], pr[-1], Bh[ni][kj], Bl[ni][kj]);
                }
            }
#pragma unroll
            for (int mi=0;mi<2;mi++)
#pragma unroll
            for (int ni=0;ni<4;ni++)
                bmma3(c[mi][ni], Ah[mi], Al[mi], Bh[ni], Bl[ni]);
        }
    }
#pragma unroll
    for (int mi=0;mi<2;mi++){
        int co = co0+mrow+mi*16+gp;
        float b0v = bup[co], b1v = bup[co+8];
#pragma unroll
        for (int ni=0;ni<4;ni++){
            int n = ncol+ni*8+2*tig; int uu=n>>5, vv=n&31;
            int oy = 2*(uq*4+uu) + 1 - py;
            int ox = 2*vv + 1 - pxp;
            size_t o0 = (((size_t)(b*C+co))<<12) + oy*64 + ox;
            float v00 = c[mi][ni][0]+b0v, v01 = c[mi][ni][1]+b0v;
            g_coarse[o0] = v00; g_coarse[o0+2] = v01;
            g_y[o0] = v00; g_y[o0+2] = v01;
            size_t o1 = (((size_t)(b*C+co+8))<<12) + oy*64 + ox;
            float v10 = c[mi][ni][2]+b1v, v11 = c[mi][ni][3]+b1v;
            g_coarse[o1] = v10; g_coarse[o1+2] = v11;
            g_y[o1] = v10; g_y[o1+2] = v11;
        }
    }
}

// ---- qkv (tf32, unchanged): grid(32,16) ----
__global__ __launch_bounds__(256) void k_qkv_t(const float* __restrict__ Wm,
                                               const float* __restrict__ bias, int fine) {
    int bh = blockIdx.x, pt = blockIdx.y;
    int b = bh >> 2, h = bh & 3;
    __shared__ float sA[64*68];
    __shared__ float sW[64*104];
    int t=threadIdx.x, w=t>>5, lane=t&31, gp=lane>>2, tig=lane&3;
    int mrow=(w>>2)*32, ncol=(w&3)*24;
    if (!fine) {
        const float* src = g_xd + ((size_t)(b*C + h*HD)) * PLANE32 + pt*64;
        for (int idx = t; idx < 4096; idx += 256) {
            int d = idx >> 6, p = idx & 63;
            sA[p*68 + d] = src[d * PLANE32 + p];
        }
    } else {
        for (int idx = t; idx < 4096; idx += 256) {
            int d = idx >> 6, p = idx & 63;
            int tok = pt*64 + p;
            int ki = tok >> 2, s = tok & 3;
            int pi = g_topk[bh*KF + ki];
            int yy = ((pi >> 5) << 1) + (s >> 1);
            int xx = ((pi & 31) << 1) + (s & 1);
            sA[p*68 + d] = g_coarse[(((size_t)(b*C + h*HD + d)) << 12) + (yy << 6) + xx];
        }
    }
    float* dst = g_qkv + ((size_t)bh * P + pt*64) * 192;
    for (int half = 0; half < 2; half++) {
        __syncthreads();
        for (int idx = t; idx < 1536; idx += 256) {
            int d = idx / 24, n4 = (idx - d*24) << 2;
            *(float4*)(sW + d*104 + n4) = *(const float4*)(Wm + d*192 + half*96 + n4);
        }
        __syncthreads();
        float c[2][3][4];
#pragma unroll
        for (int i=0;i<2;i++)
#pragma unroll
        for (int jn=0;jn<3;jn++)
#pragma unroll
        for (int k=0;k<4;k++) c[i][jn][k]=0.f;
#pragma unroll
        for (int kk=0;kk<8;kk++){
            int k0=kk*8;
            unsigned ah[2][4], al[2][4], bhi[3][2], blo[3][2];
#pragma unroll
            for (int mi=0;mi<2;mi++){
                const float* base = sA + (mrow+mi*16+gp)*68 + k0 + tig;
                msplit(base[0],      ah[mi][0], al[mi][0]);
                msplit(base[8*68],   ah[mi][1], al[mi][1]);
                msplit(base[4],      ah[mi][2], al[mi][2]);
                msplit(base[8*68+4], ah[mi][3], al[mi][3]);
            }
#pragma unroll
            for (int ni=0;ni<3;ni++){
                int n = ncol+ni*8+gp;
                msplit(sW[(k0+tig)*104 + n],   bhi[ni][0], blo[ni][0]);
                msplit(sW[(k0+tig+4)*104 + n], bhi[ni][1], blo[ni][1]);
            }
#pragma unroll
            for (int mi=0;mi<2;mi++)
#pragma unroll
            for (int ni=0;ni<3;ni++)
                mma3x(c[mi][ni], ah[mi], al[mi], bhi[ni], blo[ni]);
        }
#pragma unroll
        for (int mi=0;mi<2;mi++){
            int p = mrow+mi*16+gp;
#pragma unroll
            for (int ni=0;ni<3;ni++){
                int n = half*96 + ncol+ni*8+2*tig;
                float bb0 = bias[n], bb1 = bias[n+1];
                *(float2*)(dst + p*192 + n) = make_float2(c[mi][ni][0]+bb0, c[mi][ni][1]+bb1);
                *(float2*)(dst + (p+8)*192 + n) = make_float2(c[mi][ni][2]+bb0, c[mi][ni][3]+bb1);
            }
        }
    }
}

// ---- logits bf16: grid(32,16,2) ----
__global__ __launch_bounds__(256) void k_logits_t() {
    int bh = blockIdx.x, qt = blockIdx.y, kz = blockIdx.z;
    __shared__ unsigned sQh[64*36], sQl[64*36];
    __shared__ unsigned sKh[128*36], sKl[128*36];
    int t=threadIdx.x, w=t>>5, lane=t&31, gp=lane>>2, tig=lane&3;
    int mrow=(w>>2)*32, ncol=(w&3)*32;
    const float* qkv = g_qkv + (size_t)bh*P*192;
    for (int idx=t; idx<1024; idx+=256){
        int r=idx>>4, f4=idx&15;
        float4 v = *(const float4*)(qkv + (qt*64+r)*192 + f4*4);
        bsplit2(v.x, v.y, sQh[r*36+f4*2],   sQl[r*36+f4*2]);
        bsplit2(v.z, v.w, sQh[r*36+f4*2+1], sQl[r*36+f4*2+1]);
    }
    float* dst = g_attn + ((size_t)bh<<20) + (size_t)qt*64*1024;
    for (int s=0; s<4; s++){
        int colbase = kz*512 + s*128;
        __syncthreads();
        for (int idx=t; idx<2048; idx+=256){
            int r=idx>>4, f4=idx&15;
            float4 v = *(const float4*)(qkv + (colbase+r)*192 + 64 + f4*4);
            bsplit2(v.x, v.y, sKh[r*36+f4*2],   sKl[r*36+f4*2]);
            bsplit2(v.z, v.w, sKh[r*36+f4*2+1], sKl[r*36+f4*2+1]);
        }
        __syncthreads();
        float c[2][4][4];
#pragma unroll
        for (int i=0;i<2;i++)
#pragma unroll
        for (int jn=0;jn<4;jn++)
#pragma unroll
        for (int k=0;k<4;k++) c[i][jn][k]=0.f;
#pragma unroll
        for (int kk=0;kk<4;kk++){
            unsigned Ah[2][4], Al[2][4], Bh[4][2], Bl[4][2];
#pragma unroll
            for (int mi=0;mi<2;mi++){
                const unsigned* bh_ = sQh + (mrow+mi*16+gp)*36 + kk*8 + tig;
                const unsigned* bl_ = sQl + (mrow+mi*16+gp)*36 + kk*8 + tig;
                Ah[mi][0]=bh_[0]; Ah[mi][1]=bh_[8*36]; Ah[mi][2]=bh_[4]; Ah[mi][3]=bh_[8*36+4];
                Al[mi][0]=bl_[0]; Al[mi][1]=bl_[8*36]; Al[mi][2]=bl_[4]; Al[mi][3]=bl_[8*36+4];
            }
#pragma unroll
            for (int ni=0;ni<4;ni++){
                const unsigned* bh_ = sKh + (ncol+ni*8+gp)*36 + kk*8 + tig;
                const unsigned* bl_ = sKl + (ncol+ni*8+gp)*36 + kk*8 + tig;
                Bh[ni][0]=bh_[0]; Bh[ni][1]=bh_[4];
                Bl[ni][0]=bl_[0]; Bl[ni][1]=bl_[4];
            }
#pragma unroll
            for (int mi=0;mi<2;mi++)
#pragma unroll
            for (int ni=0;ni<4;ni++)
                bmma3(c[mi][ni], Ah[mi], Al[mi], Bh[ni], Bl[ni]);
        }
#pragma unroll
        for (int mi=0;mi<2;mi++)
#pragma unroll
        for (int ni=0;ni<4;ni++){
            int row = mrow+mi*16+gp, col = colbase+ncol+ni*8+2*tig;
            *(float2*)(dst + (size_t)row*1024 + col) =
                make_float2(c[mi][ni][0]*0.125f, c[mi][ni][1]*0.125f);
            *(float2*)(dst + (size_t)(row+8)*1024 + col) =
                make_float2(c[mi][ni][2]*0.125f, c[mi][ni][3]*0.125f);
        }
    }
}

// ---- softmax / colsum / topk (unchanged) ----
__global__ __launch_bounds__(256) void k_softmax() {
    float* row = g_attn + ((size_t)blockIdx.x * 1024 + blockIdx.y) * 1024;
    int t = threadIdx.x;
    float v0 = row[t], v1 = row[t+256], v2 = row[t+512], v3 = row[t+768];
    float m = fmaxf(fmaxf(v0, v1), fmaxf(v2, v3));
    __shared__ float red[8], red2[8];
#pragma unroll
    for (int o = 16; o; o >>= 1) m = fmaxf(m, __shfl_xor_sync(0xffffffffu, m, o));
    if ((t & 31) == 0) red[t >> 5] = m;
    __syncthreads();
    if (t == 0) { float mm = red[0];
#pragma unroll
        for (int i = 1; i < 8; i++) mm = fmaxf(mm, red[i]);
        red[0] = mm; }
    __syncthreads();
    m = red[0];
    float e0 = __expf(v0 - m), e1 = __expf(v1 - m), e2 = __expf(v2 - m), e3 = __expf(v3 - m);
    float s = e0 + e1 + e2 + e3;
#pragma unroll
    for (int o = 16; o; o >>= 1) s += __shfl_xor_sync(0xffffffffu, s, o);
    if ((t & 31) == 0) red2[t >> 5] = s;
    __syncthreads();
    if (t == 0) { float ss = 0.f;
#pragma unroll
        for (int i = 0; i < 8; i++) ss += red2[i];
        red2[0] = ss; }
    __syncthreads();
    float inv = 1.0f / red2[0];
    row[t] = e0*inv; row[t+256] = e1*inv; row[t+512] = e2*inv; row[t+768] = e3*inv;
}
__global__ __launch_bounds__(256) void k_colsum() {
    int bh = blockIdx.x;
    int k = blockIdx.y * 256 + threadIdx.x;
    const float* a = g_attn + ((size_t)bh << 20) + k;
    float s = 0.f;
#pragma unroll 8
    for (int q = 0; q < 1024; q++) s += a[(size_t)q << 10];
    g_score[bh*1024 + k] = s;
}
__global__ __launch_bounds__(512) void k_topk() {
    int bh = blockIdx.x;
    __shared__ float sv[1024];
    __shared__ int si[1024];
    int t = threadIdx.x;
    sv[t] = g_score[bh*1024 + t]; si[t] = t;
    sv[t+512] = g_score[bh*1024 + t + 512]; si[t+512] = t + 512;
    __syncthreads();
    for (int k = 2; k <= 1024; k <<= 1) {
        for (int j = k >> 1; j > 0; j >>= 1) {
#pragma unroll
            for (int mm = 0; mm < 2; mm++) {
                int i = t + mm*512;
                int l = i ^ j;
                if (l > i) {
                    float vi = sv[i], vl = sv[l];
                    int ii = si[i], il = si[l];
                    bool before = (vi > vl) || (vi == vl && ii < il);
                    bool keep = ((i & k) == 0) ? before : !before;
                    if (!keep) { sv[i] = vl; sv[l] = vi; si[i] = il; si[l] = ii; }
                }
            }
            __syncthreads();
        }
    }
    if (t < 256) g_topk[bh*KF + t] = si[t];
}

// ---- attn @ V bf16: grid(32,8) block m128 n64 ----
__global__ __launch_bounds__(256) void k_av_t(int fine) {
    int bh = blockIdx.x, qb = blockIdx.y;
    int b = bh >> 2, h = bh & 3;
    __shared__ unsigned sAh[128*36], sAl[128*36];
    __shared__ unsigned sVh[64*36],  sVl[64*36];
    int t=threadIdx.x, w=t>>5, lane=t&31, gp=lane>>2, tig=lane&3;
    int mrow=(w>>1)*32, ncol=(w&1)*32;
    const float* attn = g_attn + ((size_t)bh << 20) + (size_t)qb*128*1024;
    const float* vptr = g_qkv + (size_t)bh * P * 192 + 128;
    float c[2][4][4];
#pragma unroll
    for (int i=0;i<2;i++)
#pragma unroll
    for (int jn=0;jn<4;jn++)
#pragma unroll
    for (int k=0;k<4;k++) c[i][jn][k]=0.f;
    for (int kc = 0; kc < 16; kc++) {
        __syncthreads();
        for (int idx=t; idx<2048; idx+=256){
            int r=idx>>4, f4=idx&15;
            float4 v = *(const float4*)(attn + (size_t)r*1024 + kc*64 + f4*4);
            bsplit2(v.x, v.y, sAh[r*36+f4*2],   sAl[r*36+f4*2]);
            bsplit2(v.z, v.w, sAh[r*36+f4*2+1], sAl[r*36+f4*2+1]);
        }
        for (int idx=t; idx<2048; idx+=256){
            int d=idx&63, tp=idx>>6;
            float v0 = vptr[(size_t)(kc*64+2*tp)*192 + d];
            float v1 = vptr[(size_t)(kc*64+2*tp+1)*192 + d];
            bsplit2(v0, v1, sVh[d*36+tp], sVl[d*36+tp]);
        }
        __syncthreads();
#pragma unroll
        for (int kk=0;kk<4;kk++){
            unsigned Ah[2][4], Al[2][4], Bh[4][2], Bl[4][2];
#pragma unroll
            for (int mi=0;mi<2;mi++){
                const unsigned* bh_ = sAh + (mrow+mi*16+gp)*36 + kk*8 + tig;
                const unsigned* bl_ = sAl + (mrow+mi*16+gp)*36 + kk*8 + tig;
                Ah[mi][0]=bh_[0]; Ah[mi][1]=bh_[8*36]; Ah[mi][2]=bh_[4]; Ah[mi][3]=bh_[8*36+4];
                Al[mi][0]=bl_[0]; Al[mi][1]=bl_[8*36]; Al[mi][2]=bl_[4]; Al[mi][3]=bl_[8*36+4];
            }
#pragma unroll
            for (int ni=0;ni<4;ni++){
                const unsigned* bh_ = sVh + (ncol+ni*8+gp)*36 + kk*8 + tig;
                const unsigned* bl_ = sVl + (ncol+ni*8+gp)*36 + kk*8 + tig;
                Bh[ni][0]=bh_[0]; Bh[ni][1]=bh_[4];
                Bl[ni][0]=bl_[0]; Bl[ni][1]=bl_[4];
            }
#pragma unroll
            for (int mi=0;mi<2;mi++)
#pragma unroll
            for (int ni=0;ni<4;ni++)
                bmma3(c[mi][ni], Ah[mi], Al[mi], Bh[ni], Bl[ni]);
        }
    }
    if (!fine) {
#pragma unroll
        for (int mi=0;mi<2;mi++)
#pragma unroll
        for (int ni=0;ni<4;ni++){
            int row = qb*128 + mrow+mi*16+gp;
            int d0 = ncol+ni*8+2*tig;
            g_outc[((size_t)(b*C + h*HD + d0  ))*PLANE32 + row] = c[mi][ni][0];
            g_outc[((size_t)(b*C + h*HD + d0+1))*PLANE32 + row] = c[mi][ni][1];
            g_outc[((size_t)(b*C + h*HD + d0  ))*PLANE32 + row + 8] = c[mi][ni][2];
            g_outc[((size_t)(b*C + h*HD + d0+1))*PLANE32 + row + 8] = c[mi][ni][3];
        }
    } else {
#pragma unroll
        for (int mi=0;mi<2;mi++)
#pragma unroll
        for (int ni=0;ni<4;ni++){
            int row = qb*128 + mrow+mi*16+gp;
            int d0 = ncol+ni*8+2*tig;
            *(float2*)(g_outf + ((size_t)bh*P + row)*HD + d0) =
                make_float2(c[mi][ni][0], c[mi][ni][1]);
            *(float2*)(g_outf + ((size_t)bh*P + row + 8)*HD + d0) =
                make_float2(c[mi][ni][2], c[mi][ni][3]);
        }
    }
}

// ---- scatter / dw (unchanged) ----
__global__ __launch_bounds__(256) void k_scatter() {
    int bh = blockIdx.x, ki = blockIdx.y;
    int t = threadIdx.x;
    int s = t >> 6, d = t & 63;
    int b = bh >> 2, h = bh & 3;
    int p = g_topk[bh*KF + ki];
    int yy = ((p >> 5) << 1) + (s >> 1);
    int xx = ((p & 31) << 1) + (s & 1);
    float val = g_outf[((size_t)bh * P + ki*4 + s) * HD + d];
    g_y[(((size_t)(b*C + h*HD + d)) << 12) + (yy << 6) + xx] += val;
}
__global__ __launch_bounds__(256) void k_dw(const float* __restrict__ wdw,
                                            const float* __restrict__ g,
                                            const float* __restrict__ bb,
                                            const float* __restrict__ m,
                                            const float* __restrict__ vv) {
    size_t i = (size_t)blockIdx.x * 256 + threadIdx.x;
    int x = i & 63, y = (i >> 6) & 63;
    int c = (int)((i >> 12) & 255);
    const float* plane = g_y + ((i >> 12) << 12);
    const float* wc = wdw + c*9;
    float s = 0.f;
#pragma unroll
    for (int ky = 0; ky < 3; ky++) {
        int yy = y + ky - 1;
        if (yy < 0 || yy >= 64) continue;
#pragma unroll
        for (int kx = 0; kx < 3; kx++) {
            int xx = x + kx - 1;
            if (xx < 0 || xx >= 64) continue;
            s = fmaf(wc[ky*3 + kx], plane[(yy << 6) + xx], s);
        }
    }
    float sc = g[c] * rsqrtf(vv[c] + 1e-5f);
    float r = s * sc + (bb[c] - m[c] * sc);
    g_yd[i] = fminf(fmaxf(r, 0.f), 6.f);
}

// ---- pointwise bf16 + BN + relu6: grid(8,32,4) ----
__global__ __launch_bounds__(256) void k_pw_t(const float* __restrict__ g,
                                              const float* __restrict__ bb,
                                              const float* __restrict__ m,
                                              const float* __restrict__ vv,
                                              float* __restrict__ out) {
    int b = blockIdx.x, sp = blockIdx.y, cg = blockIdx.z;
    __shared__ unsigned sWh[64*20], sWl[64*20];
    __shared__ unsigned sXh[128*20], sXl[128*20];
    int t=threadIdx.x, w=t>>5, lane=t&31, gp=lane>>2, tig=lane&3;
    int mrow=(w>>2)*32, ncol=(w&3)*32;
    float c[2][4][4];
#pragma unroll
    for (int i=0;i<2;i++)
#pragma unroll
    for (int jn=0;jn<4;jn++)
#pragma unroll
    for (int k=0;k<4;k++) c[i][jn][k]=0.f;
    const float* xin = g_yd + (size_t)b * C * HW + sp * 128;
    for (int cc = 0; cc < 8; cc++) {
        __syncthreads();
        if (t < 256) {
            int idx = t;
            int co=idx>>2, c4=(idx&3)<<2;
            *(uint4*)(sWh + co*20 + c4) = *(const uint4*)(g_pwh + (size_t)(cg*64+co)*128 + cc*16 + c4);
            *(uint4*)(sWl + co*20 + c4) = *(const uint4*)(g_pwl + (size_t)(cg*64+co)*128 + cc*16 + c4);
        }
        for (int idx=t; idx<2048; idx+=256){
            int px = idx&127, kp = idx>>7;
            float v0 = xin[(size_t)(cc*32+2*kp)*HW + px];
            float v1 = xin[(size_t)(cc*32+2*kp+1)*HW + px];
            bsplit2(v0, v1, sXh[px*20+kp], sXl[px*20+kp]);
        }
        __syncthreads();
#pragma unroll
        for (int kk=0;kk<2;kk++){
            unsigned Ah[2][4], Al[2][4], Bh[4][2], Bl[4][2];
#pragma unroll
            for (int mi=0;mi<2;mi++){
                const unsigned* bh_ = sWh + (mrow+mi*16+gp)*20 + kk*8 + tig;
                const unsigned* bl_ = sWl + (mrow+mi*16+gp)*20 + kk*8 + tig;
                Ah[mi][0]=bh_[0]; Ah[mi][1]=bh_[8*20]; Ah[mi][2]=bh_[4]; Ah[mi][3]=bh_[8*20+4];
                Al[mi][0]=bl_[0]; Al[mi][1]=bl_[8*20]; Al[mi][2]=bl_[4]; Al[mi][3]=bl_[8*20+4];
            }
#pragma unroll
            for (int ni=0;ni<4;ni++){
                const unsigned* bh_ = sXh + (ncol+ni*8+gp)*20 + kk*8 + tig;
                const unsigned* bl_ = sXl + (ncol+ni*8+gp)*20 + kk*8 + tig;
                Bh[ni][0]=bh_[0]; Bh[ni][1]=bh_[4];
                Bl[ni][0]=bl_[0]; Bl[ni][1]=bl_[4];
            }
#pragma unroll
            for (int mi=0;mi<2;mi++)
#pragma unroll
            for (int ni=0;ni<4;ni++)
                bmma3(c[mi][ni], Ah[mi], Al[mi], Bh[ni], Bl[ni]);
        }
    }
#pragma unroll
    for (int mi=0;mi<2;mi++){
        int co = cg*64 + mrow+mi*16+gp;
        float sc0 = g[co] * rsqrtf(vv[co] + 1e-5f);
        float of0 = bb[co] - m[co] * sc0;
        float sc1 = g[co+8] * rsqrtf(vv[co+8] + 1e-5f);
        float of1 = bb[co+8] - m[co+8] * sc1;
#pragma unroll
        for (int ni=0;ni<4;ni++){
            int px = sp*128 + ncol+ni*8+2*tig;
            float r0 = fminf(fmaxf(c[mi][ni][0]*sc0 + of0, 0.f), 6.f);
            float r1 = fminf(fmaxf(c[mi][ni][1]*sc0 + of0, 0.f), 6.f);
            float r2 = fminf(fmaxf(c[mi][ni][2]*sc1 + of1, 0.f), 6.f);
            float r3 = fminf(fmaxf(c[mi][ni][3]*sc1 + of1, 0.f), 6.f);
            *(float2*)(out + ((size_t)(b*C+co))*HW + px)   = make_float2(r0, r1);
            *(float2*)(out + ((size_t)(b*C+co+8))*HW + px) = make_float2(r2, r3);
        }
    }
}

extern "C" void kernel_launch(void* const* d_in, const int* in_sizes, int n_in,
                              void* d_out, int out_size) {
    const float* x       = (const float*)d_in[0];
    const float* w_down  = (const float*)d_in[1];
    const float* b_down  = (const float*)d_in[2];
    const float* w_qkv_c = (const float*)d_in[3];
    const float* b_qkv_c = (const float*)d_in[4];
    const float* w_up    = (const float*)d_in[5];
    const float* b_up    = (const float*)d_in[6];
    const float* w_qkv_f = (const float*)d_in[7];
    const float* b_qkv_f = (const float*)d_in[8];
    const float* w_dw    = (const float*)d_in[9];
    const float* bn_dw_g = (const float*)d_in[10];
    const float* bn_dw_b = (const float*)d_in[11];
    const float* bn_dw_m = (const float*)d_in[12];
    const float* bn_dw_v = (const float*)d_in[13];
    const float* w_pw    = (const float*)d_in[14];
    const float* bn_pw_g = (const float*)d_in[15];
    const float* bn_pw_b = (const float*)d_in[16];
    const float* bn_pw_m = (const float*)d_in[17];
    const float* bn_pw_v = (const float*)d_in[18];
    float* out = (float*)d_out;

    k_prep_wd<<<2048, 256>>>(w_down);
    k_wt<<<2048, 256>>>(w_up);
    k_prep_pw<<<128, 256>>>(w_pw);

    k_down_t<<<dim3(64, 4), 256>>>(x, b_down);
    k_qkv_t<<<dim3(32, 16), 256>>>(w_qkv_c, b_qkv_c, 0);
    k_logits_t<<<dim3(32, 16, 2), 256>>>();
    k_softmax<<<dim3(32, 1024), 256>>>();
    k_colsum<<<dim3(32, 4), 256>>>();
    k_av_t<<<dim3(32, 8), 256>>>(0);
    k_topk<<<32, 512>>>();
    k_up_t<<<dim3(64, 16), 256>>>(b_up);

    k_qkv_t<<<dim3(32, 16), 256>>>(w_qkv_f, b_qkv_f, 1);
    k_logits_t<<<dim3(32, 16, 2), 256>>>();
    k_softmax<<<dim3(32, 1024), 256>>>();
    k_av_t<<<dim3(32, 8), 256>>>(1);

    k_scatter<<<dim3(32, 256), 256>>>();
    k_dw<<<32768, 256>>>(w_dw, bn_dw_g, bn_dw_b, bn_dw_m, bn_dw_v);
    k_pw_t<<<dim3(8, 32, 4), 256>>>(bn_pw_g, bn_pw_b, bn_pw_m, bn_pw_v, out);
}

// round 8
// speedup vs baseline: 2.7675x; 1.0184x over previous
#include <cuda_runtime.h>
#include <math.h>

#define BATCH 8
#define C 256
#define NH 4
#define HD 64
#define P 1024
#define KF 256
#define HW 4096
#define PLANE32 1024

__device__ float g_xd[BATCH*C*PLANE32];
__device__ float g_qkv[BATCH*NH*P*192];
__device__ float g_attn[(size_t)BATCH*NH*P*P];
__device__ float g_outc[BATCH*C*PLANE32];
__device__ float g_coarse[BATCH*C*HW];
__device__ float g_score[BATCH*NH*P];
__device__ int   g_topk[BATCH*NH*KF];
__device__ float g_outf[BATCH*NH*P*HD];
__device__ float g_y[BATCH*C*HW];
__device__ float g_yd[BATCH*C*HW];
__device__ unsigned g_wdh[256*2048], g_wdl[256*2048];
__device__ unsigned g_wuh[4*256*512], g_wul[4*256*512];
__device__ unsigned g_pwh[256*128],  g_pwl[256*128];

// ---- bf16 helpers ----
__device__ __forceinline__ unsigned bpack(float x0, float x1){
    unsigned r; asm("cvt.rn.bf16x2.f32 %0, %1, %2;" : "=r"(r) : "f"(x1), "f"(x0)); return r;
}
__device__ __forceinline__ void bsplit2(float x0, float x1, unsigned &h, unsigned &l){
    h = bpack(x0, x1);
    l = bpack(x0 - __uint_as_float(h << 16), x1 - __uint_as_float(h & 0xFFFF0000u));
}
__device__ __forceinline__ void bmma(float* c, unsigned a0,unsigned a1,unsigned a2,unsigned a3,
                                     unsigned b0,unsigned b1){
    asm volatile("mma.sync.aligned.m16n8k16.row.col.f32.bf16.bf16.f32 "
        "{%0,%1,%2,%3}, {%4,%5,%6,%7}, {%8,%9}, {%0,%1,%2,%3};"
        : "+f"(c[0]),"+f"(c[1]),"+f"(c[2]),"+f"(c[3])
        : "r"(a0),"r"(a1),"r"(a2),"r"(a3),"r"(b0),"r"(b1));
}
__device__ __forceinline__ void bmma3(float* c, const unsigned* Ah, const unsigned* Al,
                                      const unsigned* Bh, const unsigned* Bl){
    bmma(c, Ah[0],Ah[1],Ah[2],Ah[3], Bh[0],Bh[1]);
    bmma(c, Ah[0],Ah[1],Ah[2],Ah[3], Bl[0],Bl[1]);
    bmma(c, Al[0],Al[1],Al[2],Al[3], Bh[0],Bh[1]);
}

// ---- weight prep ----
__global__ __launch_bounds__(256) void k_prep_wd(const float* __restrict__ w){
    int i = blockIdx.x*256 + threadIdx.x;
    float2 v = *(const float2*)(w + 2*(size_t)i);
    bsplit2(v.x, v.y, g_wdh[i], g_wdl[i]);
}
__global__ __launch_bounds__(256) void k_wt(const float* __restrict__ wup){
    int idx = blockIdx.x*256 + threadIdx.x;
    int cls = idx>>17, co = (idx>>9)&255, kp = idx&511;
    int py = cls>>1, pxp = cls&1;
    int ci = kp>>1, j0 = (kp&1)*2;
    int ky0 = py + ((j0>>1)<<1);
    float v0 = wup[((size_t)ci*256+co)*16 + ky0*4 + pxp];
    float v1 = wup[((size_t)ci*256+co)*16 + ky0*4 + pxp + 2];
    bsplit2(v0, v1, g_wuh[idx], g_wul[idx]);
}
__global__ __launch_bounds__(256) void k_prep_pw(const float* __restrict__ w){
    int i = blockIdx.x*256 + threadIdx.x;
    float2 v = *(const float2*)(w + 2*(size_t)i);
    bsplit2(v.x, v.y, g_pwh[i], g_pwl[i]);
}

// ---- down conv bf16: grid(128,4), 2 out rows (64 px), warp m32 x n16 ----
__global__ __launch_bounds__(256) void k_down_t(const float* __restrict__ x,
                                                const float* __restrict__ bias){
    int b = blockIdx.x>>4, oyp = blockIdx.x&15;
    int co0 = blockIdx.y*64;
    __shared__ unsigned sWh[64*36], sWl[64*36];
    __shared__ float sraw[4*6*72];
    int t=threadIdx.x, w=t>>5, lane=t&31, gp=lane>>2, tig=lane&3;
    int mrow=(w>>2)*32, ncol=(w&3)*16;
    float c[2][2][4];
#pragma unroll
    for (int i=0;i<2;i++)
#pragma unroll
    for (int jn=0;jn<2;jn++)
#pragma unroll
    for (int k=0;k<4;k++) c[i][jn][k]=0.f;
    for (int cc=0; cc<64; cc++){
        __syncthreads();
        for (int idx=t; idx<512; idx+=256){
            int co=idx>>3, c4=(idx&7)<<2;
            *(uint4*)(sWh + co*36 + c4) = *(const uint4*)(g_wdh + (size_t)(co0+co)*2048 + cc*32 + c4);
            *(uint4*)(sWl + co*36 + c4) = *(const uint4*)(g_wdl + (size_t)(co0+co)*2048 + cc*32 + c4);
        }
        int ci0 = cc*4;
        for (int idx=t; idx<384; idx+=256){
            int rowid = idx>>4, c4=(idx&15)<<2;
            int ci4 = rowid/6, r = rowid - ci4*6;
            int iy = oyp*4 - 1 + r;
            float4 v = make_float4(0.f,0.f,0.f,0.f);
            if (iy>=0 && iy<64)
                v = *(const float4*)(x + (((size_t)(b*C + ci0+ci4))<<12) + (iy<<6) + c4);
            *(float4*)(sraw + rowid*72 + 4 + c4) = v;
        }
        if (t<24){ sraw[t*72+3]=0.f; sraw[t*72+68]=0.f; }
        __syncthreads();
#pragma unroll
        for (int kk=0;kk<4;kk++){
            unsigned Ah[2][4], Al[2][4], Bh[2][2], Bl[2][2];
#pragma unroll
            for (int mi=0;mi<2;mi++){
                const unsigned* bh_ = sWh + (mrow+mi*16+gp)*36 + kk*8 + tig;
                const unsigned* bl_ = sWl + (mrow+mi*16+gp)*36 + kk*8 + tig;
                Ah[mi][0]=bh_[0]; Ah[mi][1]=bh_[8*36]; Ah[mi][2]=bh_[4]; Ah[mi][3]=bh_[8*36+4];
                Al[mi][0]=bl_[0]; Al[mi][1]=bl_[8*36]; Al[mi][2]=bl_[4]; Al[mi][3]=bl_[8*36+4];
            }
#pragma unroll
            for (int ni=0;ni<2;ni++){
                int n = ncol+ni*8+gp; int opy=n>>5, opx=n&31;
#pragma unroll
                for (int kj=0;kj<2;kj++){
                    int k0 = kk*16 + kj*8 + 2*tig;
                    int ci4=k0>>4, tap=k0&15, ky=tap>>2, kx=tap&3;
                    const float* pr = sraw + (ci4*6 + 2*opy+ky)*72 + 3 + 2*opx + kx;
                    bsplit2(pr[0], pr[1], Bh[ni][kj], Bl[ni][kj]);
                }
            }
#pragma unroll
            for (int mi=0;mi<2;mi++)
#pragma unroll
            for (int ni=0;ni<2;ni++)
                bmma3(c[mi][ni], Ah[mi], Al[mi], Bh[ni], Bl[ni]);
        }
    }
#pragma unroll
    for (int mi=0;mi<2;mi++){
        int co = co0+mrow+mi*16+gp;
        float b0v = bias[co], b1v = bias[co+8];
#pragma unroll
        for (int ni=0;ni<2;ni++){
            int n = ncol+ni*8+2*tig;
            size_t o = ((size_t)(b*C+co)<<10) + oyp*64 + n;
            *(float2*)(g_xd + o) = make_float2(c[mi][ni][0]+b0v, c[mi][ni][1]+b0v);
            *(float2*)(g_xd + o + (8<<10)) = make_float2(c[mi][ni][2]+b1v, c[mi][ni][3]+b1v);
        }
    }
}

// ---- convT bf16: grid(64,16); also writes g_y ----
__global__ __launch_bounds__(256) void k_up_t(const float* __restrict__ bup){
    int b = blockIdx.x>>3, uq = blockIdx.x&7;
    int cls = blockIdx.y>>2, co0 = (blockIdx.y&3)*64;
    int py = cls>>1, pxp = cls&1;
    __shared__ unsigned sWh[64*36], sWl[64*36];
    __shared__ float sraw[16*5*40];
    int t=threadIdx.x, w=t>>5, lane=t&31, gp=lane>>2, tig=lane&3;
    int mrow=(w>>2)*32, ncol=(w&3)*32;
    float c[2][4][4];
#pragma unroll
    for (int i=0;i<2;i++)
#pragma unroll
    for (int jn=0;jn<4;jn++)
#pragma unroll
    for (int k=0;k<4;k++) c[i][jn][k]=0.f;
    for (int cc=0; cc<16; cc++){
        __syncthreads();
        for (int idx=t; idx<512; idx+=256){
            int co=idx>>3, c4=(idx&7)<<2;
            size_t s = (size_t)cls*131072 + (size_t)(co0+co)*512 + cc*32 + c4;
            *(uint4*)(sWh + co*36 + c4) = *(const uint4*)(g_wuh + s);
            *(uint4*)(sWl + co*36 + c4) = *(const uint4*)(g_wul + s);
        }
        int ci0 = cc*16;
        for (int idx=t; idx<640; idx+=256){
            int rowid=idx>>3, c4=(idx&7)<<2;
            int ci16=rowid/5, rr=rowid-ci16*5;
            int iy = uq*4 - py + rr;
            float4 v = make_float4(0.f,0.f,0.f,0.f);
            if (iy>=0 && iy<32)
                v = *(const float4*)(g_outc + (((size_t)(b*C+ci0+ci16))<<10) + (iy<<5) + c4);
            *(float4*)(sraw + rowid*40 + 4 + c4) = v;
        }
        if (t<80){ sraw[t*40+3]=0.f; sraw[t*40+36]=0.f; }
        __syncthreads();
#pragma unroll
        for (int kk=0;kk<4;kk++){
            unsigned Ah[2][4], Al[2][4], Bh[4][2], Bl[4][2];
#pragma unroll
            for (int mi=0;mi<2;mi++){
                const unsigned* bh_ = sWh + (mrow+mi*16+gp)*36 + kk*8 + tig;
                const unsigned* bl_ = sWl + (mrow+mi*16+gp)*36 + kk*8 + tig;
                Ah[mi][0]=bh_[0]; Ah[mi][1]=bh_[8*36]; Ah[mi][2]=bh_[4]; Ah[mi][3]=bh_[8*36+4];
                Al[mi][0]=bl_[0]; Al[mi][1]=bl_[8*36]; Al[mi][2]=bl_[4]; Al[mi][3]=bl_[8*36+4];
            }
#pragma unroll
            for (int ni=0;ni<4;ni++){
                int n = ncol+ni*8+gp; int uu=n>>5, vv=n&31;
#pragma unroll
                for (int kj=0;kj<2;kj++){
                    int k0 = kk*16 + kj*8 + 2*tig;
                    int ci16=k0>>2, j=k0&3;
                    const float* pr = sraw + (ci16*5 + uu+1-(j>>1))*40 + vv + 5 - pxp;
                    bsplit2(pr[0], pr[-1], Bh[ni][kj], Bl[ni][kj]);
                }
            }
#pragma unroll
            for (int mi=0;mi<2;mi++)
#pragma unroll
            for (int ni=0;ni<4;ni++)
                bmma3(c[mi][ni], Ah[mi], Al[mi], Bh[ni], Bl[ni]);
        }
    }
#pragma unroll
    for (int mi=0;mi<2;mi++){
        int co = co0+mrow+mi*16+gp;
        float b0v = bup[co], b1v = bup[co+8];
#pragma unroll
        for (int ni=0;ni<4;ni++){
            int n = ncol+ni*8+2*tig; int uu=n>>5, vv=n&31;
            int oy = 2*(uq*4+uu) + 1 - py;
            int ox = 2*vv + 1 - pxp;
            size_t o0 = (((size_t)(b*C+co))<<12) + oy*64 + ox;
            float v00 = c[mi][ni][0]+b0v, v01 = c[mi][ni][1]+b0v;
            g_coarse[o0] = v00; g_coarse[o0+2] = v01;
            g_y[o0] = v00; g_y[o0+2] = v01;
            size_t o1 = (((size_t)(b*C+co+8))<<12) + oy*64 + ox;
            float v10 = c[mi][ni][2]+b1v, v11 = c[mi][ni][3]+b1v;
            g_coarse[o1] = v10; g_coarse[o1+2] = v11;
            g_y[o1] = v10; g_y[o1+2] = v11;
        }
    }
}

// ---- qkv bf16: grid(32,16), warp m32 x n24, two halves of 96 ----
__global__ __launch_bounds__(256) void k_qkv_t(const float* __restrict__ Wm,
                                               const float* __restrict__ bias, int fine) {
    int bh = blockIdx.x, pt = blockIdx.y;
    int b = bh >> 2, h = bh & 3;
    __shared__ unsigned sAh[64*36], sAl[64*36];   // [p][dpair]
    __shared__ unsigned sWh2[96*36], sWl2[96*36]; // [n][dpair]
    int t=threadIdx.x, w=t>>5, lane=t&31, gp=lane>>2, tig=lane&3;
    int mrow=(w>>2)*32, ncol=(w&3)*24;
    if (!fine) {
        const float* src = g_xd + ((size_t)(b*C + h*HD)) * PLANE32 + pt*64;
        for (int idx = t; idx < 2048; idx += 256) {
            int dp = idx >> 6, p = idx & 63;
            float v0 = src[(2*dp)*PLANE32 + p];
            float v1 = src[(2*dp+1)*PLANE32 + p];
            bsplit2(v0, v1, sAh[p*36+dp], sAl[p*36+dp]);
        }
    } else {
        for (int idx = t; idx < 2048; idx += 256) {
            int dp = idx >> 6, p = idx & 63;
            int tok = pt*64 + p;
            int ki = tok >> 2, s = tok & 3;
            int pi = g_topk[bh*KF + ki];
            int yy = ((pi >> 5) << 1) + (s >> 1);
            int xx = ((pi & 31) << 1) + (s & 1);
            size_t base = (((size_t)(b*C + h*HD)) << 12) + (yy << 6) + xx;
            float v0 = g_coarse[base + ((size_t)(2*dp) << 12)];
            float v1 = g_coarse[base + ((size_t)(2*dp+1) << 12)];
            bsplit2(v0, v1, sAh[p*36+dp], sAl[p*36+dp]);
        }
    }
    float* dst = g_qkv + ((size_t)bh * P + pt*64) * 192;
    for (int half = 0; half < 2; half++) {
        __syncthreads();
        for (int idx = t; idx < 3072; idx += 256) {
            int dp = idx / 96, n = idx - 96*dp;
            float v0 = Wm[(2*dp)*192 + half*96 + n];
            float v1 = Wm[(2*dp+1)*192 + half*96 + n];
            bsplit2(v0, v1, sWh2[n*36+dp], sWl2[n*36+dp]);
        }
        __syncthreads();
        float c[2][3][4];
#pragma unroll
        for (int i=0;i<2;i++)
#pragma unroll
        for (int jn=0;jn<3;jn++)
#pragma unroll
        for (int k=0;k<4;k++) c[i][jn][k]=0.f;
#pragma unroll
        for (int kk=0;kk<4;kk++){
            unsigned Ah[2][4], Al[2][4], Bh[3][2], Bl[3][2];
#pragma unroll
            for (int mi=0;mi<2;mi++){
                const unsigned* bh_ = sAh + (mrow+mi*16+gp)*36 + kk*8 + tig;
                const unsigned* bl_ = sAl + (mrow+mi*16+gp)*36 + kk*8 + tig;
                Ah[mi][0]=bh_[0]; Ah[mi][1]=bh_[8*36]; Ah[mi][2]=bh_[4]; Ah[mi][3]=bh_[8*36+4];
                Al[mi][0]=bl_[0]; Al[mi][1]=bl_[8*36]; Al[mi][2]=bl_[4]; Al[mi][3]=bl_[8*36+4];
            }
#pragma unroll
            for (int ni=0;ni<3;ni++){
                const unsigned* bh_ = sWh2 + (ncol+ni*8+gp)*36 + kk*8 + tig;
                const unsigned* bl_ = sWl2 + (ncol+ni*8+gp)*36 + kk*8 + tig;
                Bh[ni][0]=bh_[0]; Bh[ni][1]=bh_[4];
                Bl[ni][0]=bl_[0]; Bl[ni][1]=bl_[4];
            }
#pragma unroll
            for (int mi=0;mi<2;mi++)
#pragma unroll
            for (int ni=0;ni<3;ni++)
                bmma3(c[mi][ni], Ah[mi], Al[mi], Bh[ni], Bl[ni]);
        }
#pragma unroll
        for (int mi=0;mi<2;mi++){
            int p = mrow+mi*16+gp;
#pragma unroll
            for (int ni=0;ni<3;ni++){
                int n = half*96 + ncol+ni*8+2*tig;
                float bb0 = bias[n], bb1 = bias[n+1];
                *(float2*)(dst + p*192 + n) = make_float2(c[mi][ni][0]+bb0, c[mi][ni][1]+bb1);
                *(float2*)(dst + (p+8)*192 + n) = make_float2(c[mi][ni][2]+bb0, c[mi][ni][3]+bb1);
            }
        }
    }
}

// ---- logits bf16: grid(32,16,2) ----
__global__ __launch_bounds__(256) void k_logits_t() {
    int bh = blockIdx.x, qt = blockIdx.y, kz = blockIdx.z;
    __shared__ unsigned sQh[64*36], sQl[64*36];
    __shared__ unsigned sKh[128*36], sKl[128*36];
    int t=threadIdx.x, w=t>>5, lane=t&31, gp=lane>>2, tig=lane&3;
    int mrow=(w>>2)*32, ncol=(w&3)*32;
    const float* qkv = g_qkv + (size_t)bh*P*192;
    for (int idx=t; idx<1024; idx+=256){
        int r=idx>>4, f4=idx&15;
        float4 v = *(const float4*)(qkv + (qt*64+r)*192 + f4*4);
        bsplit2(v.x, v.y, sQh[r*36+f4*2],   sQl[r*36+f4*2]);
        bsplit2(v.z, v.w, sQh[r*36+f4*2+1], sQl[r*36+f4*2+1]);
    }
    float* dst = g_attn + ((size_t)bh<<20) + (size_t)qt*64*1024;
    for (int s=0; s<4; s++){
        int colbase = kz*512 + s*128;
        __syncthreads();
        for (int idx=t; idx<2048; idx+=256){
            int r=idx>>4, f4=idx&15;
            float4 v = *(const float4*)(qkv + (colbase+r)*192 + 64 + f4*4);
            bsplit2(v.x, v.y, sKh[r*36+f4*2],   sKl[r*36+f4*2]);
            bsplit2(v.z, v.w, sKh[r*36+f4*2+1], sKl[r*36+f4*2+1]);
        }
        __syncthreads();
        float c[2][4][4];
#pragma unroll
        for (int i=0;i<2;i++)
#pragma unroll
        for (int jn=0;jn<4;jn++)
#pragma unroll
        for (int k=0;k<4;k++) c[i][jn][k]=0.f;
#pragma unroll
        for (int kk=0;kk<4;kk++){
            unsigned Ah[2][4], Al[2][4], Bh[4][2], Bl[4][2];
#pragma unroll
            for (int mi=0;mi<2;mi++){
                const unsigned* bh_ = sQh + (mrow+mi*16+gp)*36 + kk*8 + tig;
                const unsigned* bl_ = sQl + (mrow+mi*16+gp)*36 + kk*8 + tig;
                Ah[mi][0]=bh_[0]; Ah[mi][1]=bh_[8*36]; Ah[mi][2]=bh_[4]; Ah[mi][3]=bh_[8*36+4];
                Al[mi][0]=bl_[0]; Al[mi][1]=bl_[8*36]; Al[mi][2]=bl_[4]; Al[mi][3]=bl_[8*36+4];
            }
#pragma unroll
            for (int ni=0;ni<4;ni++){
                const unsigned* bh_ = sKh + (ncol+ni*8+gp)*36 + kk*8 + tig;
                const unsigned* bl_ = sKl + (ncol+ni*8+gp)*36 + kk*8 + tig;
                Bh[ni][0]=bh_[0]; Bh[ni][1]=bh_[4];
                Bl[ni][0]=bl_[0]; Bl[ni][1]=bl_[4];
            }
#pragma unroll
            for (int mi=0;mi<2;mi++)
#pragma unroll
            for (int ni=0;ni<4;ni++)
                bmma3(c[mi][ni], Ah[mi], Al[mi], Bh[ni], Bl[ni]);
        }
#pragma unroll
        for (int mi=0;mi<2;mi++)
#pragma unroll
        for (int ni=0;ni<4;ni++){
            int row = mrow+mi*16+gp, col = colbase+ncol+ni*8+2*tig;
            *(float2*)(dst + (size_t)row*1024 + col) =
                make_float2(c[mi][ni][0]*0.125f, c[mi][ni][1]*0.125f);
            *(float2*)(dst + (size_t)(row+8)*1024 + col) =
                make_float2(c[mi][ni][2]*0.125f, c[mi][ni][3]*0.125f);
        }
    }
}

// ---- softmax (float4) ----
__global__ __launch_bounds__(256) void k_softmax() {
    float* row = g_attn + ((size_t)blockIdx.x * 1024 + blockIdx.y) * 1024;
    int t = threadIdx.x;
    float4 v = *(float4*)(row + t*4);
    float m = fmaxf(fmaxf(v.x, v.y), fmaxf(v.z, v.w));
    __shared__ float red[8], red2[8];
#pragma unroll
    for (int o = 16; o; o >>= 1) m = fmaxf(m, __shfl_xor_sync(0xffffffffu, m, o));
    if ((t & 31) == 0) red[t >> 5] = m;
    __syncthreads();
    if (t == 0) { float mm = red[0];
#pragma unroll
        for (int i = 1; i < 8; i++) mm = fmaxf(mm, red[i]);
        red[0] = mm; }
    __syncthreads();
    m = red[0];
    float e0 = __expf(v.x - m), e1 = __expf(v.y - m), e2 = __expf(v.z - m), e3 = __expf(v.w - m);
    float s = e0 + e1 + e2 + e3;
#pragma unroll
    for (int o = 16; o; o >>= 1) s += __shfl_xor_sync(0xffffffffu, s, o);
    if ((t & 31) == 0) red2[t >> 5] = s;
    __syncthreads();
    if (t == 0) { float ss = 0.f;
#pragma unroll
        for (int i = 0; i < 8; i++) ss += red2[i];
        red2[0] = ss; }
    __syncthreads();
    float inv = 1.0f / red2[0];
    *(float4*)(row + t*4) = make_float4(e0*inv, e1*inv, e2*inv, e3*inv);
}
__global__ __launch_bounds__(256) void k_colsum() {
    int bh = blockIdx.x;
    int k = blockIdx.y * 256 + threadIdx.x;
    const float* a = g_attn + ((size_t)bh << 20) + k;
    float s = 0.f;
#pragma unroll 8
    for (int q = 0; q < 1024; q++) s += a[(size_t)q << 10];
    g_score[bh*1024 + k] = s;
}
__global__ __launch_bounds__(512) void k_topk() {
    int bh = blockIdx.x;
    __shared__ float sv[1024];
    __shared__ int si[1024];
    int t = threadIdx.x;
    sv[t] = g_score[bh*1024 + t]; si[t] = t;
    sv[t+512] = g_score[bh*1024 + t + 512]; si[t+512] = t + 512;
    __syncthreads();
    for (int k = 2; k <= 1024; k <<= 1) {
        for (int j = k >> 1; j > 0; j >>= 1) {
#pragma unroll
            for (int mm = 0; mm < 2; mm++) {
                int i = t + mm*512;
                int l = i ^ j;
                if (l > i) {
                    float vi = sv[i], vl = sv[l];
                    int ii = si[i], il = si[l];
                    bool before = (vi > vl) || (vi == vl && ii < il);
                    bool keep = ((i & k) == 0) ? before : !before;
                    if (!keep) { sv[i] = vl; sv[l] = vi; si[i] = il; si[l] = ii; }
                }
            }
            __syncthreads();
        }
    }
    if (t < 256) g_topk[bh*KF + t] = si[t];
}

// ---- attn @ V bf16: grid(32,16) m64 tiles, warp m32 x n16 ----
__global__ __launch_bounds__(256) void k_av_t(int fine) {
    int bh = blockIdx.x, qb = blockIdx.y;
    int b = bh >> 2, h = bh & 3;
    __shared__ unsigned sAh[64*36], sAl[64*36];
    __shared__ unsigned sVh[64*36],  sVl[64*36];
    int t=threadIdx.x, w=t>>5, lane=t&31, gp=lane>>2, tig=lane&3;
    int mrow=(w>>2)*32, ncol=(w&3)*16;
    const float* attn = g_attn + ((size_t)bh << 20) + (size_t)qb*64*1024;
    const float* vptr = g_qkv + (size_t)bh * P * 192 + 128;
    float c[2][2][4];
#pragma unroll
    for (int i=0;i<2;i++)
#pragma unroll
    for (int jn=0;jn<2;jn++)
#pragma unroll
    for (int k=0;k<4;k++) c[i][jn][k]=0.f;
    for (int kc = 0; kc < 16; kc++) {
        __syncthreads();
        for (int idx=t; idx<1024; idx+=256){
            int r=idx>>4, f4=idx&15;
            float4 v = *(const float4*)(attn + (size_t)r*1024 + kc*64 + f4*4);
            bsplit2(v.x, v.y, sAh[r*36+f4*2],   sAl[r*36+f4*2]);
            bsplit2(v.z, v.w, sAh[r*36+f4*2+1], sAl[r*36+f4*2+1]);
        }
        for (int idx=t; idx<2048; idx+=256){
            int d=idx&63, tp=idx>>6;
            float v0 = vptr[(size_t)(kc*64+2*tp)*192 + d];
            float v1 = vptr[(size_t)(kc*64+2*tp+1)*192 + d];
            bsplit2(v0, v1, sVh[d*36+tp], sVl[d*36+tp]);
        }
        __syncthreads();
#pragma unroll
        for (int kk=0;kk<4;kk++){
            unsigned Ah[2][4], Al[2][4], Bh[2][2], Bl[2][2];
#pragma unroll
            for (int mi=0;mi<2;mi++){
                const unsigned* bh_ = sAh + (mrow+mi*16+gp)*36 + kk*8 + tig;
                const unsigned* bl_ = sAl + (mrow+mi*16+gp)*36 + kk*8 + tig;
                Ah[mi][0]=bh_[0]; Ah[mi][1]=bh_[8*36]; Ah[mi][2]=bh_[4]; Ah[mi][3]=bh_[8*36+4];
                Al[mi][0]=bl_[0]; Al[mi][1]=bl_[8*36]; Al[mi][2]=bl_[4]; Al[mi][3]=bl_[8*36+4];
            }
#pragma unroll
            for (int ni=0;ni<2;ni++){
                const unsigned* bh_ = sVh + (ncol+ni*8+gp)*36 + kk*8 + tig;
                const unsigned* bl_ = sVl + (ncol+ni*8+gp)*36 + kk*8 + tig;
                Bh[ni][0]=bh_[0]; Bh[ni][1]=bh_[4];
                Bl[ni][0]=bl_[0]; Bl[ni][1]=bl_[4];
            }
#pragma unroll
            for (int mi=0;mi<2;mi++)
#pragma unroll
            for (int ni=0;ni<2;ni++)
                bmma3(c[mi][ni], Ah[mi], Al[mi], Bh[ni], Bl[ni]);
        }
    }
    if (!fine) {
#pragma unroll
        for (int mi=0;mi<2;mi++)
#pragma unroll
        for (int ni=0;ni<2;ni++){
            int row = qb*64 + mrow+mi*16+gp;
            int d0 = ncol+ni*8+2*tig;
            g_outc[((size_t)(b*C + h*HD + d0  ))*PLANE32 + row] = c[mi][ni][0];
            g_outc[((size_t)(b*C + h*HD + d0+1))*PLANE32 + row] = c[mi][ni][1];
            g_outc[((size_t)(b*C + h*HD + d0  ))*PLANE32 + row + 8] = c[mi][ni][2];
            g_outc[((size_t)(b*C + h*HD + d0+1))*PLANE32 + row + 8] = c[mi][ni][3];
        }
    } else {
#pragma unroll
        for (int mi=0;mi<2;mi++)
#pragma unroll
        for (int ni=0;ni<2;ni++){
            int row = qb*64 + mrow+mi*16+gp;
            int d0 = ncol+ni*8+2*tig;
            *(float2*)(g_outf + ((size_t)bh*P + row)*HD + d0) =
                make_float2(c[mi][ni][0], c[mi][ni][1]);
            *(float2*)(g_outf + ((size_t)bh*P + row + 8)*HD + d0) =
                make_float2(c[mi][ni][2], c[mi][ni][3]);
        }
    }
}

// ---- scatter / dw ----
__global__ __launch_bounds__(256) void k_scatter() {
    int bh = blockIdx.x, ki = blockIdx.y;
    int t = threadIdx.x;
    int s = t >> 6, d = t & 63;
    int b = bh >> 2, h = bh & 3;
    int p = g_topk[bh*KF + ki];
    int yy = ((p >> 5) << 1) + (s >> 1);
    int xx = ((p & 31) << 1) + (s & 1);
    float val = g_outf[((size_t)bh * P + ki*4 + s) * HD + d];
    g_y[(((size_t)(b*C + h*HD + d)) << 12) + (yy << 6) + xx] += val;
}
__global__ __launch_bounds__(256) void k_dw(const float* __restrict__ wdw,
                                            const float* __restrict__ g,
                                            const float* __restrict__ bb,
                                            const float* __restrict__ m,
                                            const float* __restrict__ vv) {
    size_t i = (size_t)blockIdx.x * 256 + threadIdx.x;
    int x = i & 63, y = (i >> 6) & 63;
    int c = (int)((i >> 12) & 255);
    const float* plane = g_y + ((i >> 12) << 12);
    const float* wc = wdw + c*9;
    float s = 0.f;
#pragma unroll
    for (int ky = 0; ky < 3; ky++) {
        int yy = y + ky - 1;
        if (yy < 0 || yy >= 64) continue;
#pragma unroll
        for (int kx = 0; kx < 3; kx++) {
            int xx = x + kx - 1;
            if (xx < 0 || xx >= 64) continue;
            s = fmaf(wc[ky*3 + kx], plane[(yy << 6) + xx], s);
        }
    }
    float sc = g[c] * rsqrtf(vv[c] + 1e-5f);
    float r = s * sc + (bb[c] - m[c] * sc);
    g_yd[i] = fminf(fmaxf(r, 0.f), 6.f);
}

// ---- pointwise bf16: grid(8,32,4) ----
__global__ __launch_bounds__(256) void k_pw_t(const float* __restrict__ g,
                                              const float* __restrict__ bb,
                                              const float* __restrict__ m,
                                              const float* __restrict__ vv,
                                              float* __restrict__ out) {
    int b = blockIdx.x, sp = blockIdx.y, cg = blockIdx.z;
    __shared__ unsigned sWh[64*20], sWl[64*20];
    __shared__ unsigned sXh[128*20], sXl[128*20];
    int t=threadIdx.x, w=t>>5, lane=t&31, gp=lane>>2, tig=lane&3;
    int mrow=(w>>2)*32, ncol=(w&3)*32;
    float c[2][4][4];
#pragma unroll
    for (int i=0;i<2;i++)
#pragma unroll
    for (int jn=0;jn<4;jn++)
#pragma unroll
    for (int k=0;k<4;k++) c[i][jn][k]=0.f;
    const float* xin = g_yd + (size_t)b * C * HW + sp * 128;
    for (int cc = 0; cc < 8; cc++) {
        __syncthreads();
        {
            int idx = t;
            int co=idx>>2, c4=(idx&3)<<2;
            *(uint4*)(sWh + co*20 + c4) = *(const uint4*)(g_pwh + (size_t)(cg*64+co)*128 + cc*16 + c4);
            *(uint4*)(sWl + co*20 + c4) = *(const uint4*)(g_pwl + (size_t)(cg*64+co)*128 + cc*16 + c4);
        }
        for (int idx=t; idx<2048; idx+=256){
            int px = idx&127, kp = idx>>7;
            float v0 = xin[(size_t)(cc*32+2*kp)*HW + px];
            float v1 = xin[(size_t)(cc*32+2*kp+1)*HW + px];
            bsplit2(v0, v1, sXh[px*20+kp], sXl[px*20+kp]);
        }
        __syncthreads();
#pragma unroll
        for (int kk=0;kk<2;kk++){
            unsigned Ah[2][4], Al[2][4], Bh[4][2], Bl[4][2];
#pragma unroll
            for (int mi=0;mi<2;mi++){
                const unsigned* bh_ = sWh + (mrow+mi*16+gp)*20 + kk*8 + tig;
                const unsigned* bl_ = sWl + (mrow+mi*16+gp)*20 + kk*8 + tig;
                Ah[mi][0]=bh_[0]; Ah[mi][1]=bh_[8*20]; Ah[mi][2]=bh_[4]; Ah[mi][3]=bh_[8*20+4];
                Al[mi][0]=bl_[0]; Al[mi][1]=bl_[8*20]; Al[mi][2]=bl_[4]; Al[mi][3]=bl_[8*20+4];
            }
#pragma unroll
            for (int ni=0;ni<4;ni++){
                const unsigned* bh_ = sXh + (ncol+ni*8+gp)*20 + kk*8 + tig;
                const unsigned* bl_ = sXl + (ncol+ni*8+gp)*20 + kk*8 + tig;
                Bh[ni][0]=bh_[0]; Bh[ni][1]=bh_[4];
                Bl[ni][0]=bl_[0]; Bl[ni][1]=bl_[4];
            }
#pragma unroll
            for (int mi=0;mi<2;mi++)
#pragma unroll
            for (int ni=0;ni<4;ni++)
                bmma3(c[mi][ni], Ah[mi], Al[mi], Bh[ni], Bl[ni]);
        }
    }
#pragma unroll
    for (int mi=0;mi<2;mi++){
        int co = cg*64 + mrow+mi*16+gp;
        float sc0 = g[co] * rsqrtf(vv[co] + 1e-5f);
        float of0 = bb[co] - m[co] * sc0;
        float sc1 = g[co+8] * rsqrtf(vv[co+8] + 1e-5f);
        float of1 = bb[co+8] - m[co+8] * sc1;
#pragma unroll
        for (int ni=0;ni<4;ni++){
            int px = sp*128 + ncol+ni*8+2*tig;
            float r0 = fminf(fmaxf(c[mi][ni][0]*sc0 + of0, 0.f), 6.f);
            float r1 = fminf(fmaxf(c[mi][ni][1]*sc0 + of0, 0.f), 6.f);
            float r2 = fminf(fmaxf(c[mi][ni][2]*sc1 + of1, 0.f), 6.f);
            float r3 = fminf(fmaxf(c[mi][ni][3]*sc1 + of1, 0.f), 6.f);
            *(float2*)(out + ((size_t)(b*C+co))*HW + px)   = make_float2(r0, r1);
            *(float2*)(out + ((size_t)(b*C+co+8))*HW + px) = make_float2(r2, r3);
        }
    }
}

extern "C" void kernel_launch(void* const* d_in, const int* in_sizes, int n_in,
                              void* d_out, int out_size) {
    const float* x       = (const float*)d_in[0];
    const float* w_down  = (const float*)d_in[1];
    const float* b_down  = (const float*)d_in[2];
    const float* w_qkv_c = (const float*)d_in[3];
    const float* b_qkv_c = (const float*)d_in[4];
    const float* w_up    = (const float*)d_in[5];
    const float* b_up    = (const float*)d_in[6];
    const float* w_qkv_f = (const float*)d_in[7];
    const float* b_qkv_f = (const float*)d_in[8];
    const float* w_dw    = (const float*)d_in[9];
    const float* bn_dw_g = (const float*)d_in[10];
    const float* bn_dw_b = (const float*)d_in[11];
    const float* bn_dw_m = (const float*)d_in[12];
    const float* bn_dw_v = (const float*)d_in[13];
    const float* w_pw    = (const float*)d_in[14];
    const float* bn_pw_g = (const float*)d_in[15];
    const float* bn_pw_b = (const float*)d_in[16];
    const float* bn_pw_m = (const float*)d_in[17];
    const float* bn_pw_v = (const float*)d_in[18];
    float* out = (float*)d_out;

    k_prep_wd<<<2048, 256>>>(w_down);
    k_wt<<<2048, 256>>>(w_up);
    k_prep_pw<<<128, 256>>>(w_pw);

    k_down_t<<<dim3(128, 4), 256>>>(x, b_down);
    k_qkv_t<<<dim3(32, 16), 256>>>(w_qkv_c, b_qkv_c, 0);
    k_logits_t<<<dim3(32, 16, 2), 256>>>();
    k_softmax<<<dim3(32, 1024), 256>>>();
    k_colsum<<<dim3(32, 4), 256>>>();
    k_av_t<<<dim3(32, 16), 256>>>(0);
    k_topk<<<32, 512>>>();
    k_up_t<<<dim3(64, 16), 256>>>(b_up);

    k_qkv_t<<<dim3(32, 16), 256>>>(w_qkv_f, b_qkv_f, 1);
    k_logits_t<<<dim3(32, 16, 2), 256>>>();
    k_softmax<<<dim3(32, 1024), 256>>>();
    k_av_t<<<dim3(32, 16), 256>>>(1);

    k_scatter<<<dim3(32, 256), 256>>>();
    k_dw<<<32768, 256>>>(w_dw, bn_dw_g, bn_dw_b, bn_dw_m, bn_dw_v);
    k_pw_t<<<dim3(8, 32, 4), 256>>>(bn_pw_g, bn_pw_b, bn_pw_m, bn_pw_v, out);
}

// round 9
// speedup vs baseline: 2.7711x; 1.0013x over previous
#include <cuda_runtime.h>
#include <math.h>

#define BATCH 8
#define C 256
#define NH 4
#define HD 64
#define P 1024
#define KF 256
#define HW 4096
#define PLANE32 1024

__device__ float g_xd[BATCH*C*PLANE32];
__device__ float g_qkv[BATCH*NH*P*192];
__device__ float g_attn[(size_t)BATCH*NH*P*P];
__device__ float g_outc[BATCH*C*PLANE32];
__device__ float g_coarse[BATCH*C*HW];
__device__ float g_score[BATCH*NH*P];
__device__ int   g_topk[BATCH*NH*KF];
__device__ float g_outf[BATCH*NH*P*HD];
__device__ float g_y[BATCH*C*HW];
__device__ float g_yd[BATCH*C*HW];
__device__ unsigned g_wdh[256*2048], g_wdl[256*2048];
__device__ unsigned g_wuh[4*256*512], g_wul[4*256*512];
__device__ unsigned g_pwh[256*128],  g_pwl[256*128];

// ---- bf16 helpers ----
__device__ __forceinline__ unsigned bpack(float x0, float x1){
    unsigned r; asm("cvt.rn.bf16x2.f32 %0, %1, %2;" : "=r"(r) : "f"(x1), "f"(x0)); return r;
}
__device__ __forceinline__ void bsplit2(float x0, float x1, unsigned &h, unsigned &l){
    h = bpack(x0, x1);
    l = bpack(x0 - __uint_as_float(h << 16), x1 - __uint_as_float(h & 0xFFFF0000u));
}
__device__ __forceinline__ void bmma(float* c, unsigned a0,unsigned a1,unsigned a2,unsigned a3,
                                     unsigned b0,unsigned b1){
    asm volatile("mma.sync.aligned.m16n8k16.row.col.f32.bf16.bf16.f32 "
        "{%0,%1,%2,%3}, {%4,%5,%6,%7}, {%8,%9}, {%0,%1,%2,%3};"
        : "+f"(c[0]),"+f"(c[1]),"+f"(c[2]),"+f"(c[3])
        : "r"(a0),"r"(a1),"r"(a2),"r"(a3),"r"(b0),"r"(b1));
}
__device__ __forceinline__ void bmma3(float* c, const unsigned* Ah, const unsigned* Al,
                                      const unsigned* Bh, const unsigned* Bl){
    bmma(c, Ah[0],Ah[1],Ah[2],Ah[3], Bh[0],Bh[1]);
    bmma(c, Ah[0],Ah[1],Ah[2],Ah[3], Bl[0],Bl[1]);
    bmma(c, Al[0],Al[1],Al[2],Al[3], Bh[0],Bh[1]);
}
__device__ __forceinline__ void ldsm4(unsigned &r0, unsigned &r1, unsigned &r2, unsigned &r3,
                                      const unsigned* p){
    unsigned a = (unsigned)__cvta_generic_to_shared(p);
    asm volatile("ldmatrix.sync.aligned.m8n8.x4.shared.b16 {%0,%1,%2,%3}, [%4];"
        : "=r"(r0),"=r"(r1),"=r"(r2),"=r"(r3) : "r"(a));
}
__device__ __forceinline__ void ldsm2(unsigned &r0, unsigned &r1, const unsigned* p){
    unsigned a = (unsigned)__cvta_generic_to_shared(p);
    asm volatile("ldmatrix.sync.aligned.m8n8.x2.shared.b16 {%0,%1}, [%2];"
        : "=r"(r0),"=r"(r1) : "r"(a));
}
// A-fragment lane offset (stride s uints): row (lane&15), chunk (lane>>4)*4
#define AOFF(lane,s) (((lane)&15)*(s) + (((lane)>>4)<<2))
// B-fragment (two n-octets) lane offset: row ((lane>>4)*8+(lane&7)), chunk ((lane>>3)&1)*4
#define BOFF(lane,s) (((((lane)>>4)<<3)+((lane)&7))*(s) + ((((lane)>>3)&1)<<2))
// B-fragment (one n-octet, x2) lane offset
#define B2OFF(lane,s) ((((lane)&7))*(s) + ((((lane)>>3)&1)<<2))

// ---- weight prep ----
__global__ __launch_bounds__(256) void k_prep_wd(const float* __restrict__ w){
    int i = blockIdx.x*256 + threadIdx.x;
    float2 v = *(const float2*)(w + 2*(size_t)i);
    bsplit2(v.x, v.y, g_wdh[i], g_wdl[i]);
}
__global__ __launch_bounds__(256) void k_wt(const float* __restrict__ wup){
    int idx = blockIdx.x*256 + threadIdx.x;
    int cls = idx>>17, co = (idx>>9)&255, kp = idx&511;
    int py = cls>>1, pxp = cls&1;
    int ci = kp>>1, j0 = (kp&1)*2;
    int ky0 = py + ((j0>>1)<<1);
    float v0 = wup[((size_t)ci*256+co)*16 + ky0*4 + pxp];
    float v1 = wup[((size_t)ci*256+co)*16 + ky0*4 + pxp + 2];
    bsplit2(v0, v1, g_wuh[idx], g_wul[idx]);
}
__global__ __launch_bounds__(256) void k_prep_pw(const float* __restrict__ w){
    int i = blockIdx.x*256 + threadIdx.x;
    float2 v = *(const float2*)(w + 2*(size_t)i);
    bsplit2(v.x, v.y, g_pwh[i], g_pwl[i]);
}

// ---- down conv bf16: grid(128,4), warp m32 x n16, A via ldmatrix ----
__global__ __launch_bounds__(256) void k_down_t(const float* __restrict__ x,
                                                const float* __restrict__ bias){
    int b = blockIdx.x>>4, oyp = blockIdx.x&15;
    int co0 = blockIdx.y*64;
    __shared__ unsigned sWh[64*36], sWl[64*36];
    __shared__ float sraw[4*6*72];
    int t=threadIdx.x, w=t>>5, lane=t&31, gp=lane>>2, tig=lane&3;
    int mrow=(w>>2)*32, ncol=(w&3)*16;
    int aoff = AOFF(lane,36);
    float c[2][2][4];
#pragma unroll
    for (int i=0;i<2;i++)
#pragma unroll
    for (int jn=0;jn<2;jn++)
#pragma unroll
    for (int k=0;k<4;k++) c[i][jn][k]=0.f;
    for (int cc=0; cc<64; cc++){
        __syncthreads();
        for (int idx=t; idx<512; idx+=256){
            int co=idx>>3, c4=(idx&7)<<2;
            *(uint4*)(sWh + co*36 + c4) = *(const uint4*)(g_wdh + (size_t)(co0+co)*2048 + cc*32 + c4);
            *(uint4*)(sWl + co*36 + c4) = *(const uint4*)(g_wdl + (size_t)(co0+co)*2048 + cc*32 + c4);
        }
        int ci0 = cc*4;
        for (int idx=t; idx<384; idx+=256){
            int rowid = idx>>4, c4=(idx&15)<<2;
            int ci4 = rowid/6, r = rowid - ci4*6;
            int iy = oyp*4 - 1 + r;
            float4 v = make_float4(0.f,0.f,0.f,0.f);
            if (iy>=0 && iy<64)
                v = *(const float4*)(x + (((size_t)(b*C + ci0+ci4))<<12) + (iy<<6) + c4);
            *(float4*)(sraw + rowid*72 + 4 + c4) = v;
        }
        if (t<24){ sraw[t*72+3]=0.f; sraw[t*72+68]=0.f; }
        __syncthreads();
#pragma unroll
        for (int kk=0;kk<4;kk++){
            unsigned Ah[2][4], Al[2][4], Bh[2][2], Bl[2][2];
#pragma unroll
            for (int mi=0;mi<2;mi++){
                ldsm4(Ah[mi][0],Ah[mi][1],Ah[mi][2],Ah[mi][3],
                      sWh + (mrow+mi*16)*36 + kk*8 + aoff);
                ldsm4(Al[mi][0],Al[mi][1],Al[mi][2],Al[mi][3],
                      sWl + (mrow+mi*16)*36 + kk*8 + aoff);
            }
#pragma unroll
            for (int ni=0;ni<2;ni++){
                int n = ncol+ni*8+gp; int opy=n>>5, opx=n&31;
#pragma unroll
                for (int kj=0;kj<2;kj++){
                    int k0 = kk*16 + kj*8 + 2*tig;
                    int ci4=k0>>4, tap=k0&15, ky=tap>>2, kx=tap&3;
                    const float* pr = sraw + (ci4*6 + 2*opy+ky)*72 + 3 + 2*opx + kx;
                    bsplit2(pr[0], pr[1], Bh[ni][kj], Bl[ni][kj]);
                }
            }
#pragma unroll
            for (int mi=0;mi<2;mi++)
#pragma unroll
            for (int ni=0;ni<2;ni++)
                bmma3(c[mi][ni], Ah[mi], Al[mi], Bh[ni], Bl[ni]);
        }
    }
#pragma unroll
    for (int mi=0;mi<2;mi++){
        int co = co0+mrow+mi*16+gp;
        float b0v = bias[co], b1v = bias[co+8];
#pragma unroll
        for (int ni=0;ni<2;ni++){
            int n = ncol+ni*8+2*tig;
            size_t o = ((size_t)(b*C+co)<<10) + oyp*64 + n;
            *(float2*)(g_xd + o) = make_float2(c[mi][ni][0]+b0v, c[mi][ni][1]+b0v);
            *(float2*)(g_xd + o + (8<<10)) = make_float2(c[mi][ni][2]+b1v, c[mi][ni][3]+b1v);
        }
    }
}

// ---- convT bf16: grid(64,16); A via ldmatrix; also writes g_y ----
__global__ __launch_bounds__(256) void k_up_t(const float* __restrict__ bup){
    int b = blockIdx.x>>3, uq = blockIdx.x&7;
    int cls = blockIdx.y>>2, co0 = (blockIdx.y&3)*64;
    int py = cls>>1, pxp = cls&1;
    __shared__ unsigned sWh[64*36], sWl[64*36];
    __shared__ float sraw[16*5*40];
    int t=threadIdx.x, w=t>>5, lane=t&31, gp=lane>>2, tig=lane&3;
    int mrow=(w>>2)*32, ncol=(w&3)*32;
    int aoff = AOFF(lane,36);
    float c[2][4][4];
#pragma unroll
    for (int i=0;i<2;i++)
#pragma unroll
    for (int jn=0;jn<4;jn++)
#pragma unroll
    for (int k=0;k<4;k++) c[i][jn][k]=0.f;
    for (int cc=0; cc<16; cc++){
        __syncthreads();
        for (int idx=t; idx<512; idx+=256){
            int co=idx>>3, c4=(idx&7)<<2;
            size_t s = (size_t)cls*131072 + (size_t)(co0+co)*512 + cc*32 + c4;
            *(uint4*)(sWh + co*36 + c4) = *(const uint4*)(g_wuh + s);
            *(uint4*)(sWl + co*36 + c4) = *(const uint4*)(g_wul + s);
        }
        int ci0 = cc*16;
        for (int idx=t; idx<640; idx+=256){
            int rowid=idx>>3, c4=(idx&7)<<2;
            int ci16=rowid/5, rr=rowid-ci16*5;
            int iy = uq*4 - py + rr;
            float4 v = make_float4(0.f,0.f,0.f,0.f);
            if (iy>=0 && iy<32)
                v = *(const float4*)(g_outc + (((size_t)(b*C+ci0+ci16))<<10) + (iy<<5) + c4);
            *(float4*)(sraw + rowid*40 + 4 + c4) = v;
        }
        if (t<80){ sraw[t*40+3]=0.f; sraw[t*40+36]=0.f; }
        __syncthreads();
#pragma unroll
        for (int kk=0;kk<4;kk++){
            unsigned Ah[2][4], Al[2][4], Bh[4][2], Bl[4][2];
#pragma unroll
            for (int mi=0;mi<2;mi++){
                ldsm4(Ah[mi][0],Ah[mi][1],Ah[mi][2],Ah[mi][3],
                      sWh + (mrow+mi*16)*36 + kk*8 + aoff);
                ldsm4(Al[mi][0],Al[mi][1],Al[mi][2],Al[mi][3],
                      sWl + (mrow+mi*16)*36 + kk*8 + aoff);
            }
#pragma unroll
            for (int ni=0;ni<4;ni++){
                int n = ncol+ni*8+gp; int uu=n>>5, vv=n&31;
#pragma unroll
                for (int kj=0;kj<2;kj++){
                    int k0 = kk*16 + kj*8 + 2*tig;
                    int ci16=k0>>2, j=k0&3;
                    const float* pr = sraw + (ci16*5 + uu+1-(j>>1))*40 + vv + 5 - pxp;
                    bsplit2(pr[0], pr[-1], Bh[ni][kj], Bl[ni][kj]);
                }
            }
#pragma unroll
            for (int mi=0;mi<2;mi++)
#pragma unroll
            for (int ni=0;ni<4;ni++)
                bmma3(c[mi][ni], Ah[mi], Al[mi], Bh[ni], Bl[ni]);
        }
    }
#pragma unroll
    for (int mi=0;mi<2;mi++){
        int co = co0+mrow+mi*16+gp;
        float b0v = bup[co], b1v = bup[co+8];
#pragma unroll
        for (int ni=0;ni<4;ni++){
            int n = ncol+ni*8+2*tig; int uu=n>>5, vv=n&31;
            int oy = 2*(uq*4+uu) + 1 - py;
            int ox = 2*vv + 1 - pxp;
            size_t o0 = (((size_t)(b*C+co))<<12) + oy*64 + ox;
            float v00 = c[mi][ni][0]+b0v, v01 = c[mi][ni][1]+b0v;
            g_coarse[o0] = v00; g_coarse[o0+2] = v01;
            g_y[o0] = v00; g_y[o0+2] = v01;
            size_t o1 = (((size_t)(b*C+co+8))<<12) + oy*64 + ox;
            float v10 = c[mi][ni][2]+b1v, v11 = c[mi][ni][3]+b1v;
            g_coarse[o1] = v10; g_coarse[o1+2] = v11;
            g_y[o1] = v10; g_y[o1+2] = v11;
        }
    }
}

// ---- qkv bf16: grid(32,16), warp m32 x n24, ldmatrix both sides ----
__global__ __launch_bounds__(256) void k_qkv_t(const float* __restrict__ Wm,
                                               const float* __restrict__ bias, int fine) {
    int bh = blockIdx.x, pt = blockIdx.y;
    int b = bh >> 2, h = bh & 3;
    __shared__ unsigned sAh[64*36], sAl[64*36];
    __shared__ unsigned sWh2[96*36], sWl2[96*36];
    int t=threadIdx.x, w=t>>5, lane=t&31, gp=lane>>2, tig=lane&3;
    int mrow=(w>>2)*32, ncol=(w&3)*24;
    int aoff = AOFF(lane,36), boff = BOFF(lane,36), b2off = B2OFF(lane,36);
    if (!fine) {
        const float* src = g_xd + ((size_t)(b*C + h*HD)) * PLANE32 + pt*64;
        for (int idx = t; idx < 2048; idx += 256) {
            int dp = idx >> 6, p = idx & 63;
            float v0 = src[(2*dp)*PLANE32 + p];
            float v1 = src[(2*dp+1)*PLANE32 + p];
            bsplit2(v0, v1, sAh[p*36+dp], sAl[p*36+dp]);
        }
    } else {
        for (int idx = t; idx < 2048; idx += 256) {
            int dp = idx >> 6, p = idx & 63;
            int tok = pt*64 + p;
            int ki = tok >> 2, s = tok & 3;
            int pi = g_topk[bh*KF + ki];
            int yy = ((pi >> 5) << 1) + (s >> 1);
            int xx = ((pi & 31) << 1) + (s & 1);
            size_t base = (((size_t)(b*C + h*HD)) << 12) + (yy << 6) + xx;
            float v0 = g_coarse[base + ((size_t)(2*dp) << 12)];
            float v1 = g_coarse[base + ((size_t)(2*dp+1) << 12)];
            bsplit2(v0, v1, sAh[p*36+dp], sAl[p*36+dp]);
        }
    }
    float* dst = g_qkv + ((size_t)bh * P + pt*64) * 192;
    for (int half = 0; half < 2; half++) {
        __syncthreads();
        for (int idx = t; idx < 3072; idx += 256) {
            int dp = idx / 96, n = idx - 96*dp;
            float v0 = Wm[(2*dp)*192 + half*96 + n];
            float v1 = Wm[(2*dp+1)*192 + half*96 + n];
            bsplit2(v0, v1, sWh2[n*36+dp], sWl2[n*36+dp]);
        }
        __syncthreads();
        float c[2][3][4];
#pragma unroll
        for (int i=0;i<2;i++)
#pragma unroll
        for (int jn=0;jn<3;jn++)
#pragma unroll
        for (int k=0;k<4;k++) c[i][jn][k]=0.f;
#pragma unroll
        for (int kk=0;kk<4;kk++){
            unsigned Ah[2][4], Al[2][4], Bh[3][2], Bl[3][2];
#pragma unroll
            for (int mi=0;mi<2;mi++){
                ldsm4(Ah[mi][0],Ah[mi][1],Ah[mi][2],Ah[mi][3],
                      sAh + (mrow+mi*16)*36 + kk*8 + aoff);
                ldsm4(Al[mi][0],Al[mi][1],Al[mi][2],Al[mi][3],
                      sAl + (mrow+mi*16)*36 + kk*8 + aoff);
            }
            ldsm4(Bh[0][0],Bh[0][1],Bh[1][0],Bh[1][1], sWh2 + ncol*36 + kk*8 + boff);
            ldsm4(Bl[0][0],Bl[0][1],Bl[1][0],Bl[1][1], sWl2 + ncol*36 + kk*8 + boff);
            ldsm2(Bh[2][0],Bh[2][1], sWh2 + (ncol+16)*36 + kk*8 + b2off);
            ldsm2(Bl[2][0],Bl[2][1], sWl2 + (ncol+16)*36 + kk*8 + b2off);
#pragma unroll
            for (int mi=0;mi<2;mi++)
#pragma unroll
            for (int ni=0;ni<3;ni++)
                bmma3(c[mi][ni], Ah[mi], Al[mi], Bh[ni], Bl[ni]);
        }
#pragma unroll
        for (int mi=0;mi<2;mi++){
            int p = mrow+mi*16+gp;
#pragma unroll
            for (int ni=0;ni<3;ni++){
                int n = half*96 + ncol+ni*8+2*tig;
                float bb0 = bias[n], bb1 = bias[n+1];
                *(float2*)(dst + p*192 + n) = make_float2(c[mi][ni][0]+bb0, c[mi][ni][1]+bb1);
                *(float2*)(dst + (p+8)*192 + n) = make_float2(c[mi][ni][2]+bb0, c[mi][ni][3]+bb1);
            }
        }
    }
}

// ---- logits bf16: grid(32,16,2), ldmatrix both sides ----
__global__ __launch_bounds__(256) void k_logits_t() {
    int bh = blockIdx.x, qt = blockIdx.y, kz = blockIdx.z;
    __shared__ unsigned sQh[64*36], sQl[64*36];
    __shared__ unsigned sKh[128*36], sKl[128*36];
    int t=threadIdx.x, w=t>>5, lane=t&31, gp=lane>>2, tig=lane&3;
    int mrow=(w>>2)*32, ncol=(w&3)*32;
    int aoff = AOFF(lane,36), boff = BOFF(lane,36);
    const float* qkv = g_qkv + (size_t)bh*P*192;
    for (int idx=t; idx<1024; idx+=256){
        int r=idx>>4, f4=idx&15;
        float4 v = *(const float4*)(qkv + (qt*64+r)*192 + f4*4);
        bsplit2(v.x, v.y, sQh[r*36+f4*2],   sQl[r*36+f4*2]);
        bsplit2(v.z, v.w, sQh[r*36+f4*2+1], sQl[r*36+f4*2+1]);
    }
    float* dst = g_attn + ((size_t)bh<<20) + (size_t)qt*64*1024;
    for (int s=0; s<4; s++){
        int colbase = kz*512 + s*128;
        __syncthreads();
        for (int idx=t; idx<2048; idx+=256){
            int r=idx>>4, f4=idx&15;
            float4 v = *(const float4*)(qkv + (colbase+r)*192 + 64 + f4*4);
            bsplit2(v.x, v.y, sKh[r*36+f4*2],   sKl[r*36+f4*2]);
            bsplit2(v.z, v.w, sKh[r*36+f4*2+1], sKl[r*36+f4*2+1]);
        }
        __syncthreads();
        float c[2][4][4];
#pragma unroll
        for (int i=0;i<2;i++)
#pragma unroll
        for (int jn=0;jn<4;jn++)
#pragma unroll
        for (int k=0;k<4;k++) c[i][jn][k]=0.f;
#pragma unroll
        for (int kk=0;kk<4;kk++){
            unsigned Ah[2][4], Al[2][4], Bh[4][2], Bl[4][2];
#pragma unroll
            for (int mi=0;mi<2;mi++){
                ldsm4(Ah[mi][0],Ah[mi][1],Ah[mi][2],Ah[mi][3],
                      sQh + (mrow+mi*16)*36 + kk*8 + aoff);
                ldsm4(Al[mi][0],Al[mi][1],Al[mi][2],Al[mi][3],
                      sQl + (mrow+mi*16)*36 + kk*8 + aoff);
            }
            ldsm4(Bh[0][0],Bh[0][1],Bh[1][0],Bh[1][1], sKh + ncol*36 + kk*8 + boff);
            ldsm4(Bl[0][0],Bl[0][1],Bl[1][0],Bl[1][1], sKl + ncol*36 + kk*8 + boff);
            ldsm4(Bh[2][0],Bh[2][1],Bh[3][0],Bh[3][1], sKh + (ncol+16)*36 + kk*8 + boff);
            ldsm4(Bl[2][0],Bl[2][1],Bl[3][0],Bl[3][1], sKl + (ncol+16)*36 + kk*8 + boff);
#pragma unroll
            for (int mi=0;mi<2;mi++)
#pragma unroll
            for (int ni=0;ni<4;ni++)
                bmma3(c[mi][ni], Ah[mi], Al[mi], Bh[ni], Bl[ni]);
        }
#pragma unroll
        for (int mi=0;mi<2;mi++)
#pragma unroll
        for (int ni=0;ni<4;ni++){
            int row = mrow+mi*16+gp, col = colbase+ncol+ni*8+2*tig;
            *(float2*)(dst + (size_t)row*1024 + col) =
                make_float2(c[mi][ni][0]*0.125f, c[mi][ni][1]*0.125f);
            *(float2*)(dst + (size_t)(row+8)*1024 + col) =
                make_float2(c[mi][ni][2]*0.125f, c[mi][ni][3]*0.125f);
        }
    }
}

// ---- softmax / colsum / topk ----
__global__ __launch_bounds__(256) void k_softmax() {
    float* row = g_attn + ((size_t)blockIdx.x * 1024 + blockIdx.y) * 1024;
    int t = threadIdx.x;
    float4 v = *(float4*)(row + t*4);
    float m = fmaxf(fmaxf(v.x, v.y), fmaxf(v.z, v.w));
    __shared__ float red[8], red2[8];
#pragma unroll
    for (int o = 16; o; o >>= 1) m = fmaxf(m, __shfl_xor_sync(0xffffffffu, m, o));
    if ((t & 31) == 0) red[t >> 5] = m;
    __syncthreads();
    if (t == 0) { float mm = red[0];
#pragma unroll
        for (int i = 1; i < 8; i++) mm = fmaxf(mm, red[i]);
        red[0] = mm; }
    __syncthreads();
    m = red[0];
    float e0 = __expf(v.x - m), e1 = __expf(v.y - m), e2 = __expf(v.z - m), e3 = __expf(v.w - m);
    float s = e0 + e1 + e2 + e3;
#pragma unroll
    for (int o = 16; o; o >>= 1) s += __shfl_xor_sync(0xffffffffu, s, o);
    if ((t & 31) == 0) red2[t >> 5] = s;
    __syncthreads();
    if (t == 0) { float ss = 0.f;
#pragma unroll
        for (int i = 0; i < 8; i++) ss += red2[i];
        red2[0] = ss; }
    __syncthreads();
    float inv = 1.0f / red2[0];
    *(float4*)(row + t*4) = make_float4(e0*inv, e1*inv, e2*inv, e3*inv);
}
__global__ __launch_bounds__(256) void k_colsum() {
    int bh = blockIdx.x;
    int k = blockIdx.y * 256 + threadIdx.x;
    const float* a = g_attn + ((size_t)bh << 20) + k;
    float s = 0.f;
#pragma unroll 8
    for (int q = 0; q < 1024; q++) s += a[(size_t)q << 10];
    g_score[bh*1024 + k] = s;
}
__global__ __launch_bounds__(512) void k_topk() {
    int bh = blockIdx.x;
    __shared__ float sv[1024];
    __shared__ int si[1024];
    int t = threadIdx.x;
    sv[t] = g_score[bh*1024 + t]; si[t] = t;
    sv[t+512] = g_score[bh*1024 + t + 512]; si[t+512] = t + 512;
    __syncthreads();
    for (int k = 2; k <= 1024; k <<= 1) {
        for (int j = k >> 1; j > 0; j >>= 1) {
#pragma unroll
            for (int mm = 0; mm < 2; mm++) {
                int i = t + mm*512;
                int l = i ^ j;
                if (l > i) {
                    float vi = sv[i], vl = sv[l];
                    int ii = si[i], il = si[l];
                    bool before = (vi > vl) || (vi == vl && ii < il);
                    bool keep = ((i & k) == 0) ? before : !before;
                    if (!keep) { sv[i] = vl; sv[l] = vi; si[i] = il; si[l] = ii; }
                }
            }
            __syncthreads();
        }
    }
    if (t < 256) g_topk[bh*KF + t] = si[t];
}

// ---- attn @ V bf16: grid(32,16), warp m32 x n16, ldmatrix ----
__global__ __launch_bounds__(256) void k_av_t(int fine) {
    int bh = blockIdx.x, qb = blockIdx.y;
    int b = bh >> 2, h = bh & 3;
    __shared__ unsigned sAh[64*36], sAl[64*36];
    __shared__ unsigned sVh[64*36],  sVl[64*36];
    int t=threadIdx.x, w=t>>5, lane=t&31, gp=lane>>2, tig=lane&3;
    int mrow=(w>>2)*32, ncol=(w&3)*16;
    int aoff = AOFF(lane,36), boff = BOFF(lane,36);
    const float* attn = g_attn + ((size_t)bh << 20) + (size_t)qb*64*1024;
    const float* vptr = g_qkv + (size_t)bh * P * 192 + 128;
    float c[2][2][4];
#pragma unroll
    for (int i=0;i<2;i++)
#pragma unroll
    for (int jn=0;jn<2;jn++)
#pragma unroll
    for (int k=0;k<4;k++) c[i][jn][k]=0.f;
    for (int kc = 0; kc < 16; kc++) {
        __syncthreads();
        for (int idx=t; idx<1024; idx+=256){
            int r=idx>>4, f4=idx&15;
            float4 v = *(const float4*)(attn + (size_t)r*1024 + kc*64 + f4*4);
            bsplit2(v.x, v.y, sAh[r*36+f4*2],   sAl[r*36+f4*2]);
            bsplit2(v.z, v.w, sAh[r*36+f4*2+1], sAl[r*36+f4*2+1]);
        }
        for (int idx=t; idx<2048; idx+=256){
            int d=idx&63, tp=idx>>6;
            float v0 = vptr[(size_t)(kc*64+2*tp)*192 + d];
            float v1 = vptr[(size_t)(kc*64+2*tp+1)*192 + d];
            bsplit2(v0, v1, sVh[d*36+tp], sVl[d*36+tp]);
        }
        __syncthreads();
#pragma unroll
        for (int kk=0;kk<4;kk++){
            unsigned Ah[2][4], Al[2][4], Bh[2][2], Bl[2][2];
#pragma unroll
            for (int mi=0;mi<2;mi++){
                ldsm4(Ah[mi][0],Ah[mi][1],Ah[mi][2],Ah[mi][3],
                      sAh + (mrow+mi*16)*36 + kk*8 + aoff);
                ldsm4(Al[mi][0],Al[mi][1],Al[mi][2],Al[mi][3],
                      sAl + (mrow+mi*16)*36 + kk*8 + aoff);
            }
            ldsm4(Bh[0][0],Bh[0][1],Bh[1][0],Bh[1][1], sVh + ncol*36 + kk*8 + boff);
            ldsm4(Bl[0][0],Bl[0][1],Bl[1][0],Bl[1][1], sVl + ncol*36 + kk*8 + boff);
#pragma unroll
            for (int mi=0;mi<2;mi++)
#pragma unroll
            for (int ni=0;ni<2;ni++)
                bmma3(c[mi][ni], Ah[mi], Al[mi], Bh[ni], Bl[ni]);
        }
    }
    if (!fine) {
#pragma unroll
        for (int mi=0;mi<2;mi++)
#pragma unroll
        for (int ni=0;ni<2;ni++){
            int row = qb*64 + mrow+mi*16+gp;
            int d0 = ncol+ni*8+2*tig;
            g_outc[((size_t)(b*C + h*HD + d0  ))*PLANE32 + row] = c[mi][ni][0];
            g_outc[((size_t)(b*C + h*HD + d0+1))*PLANE32 + row] = c[mi][ni][1];
            g_outc[((size_t)(b*C + h*HD + d0  ))*PLANE32 + row + 8] = c[mi][ni][2];
            g_outc[((size_t)(b*C + h*HD + d0+1))*PLANE32 + row + 8] = c[mi][ni][3];
        }
    } else {
#pragma unroll
        for (int mi=0;mi<2;mi++)
#pragma unroll
        for (int ni=0;ni<2;ni++){
            int row = qb*64 + mrow+mi*16+gp;
            int d0 = ncol+ni*8+2*tig;
            *(float2*)(g_outf + ((size_t)bh*P + row)*HD + d0) =
                make_float2(c[mi][ni][0], c[mi][ni][1]);
            *(float2*)(g_outf + ((size_t)bh*P + row + 8)*HD + d0) =
                make_float2(c[mi][ni][2], c[mi][ni][3]);
        }
    }
}

// ---- scatter / dw ----
__global__ __launch_bounds__(256) void k_scatter() {
    int bh = blockIdx.x, ki = blockIdx.y;
    int t = threadIdx.x;
    int s = t >> 6, d = t & 63;
    int b = bh >> 2, h = bh & 3;
    int p = g_topk[bh*KF + ki];
    int yy = ((p >> 5) << 1) + (s >> 1);
    int xx = ((p & 31) << 1) + (s & 1);
    float val = g_outf[((size_t)bh * P + ki*4 + s) * HD + d];
    g_y[(((size_t)(b*C + h*HD + d)) << 12) + (yy << 6) + xx] += val;
}
__global__ __launch_bounds__(256) void k_dw(const float* __restrict__ wdw,
                                            const float* __restrict__ g,
                                            const float* __restrict__ bb,
                                            const float* __restrict__ m,
                                            const float* __restrict__ vv) {
    size_t i = (size_t)blockIdx.x * 256 + threadIdx.x;
    int x = i & 63, y = (i >> 6) & 63;
    int c = (int)((i >> 12) & 255);
    const float* plane = g_y + ((i >> 12) << 12);
    const float* wc = wdw + c*9;
    float s = 0.f;
#pragma unroll
    for (int ky = 0; ky < 3; ky++) {
        int yy = y + ky - 1;
        if (yy < 0 || yy >= 64) continue;
#pragma unroll
        for (int kx = 0; kx < 3; kx++) {
            int xx = x + kx - 1;
            if (xx < 0 || xx >= 64) continue;
            s = fmaf(wc[ky*3 + kx], plane[(yy << 6) + xx], s);
        }
    }
    float sc = g[c] * rsqrtf(vv[c] + 1e-5f);
    float r = s * sc + (bb[c] - m[c] * sc);
    g_yd[i] = fminf(fmaxf(r, 0.f), 6.f);
}

// ---- pointwise bf16: grid(8,32,4), ldmatrix both sides ----
__global__ __launch_bounds__(256) void k_pw_t(const float* __restrict__ g,
                                              const float* __restrict__ bb,
                                              const float* __restrict__ m,
                                              const float* __restrict__ vv,
                                              float* __restrict__ out) {
    int b = blockIdx.x, sp = blockIdx.y, cg = blockIdx.z;
    __shared__ unsigned sWh[64*20], sWl[64*20];
    __shared__ unsigned sXh[128*20], sXl[128*20];
    int t=threadIdx.x, w=t>>5, lane=t&31, gp=lane>>2, tig=lane&3;
    int mrow=(w>>2)*32, ncol=(w&3)*32;
    int aoff = AOFF(lane,20), boff = BOFF(lane,20);
    float c[2][4][4];
#pragma unroll
    for (int i=0;i<2;i++)
#pragma unroll
    for (int jn=0;jn<4;jn++)
#pragma unroll
    for (int k=0;k<4;k++) c[i][jn][k]=0.f;
    const float* xin = g_yd + (size_t)b * C * HW + sp * 128;
    for (int cc = 0; cc < 8; cc++) {
        __syncthreads();
        {
            int idx = t;
            int co=idx>>2, c4=(idx&3)<<2;
            *(uint4*)(sWh + co*20 + c4) = *(const uint4*)(g_pwh + (size_t)(cg*64+co)*128 + cc*16 + c4);
            *(uint4*)(sWl + co*20 + c4) = *(const uint4*)(g_pwl + (size_t)(cg*64+co)*128 + cc*16 + c4);
        }
        for (int idx=t; idx<2048; idx+=256){
            int px = idx&127, kp = idx>>7;
            float v0 = xin[(size_t)(cc*32+2*kp)*HW + px];
            float v1 = xin[(size_t)(cc*32+2*kp+1)*HW + px];
            bsplit2(v0, v1, sXh[px*20+kp], sXl[px*20+kp]);
        }
        __syncthreads();
#pragma unroll
        for (int kk=0;kk<2;kk++){
            unsigned Ah[2][4], Al[2][4], Bh[4][2], Bl[4][2];
#pragma unroll
            for (int mi=0;mi<2;mi++){
                ldsm4(Ah[mi][0],Ah[mi][1],Ah[mi][2],Ah[mi][3],
                      sWh + (mrow+mi*16)*20 + kk*8 + aoff);
                ldsm4(Al[mi][0],Al[mi][1],Al[mi][2],Al[mi][3],
                      sWl + (mrow+mi*16)*20 + kk*8 + aoff);
            }
            ldsm4(Bh[0][0],Bh[0][1],Bh[1][0],Bh[1][1], sXh + ncol*20 + kk*8 + boff);
            ldsm4(Bl[0][0],Bl[0][1],Bl[1][0],Bl[1][1], sXl + ncol*20 + kk*8 + boff);
            ldsm4(Bh[2][0],Bh[2][1],Bh[3][0],Bh[3][1], sXh + (ncol+16)*20 + kk*8 + boff);
            ldsm4(Bl[2][0],Bl[2][1],Bl[3][0],Bl[3][1], sXl + (ncol+16)*20 + kk*8 + boff);
#pragma unroll
            for (int mi=0;mi<2;mi++)
#pragma unroll
            for (int ni=0;ni<4;ni++)
                bmma3(c[mi][ni], Ah[mi], Al[mi], Bh[ni], Bl[ni]);
        }
    }
#pragma unroll
    for (int mi=0;mi<2;mi++){
        int co = cg*64 + mrow+mi*16+gp;
        float sc0 = g[co] * rsqrtf(vv[co] + 1e-5f);
        float of0 = bb[co] - m[co] * sc0;
        float sc1 = g[co+8] * rsqrtf(vv[co+8] + 1e-5f);
        float of1 = bb[co+8] - m[co+8] * sc1;
#pragma unroll
        for (int ni=0;ni<4;ni++){
            int px = sp*128 + ncol+ni*8+2*tig;
            float r0 = fminf(fmaxf(c[mi][ni][0]*sc0 + of0, 0.f), 6.f);
            float r1 = fminf(fmaxf(c[mi][ni][1]*sc0 + of0, 0.f), 6.f);
            float r2 = fminf(fmaxf(c[mi][ni][2]*sc1 + of1, 0.f), 6.f);
            float r3 = fminf(fmaxf(c[mi][ni][3]*sc1 + of1, 0.f), 6.f);
            *(float2*)(out + ((size_t)(b*C+co))*HW + px)   = make_float2(r0, r1);
            *(float2*)(out + ((size_t)(b*C+co+8))*HW + px) = make_float2(r2, r3);
        }
    }
}

extern "C" void kernel_launch(void* const* d_in, const int* in_sizes, int n_in,
                              void* d_out, int out_size) {
    const float* x       = (const float*)d_in[0];
    const float* w_down  = (const float*)d_in[1];
    const float* b_down  = (const float*)d_in[2];
    const float* w_qkv_c = (const float*)d_in[3];
    const float* b_qkv_c = (const float*)d_in[4];
    const float* w_up    = (const float*)d_in[5];
    const float* b_up    = (const float*)d_in[6];
    const float* w_qkv_f = (const float*)d_in[7];
    const float* b_qkv_f = (const float*)d_in[8];
    const float* w_dw    = (const float*)d_in[9];
    const float* bn_dw_g = (const float*)d_in[10];
    const float* bn_dw_b = (const float*)d_in[11];
    const float* bn_dw_m = (const float*)d_in[12];
    const float* bn_dw_v = (const float*)d_in[13];
    const float* w_pw    = (const float*)d_in[14];
    const float* bn_pw_g = (const float*)d_in[15];
    const float* bn_pw_b = (const float*)d_in[16];
    const float* bn_pw_m = (const float*)d_in[17];
    const float* bn_pw_v = (const float*)d_in[18];
    float* out = (float*)d_out;

    k_prep_wd<<<2048, 256>>>(w_down);
    k_wt<<<2048, 256>>>(w_up);
    k_prep_pw<<<128, 256>>>(w_pw);

    k_down_t<<<dim3(128, 4), 256>>>(x, b_down);
    k_qkv_t<<<dim3(32, 16), 256>>>(w_qkv_c, b_qkv_c, 0);
    k_logits_t<<<dim3(32, 16, 2), 256>>>();
    k_softmax<<<dim3(32, 1024), 256>>>();
    k_colsum<<<dim3(32, 4), 256>>>();
    k_av_t<<<dim3(32, 16), 256>>>(0);
    k_topk<<<32, 512>>>();
    k_up_t<<<dim3(64, 16), 256>>>(b_up);

    k_qkv_t<<<dim3(32, 16), 256>>>(w_qkv_f, b_qkv_f, 1);
    k_logits_t<<<dim3(32, 16, 2), 256>>>();
    k_softmax<<<dim3(32, 1024), 256>>>();
    k_av_t<<<dim3(32, 16), 256>>>(1);

    k_scatter<<<dim3(32, 256), 256>>>();
    k_dw<<<32768, 256>>>(w_dw, bn_dw_g, bn_dw_b, bn_dw_m, bn_dw_v);
    k_pw_t<<<dim3(8, 32, 4), 256>>>(bn_pw_g, bn_pw_b, bn_pw_m, bn_pw_v, out);
}